// round 7
// baseline (speedup 1.0000x reference)
#include <cuda_runtime.h>
#include <cuda_bf16.h>
#include <math.h>
#include <stdint.h>

#define DIM 128
#define NITER 8

#define MAXL 100096ull
#define MAXC 150016ull
#define MAXN 150016ull
#define MAXE 450048

// ---------------- fp32 scratch ----------------
__device__ float g_lfeat[MAXL * 128];
__device__ float g_cfeat[MAXC * 128];
__device__ float g_caggr[MAXC * 128];
__device__ float g_lx0  [MAXL * 128];   // c2l segment sum
__device__ float g_l2lm [MAXL * 128];   // l2l message (MLP out)
__device__ float g_gates[MAXN * 512];   // fused GRU gates [rz_sum | i_n | h_n]
__device__ int   g_lei32[MAXE];
__device__ int   g_cei32[MAXE];
__device__ int   g_is64;

// ---------------- bf16 split scratch ----------------
__device__ __nv_bfloat16 g_lcur_h[MAXL * 128], g_lcur_l[MAXL * 128];
__device__ __nv_bfloat16 g_ccur_h[MAXC * 128], g_ccur_l[MAXC * 128];
__device__ __nv_bfloat16 g_mw_h[98304],  g_mw_l[98304];     // 6 MLP weights 128x128
__device__ __nv_bfloat16 g_wcc_h[131072], g_wcc_l[131072];  // clause Wcat 512x256
__device__ __nv_bfloat16 g_wcl_h[196608], g_wcl_l[196608];  // literal Wcat 512x384
__device__ float g_bcat_c[512], g_bcat_l[512];

// =================== helpers ===================
__device__ __forceinline__ uint32_t smem_to_u32(const void* p) {
    uint32_t a;
    asm("{ .reg .u64 t; cvta.to.shared.u64 t, %1; cvt.u32.u64 %0, t; }"
        : "=r"(a) : "l"(p));
    return a;
}
__device__ __forceinline__ void ldx4(uint32_t* r, uint32_t addr) {
    asm volatile("ldmatrix.sync.aligned.m8n8.x4.shared.b16 {%0,%1,%2,%3}, [%4];"
                 : "=r"(r[0]), "=r"(r[1]), "=r"(r[2]), "=r"(r[3]) : "r"(addr));
}
__device__ __forceinline__ void ldx2(uint32_t* r, uint32_t addr) {
    asm volatile("ldmatrix.sync.aligned.m8n8.x2.shared.b16 {%0,%1}, [%2];"
                 : "=r"(r[0]), "=r"(r[1]) : "r"(addr));
}
__device__ __forceinline__ void mma_bf16(float* d, const uint32_t* a, const uint32_t* b) {
    asm volatile("mma.sync.aligned.m16n8k16.row.col.f32.bf16.bf16.f32 "
                 "{%0,%1,%2,%3}, {%4,%5,%6,%7}, {%8,%9}, {%0,%1,%2,%3};"
                 : "+f"(d[0]), "+f"(d[1]), "+f"(d[2]), "+f"(d[3])
                 : "r"(a[0]), "r"(a[1]), "r"(a[2]), "r"(a[3]), "r"(b[0]), "r"(b[1]));
}
__device__ __forceinline__ uint32_t pack_h(float x, float y) {
    __nv_bfloat162 p(__float2bfloat16(x), __float2bfloat16(y));
    return *(uint32_t*)&p;
}
__device__ __forceinline__ uint32_t pack_l(float x, float y) {
    __nv_bfloat16 hx = __float2bfloat16(x), hy = __float2bfloat16(y);
    __nv_bfloat162 p(__float2bfloat16(x - __bfloat162float(hx)),
                     __float2bfloat16(y - __bfloat162float(hy)));
    return *(uint32_t*)&p;
}

#define MAT_BYTES 18432                  // 128 rows x 144B (64 bf16 cols + pad)
#define SMEM_GATES 73728                 // 4 regions
#define SMEM_MLP   110592                // 6 regions

// =================== fused 2-layer MLP ===================
// out[N,128] = relu(x@W1^T + b1) @ W2^T + b2 ; x = (Ah+Al) split bf16, K=M=128.
// Hidden tile kept in smem (split bf16). 8 warps, 2x4 of 64x32 tiles.
template<int XORROW>
__global__ __launch_bounds__(256, 2)
void fused_mlp(const __nv_bfloat16* __restrict__ Ah, const __nv_bfloat16* __restrict__ Al,
               const __nv_bfloat16* __restrict__ W1h, const __nv_bfloat16* __restrict__ W1l,
               const float* __restrict__ b1,
               const __nv_bfloat16* __restrict__ W2h, const __nv_bfloat16* __restrict__ W2l,
               const float* __restrict__ b2,
               float* __restrict__ out, int N)
{
    extern __shared__ char smem[];
    const uint32_t sb = smem_to_u32(smem);
    const int tid  = threadIdx.x;
    const int lane = tid & 31;
    const int wid  = tid >> 5;
    const int wm   = wid >> 2;
    const int wn   = wid & 3;
    const int bm   = blockIdx.x * 128;

    const uint32_t aOff = (uint32_t)(wm * 64 + (lane & 15)) * 144 + ((lane >> 4) << 4);
    const uint32_t bOff = (uint32_t)(wn * 32 + (lane & 7)) * 144 + (((lane >> 3) & 1) << 4);

    float acc[4][4][4] = {};

    // ---- stage 1: hid = relu(x @ W1^T + b1) ----
    #pragma unroll
    for (int kc = 0; kc < 2; kc++) {
        if (kc) __syncthreads();
        const int k0 = kc << 6;
        #pragma unroll
        for (int t = 0; t < 4; t++) {
            int i = tid + (t << 8);
            int row = i >> 3, unit = i & 7;
            char* dst = smem + (size_t)row * 144 + (unit << 4);
            int grow = bm + row;
            uint4 vh = make_uint4(0, 0, 0, 0), vl = vh;
            if (grow < N) {
                int sr = XORROW ? (grow ^ 1) : grow;
                vh = ((const uint4*)(Ah + (size_t)sr * 128 + k0))[unit];
                vl = ((const uint4*)(Al + (size_t)sr * 128 + k0))[unit];
            }
            *(uint4*)dst               = vh;
            *(uint4*)(dst + MAT_BYTES) = vl;
            *(uint4*)(dst + 4 * MAT_BYTES) = ((const uint4*)(W1h + (size_t)row * 128 + k0))[unit];
            *(uint4*)(dst + 5 * MAT_BYTES) = ((const uint4*)(W1l + (size_t)row * 128 + k0))[unit];
        }
        __syncthreads();
        #pragma unroll
        for (int k16 = 0; k16 < 4; k16++) {
            const uint32_t kb = k16 << 5;
            uint32_t ah[4][4], al[4][4];
            #pragma unroll
            for (int mi = 0; mi < 4; mi++) {
                ldx4(ah[mi], sb + aOff + mi * (16 * 144) + kb);
                ldx4(al[mi], sb + MAT_BYTES + aOff + mi * (16 * 144) + kb);
            }
            #pragma unroll
            for (int ni = 0; ni < 4; ni++) {
                uint32_t bh[2], bl[2];
                ldx2(bh, sb + 4 * MAT_BYTES + bOff + ni * (8 * 144) + kb);
                ldx2(bl, sb + 5 * MAT_BYTES + bOff + ni * (8 * 144) + kb);
                #pragma unroll
                for (int mi = 0; mi < 4; mi++) {
                    mma_bf16(acc[mi][ni], ah[mi], bh);
                    mma_bf16(acc[mi][ni], al[mi], bh);
                    mma_bf16(acc[mi][ni], ah[mi], bl);
                }
            }
        }
    }
    __syncthreads();

    // ---- epilogue 1: relu + split -> hid in regions R0..R3 ----
    #pragma unroll
    for (int ni = 0; ni < 4; ni++) {
        int c = wn * 32 + ni * 8 + ((lane & 3) << 1);       // 0..127
        float2 bv = *(const float2*)(b1 + c);
        uint32_t roff = (uint32_t)(c >> 6) * MAT_BYTES + (uint32_t)(c & 63) * 2;
        #pragma unroll
        for (int mi = 0; mi < 4; mi++) {
            int rl0 = wm * 64 + mi * 16 + (lane >> 2);
            float vx0 = fmaxf(acc[mi][ni][0] + bv.x, 0.f);
            float vy0 = fmaxf(acc[mi][ni][1] + bv.y, 0.f);
            float vx1 = fmaxf(acc[mi][ni][2] + bv.x, 0.f);
            float vy1 = fmaxf(acc[mi][ni][3] + bv.y, 0.f);
            uint32_t o0 = roff + (uint32_t)rl0 * 144;
            uint32_t o1 = roff + (uint32_t)(rl0 + 8) * 144;
            *(uint32_t*)(smem + o0) = pack_h(vx0, vy0);
            *(uint32_t*)(smem + o0 + 2 * MAT_BYTES) = pack_l(vx0, vy0);
            *(uint32_t*)(smem + o1) = pack_h(vx1, vy1);
            *(uint32_t*)(smem + o1 + 2 * MAT_BYTES) = pack_l(vx1, vy1);
            acc[mi][ni][0] = acc[mi][ni][1] = acc[mi][ni][2] = acc[mi][ni][3] = 0.f;
        }
    }
    __syncthreads();

    // ---- stage 2: out = hid @ W2^T + b2 ----
    #pragma unroll
    for (int kc = 0; kc < 2; kc++) {
        if (kc) __syncthreads();
        const int k0 = kc << 6;
        #pragma unroll
        for (int t = 0; t < 4; t++) {
            int i = tid + (t << 8);
            int row = i >> 3, unit = i & 7;
            char* dst = smem + (size_t)row * 144 + (unit << 4);
            *(uint4*)(dst + 4 * MAT_BYTES) = ((const uint4*)(W2h + (size_t)row * 128 + k0))[unit];
            *(uint4*)(dst + 5 * MAT_BYTES) = ((const uint4*)(W2l + (size_t)row * 128 + k0))[unit];
        }
        __syncthreads();
        const uint32_t ahBase = sb + (uint32_t)kc * MAT_BYTES + aOff;
        const uint32_t alBase = sb + (uint32_t)(2 + kc) * MAT_BYTES + aOff;
        #pragma unroll
        for (int k16 = 0; k16 < 4; k16++) {
            const uint32_t kb = k16 << 5;
            uint32_t ah[4][4], al[4][4];
            #pragma unroll
            for (int mi = 0; mi < 4; mi++) {
                ldx4(ah[mi], ahBase + mi * (16 * 144) + kb);
                ldx4(al[mi], alBase + mi * (16 * 144) + kb);
            }
            #pragma unroll
            for (int ni = 0; ni < 4; ni++) {
                uint32_t bh[2], bl[2];
                ldx2(bh, sb + 4 * MAT_BYTES + bOff + ni * (8 * 144) + kb);
                ldx2(bl, sb + 5 * MAT_BYTES + bOff + ni * (8 * 144) + kb);
                #pragma unroll
                for (int mi = 0; mi < 4; mi++) {
                    mma_bf16(acc[mi][ni], ah[mi], bh);
                    mma_bf16(acc[mi][ni], al[mi], bh);
                    mma_bf16(acc[mi][ni], ah[mi], bl);
                }
            }
        }
    }

    // ---- epilogue 2 ----
    #pragma unroll
    for (int ni = 0; ni < 4; ni++) {
        int c = wn * 32 + ni * 8 + ((lane & 3) << 1);
        float2 bv = *(const float2*)(b2 + c);
        #pragma unroll
        for (int mi = 0; mi < 4; mi++) {
            int r0 = bm + wm * 64 + mi * 16 + (lane >> 2);
            if (r0 < N)
                *(float2*)(out + (size_t)r0 * 128 + c) =
                    make_float2(acc[mi][ni][0] + bv.x, acc[mi][ni][1] + bv.y);
            if (r0 + 8 < N)
                *(float2*)(out + (size_t)(r0 + 8) * 128 + c) =
                    make_float2(acc[mi][ni][2] + bv.x, acc[mi][ni][3] + bv.y);
        }
    }
}

// =================== concat GRU gates GEMM ===================
// gates[N,512] = [x | h] @ Wcat^T + bcat.  A sources: NF32 fp32 arrays (128 cols
// each, fused split) then (Ah,Al) split bf16 (128 cols). K = (NF32+1)*128.
template<int NF32>
__global__ __launch_bounds__(256, 2)
void gates_gemm(const float* __restrict__ Af0, const float* __restrict__ Af1,
                const __nv_bfloat16* __restrict__ Ah, const __nv_bfloat16* __restrict__ Al,
                const __nv_bfloat16* __restrict__ Wh, const __nv_bfloat16* __restrict__ Wl,
                const float* __restrict__ bias,
                float* __restrict__ gates, int N, int K)
{
    extern __shared__ char smem[];
    const uint32_t sb = smem_to_u32(smem);
    const int tid  = threadIdx.x;
    const int lane = tid & 31;
    const int wid  = tid >> 5;
    const int wm   = wid >> 2;
    const int wn   = wid & 3;
    const int bm   = blockIdx.x * 128;
    const int bn   = blockIdx.y * 128;
    const int nchunk = K >> 6;

    float acc[4][4][4] = {};
    const uint32_t aOff = (uint32_t)(wm * 64 + (lane & 15)) * 144 + ((lane >> 4) << 4);
    const uint32_t bOff = (uint32_t)(wn * 32 + (lane & 7)) * 144 + (((lane >> 3) & 1) << 4);

    for (int kc = 0; kc < nchunk; kc++) {
        if (kc) __syncthreads();
        const int k0 = kc << 6;
        const int s  = kc >> 1;
        #pragma unroll
        for (int t = 0; t < 4; t++) {
            int i = tid + (t << 8);
            int row = i >> 3, unit = i & 7;
            char* dst = smem + (size_t)row * 144 + (unit << 4);
            int grow = bm + row;
            uint4 vh = make_uint4(0, 0, 0, 0), vl = vh;
            if (grow < N) {
                if (s < NF32) {
                    const float* src = (s == 0 ? Af0 : Af1)
                                     + (size_t)grow * 128 + ((kc & 1) << 6) + unit * 8;
                    float4 f0 = *(const float4*)src;
                    float4 f1 = *(const float4*)(src + 4);
                    vh.x = pack_h(f0.x, f0.y); vl.x = pack_l(f0.x, f0.y);
                    vh.y = pack_h(f0.z, f0.w); vl.y = pack_l(f0.z, f0.w);
                    vh.z = pack_h(f1.x, f1.y); vl.z = pack_l(f1.x, f1.y);
                    vh.w = pack_h(f1.z, f1.w); vl.w = pack_l(f1.z, f1.w);
                } else {
                    const __nv_bfloat16* sa = Ah + (size_t)grow * 128 + ((kc & 1) << 6);
                    const __nv_bfloat16* sl = Al + (size_t)grow * 128 + ((kc & 1) << 6);
                    vh = ((const uint4*)sa)[unit];
                    vl = ((const uint4*)sl)[unit];
                }
            }
            *(uint4*)dst               = vh;
            *(uint4*)(dst + MAT_BYTES) = vl;
            *(uint4*)(dst + 2 * MAT_BYTES) = ((const uint4*)(Wh + (size_t)(bn + row) * K + k0))[unit];
            *(uint4*)(dst + 3 * MAT_BYTES) = ((const uint4*)(Wl + (size_t)(bn + row) * K + k0))[unit];
        }
        __syncthreads();

        #pragma unroll
        for (int k16 = 0; k16 < 4; k16++) {
            const uint32_t kb = k16 << 5;
            uint32_t ah[4][4], al[4][4];
            #pragma unroll
            for (int mi = 0; mi < 4; mi++) {
                ldx4(ah[mi], sb + aOff + mi * (16 * 144) + kb);
                ldx4(al[mi], sb + MAT_BYTES + aOff + mi * (16 * 144) + kb);
            }
            #pragma unroll
            for (int ni = 0; ni < 4; ni++) {
                uint32_t bh[2], bl[2];
                ldx2(bh, sb + 2 * MAT_BYTES + bOff + ni * (8 * 144) + kb);
                ldx2(bl, sb + 3 * MAT_BYTES + bOff + ni * (8 * 144) + kb);
                #pragma unroll
                for (int mi = 0; mi < 4; mi++) {
                    mma_bf16(acc[mi][ni], ah[mi], bh);
                    mma_bf16(acc[mi][ni], al[mi], bh);
                    mma_bf16(acc[mi][ni], ah[mi], bl);
                }
            }
        }
    }

    #pragma unroll
    for (int ni = 0; ni < 4; ni++) {
        int gcol = bn + wn * 32 + ni * 8 + ((lane & 3) << 1);
        float2 bv = *(const float2*)(bias + gcol);
        #pragma unroll
        for (int mi = 0; mi < 4; mi++) {
            int r0 = bm + wm * 64 + mi * 16 + (lane >> 2);
            if (r0 < N)
                *(float2*)(gates + (size_t)r0 * 512 + gcol) =
                    make_float2(acc[mi][ni][0] + bv.x, acc[mi][ni][1] + bv.y);
            if (r0 + 8 < N)
                *(float2*)(gates + (size_t)(r0 + 8) * 512 + gcol) =
                    make_float2(acc[mi][ni][2] + bv.x, acc[mi][ni][3] + bv.y);
        }
    }
}

// =================== support kernels ===================
__global__ void detect_idx64(const unsigned int* __restrict__ a,
                             const unsigned int* __restrict__ b, int E)
{
    int n = E < 32 ? E : 32;
    int is64 = 1;
    for (int i = 0; i < n; i++) {
        if (a[2 * i + 1] != 0u) is64 = 0;
        if (b[2 * i + 1] != 0u) is64 = 0;
    }
    g_is64 = is64;
}

__global__ void convert_idx(const void* __restrict__ srcA, const void* __restrict__ srcB,
                            int* __restrict__ dstA, int* __restrict__ dstB, int E)
{
    int e = blockIdx.x * blockDim.x + threadIdx.x;
    if (e >= E) return;
    if (g_is64) {
        dstA[e] = (int)((const long long*)srcA)[e];
        dstB[e] = (int)((const long long*)srcB)[e];
    } else {
        dstA[e] = ((const int*)srcA)[e];
        dstB[e] = ((const int*)srcB)[e];
    }
}

struct PrepArgs {
    const float4* mlp[6];          // 128x128 each
    const float* cWih; const float* cWhh;   // 384x128
    const float* lWih; const float* lWhh;   // 384x256 / 384x128
    const float* cbih; const float* cbhh;
    const float* lbih; const float* lbhh;
};

__device__ __forceinline__ float wcat_c_elem(const PrepArgs& a, int m, int k) {
    if (k < 128) return (m < 384) ? a.cWih[m * 128 + k] : 0.f;
    return (m < 256) ? a.cWhh[m * 128 + k - 128]
         : (m < 384) ? 0.f : a.cWhh[(m - 128) * 128 + (k - 128)];
}
__device__ __forceinline__ float wcat_l_elem(const PrepArgs& a, int m, int k) {
    if (k < 256) return (m < 384) ? a.lWih[m * 256 + k] : 0.f;
    return (m < 256) ? a.lWhh[m * 128 + k - 256]
         : (m < 384) ? 0.f : a.lWhh[(m - 128) * 128 + (k - 256)];
}

#define PREP_Q1 24576                  // MLP weight quads
#define PREP_Q2 32768                  // wcat_c quads
#define PREP_Q3 49152                  // wcat_l quads
#define PREP_TOT (PREP_Q1 + PREP_Q2 + PREP_Q3 + 1024)

__global__ void prep_all(PrepArgs a,
                         __nv_bfloat16* __restrict__ mwh, __nv_bfloat16* __restrict__ mwl,
                         __nv_bfloat16* __restrict__ wcch, __nv_bfloat16* __restrict__ wccl,
                         __nv_bfloat16* __restrict__ wclh, __nv_bfloat16* __restrict__ wcll,
                         float* __restrict__ bcc, float* __restrict__ bcl)
{
    int i = blockIdx.x * blockDim.x + threadIdx.x;
    if (i >= PREP_TOT) return;
    if (i < PREP_Q1) {
        int midx = i >> 12;                  // /4096 quads per 128x128 matrix
        float4 v = a.mlp[midx][i & 4095];
        *(uint2*)(mwh + (size_t)i * 4) = make_uint2(pack_h(v.x, v.y), pack_h(v.z, v.w));
        *(uint2*)(mwl + (size_t)i * 4) = make_uint2(pack_l(v.x, v.y), pack_l(v.z, v.w));
    } else if (i < PREP_Q1 + PREP_Q2) {
        int q = i - PREP_Q1;
        int base = q * 4, m = base >> 8, k = base & 255;
        float v0 = wcat_c_elem(a, m, k), v1 = wcat_c_elem(a, m, k + 1);
        float v2 = wcat_c_elem(a, m, k + 2), v3 = wcat_c_elem(a, m, k + 3);
        *(uint2*)(wcch + (size_t)base) = make_uint2(pack_h(v0, v1), pack_h(v2, v3));
        *(uint2*)(wccl + (size_t)base) = make_uint2(pack_l(v0, v1), pack_l(v2, v3));
    } else if (i < PREP_Q1 + PREP_Q2 + PREP_Q3) {
        int q = i - PREP_Q1 - PREP_Q2;
        int base = q * 4, m = base / 384, k = base % 384;
        float v0 = wcat_l_elem(a, m, k), v1 = wcat_l_elem(a, m, k + 1);
        float v2 = wcat_l_elem(a, m, k + 2), v3 = wcat_l_elem(a, m, k + 3);
        *(uint2*)(wclh + (size_t)base) = make_uint2(pack_h(v0, v1), pack_h(v2, v3));
        *(uint2*)(wcll + (size_t)base) = make_uint2(pack_l(v0, v1), pack_l(v2, v3));
    } else {
        int j = i - PREP_Q1 - PREP_Q2 - PREP_Q3;   // 0..1023
        if (j < 512) {
            bcc[j] = (j < 256) ? a.cbih[j] + a.cbhh[j]
                   : (j < 384) ? a.cbih[j] : a.cbhh[j - 128];
        } else {
            int m = j - 512;
            bcl[m] = (m < 256) ? a.lbih[m] + a.lbhh[m]
                   : (m < 384) ? a.lbih[m] : a.lbhh[m - 128];
        }
    }
}

__global__ void split_pair(const float* __restrict__ x,
                           __nv_bfloat16* __restrict__ xh,
                           __nv_bfloat16* __restrict__ xl, long long n4)
{
    long long i = (long long)blockIdx.x * blockDim.x + threadIdx.x;
    if (i >= n4) return;
    float4 v = *(const float4*)(x + i * 4);
    *(uint2*)(xh + i * 4) = make_uint2(pack_h(v.x, v.y), pack_h(v.z, v.w));
    *(uint2*)(xl + i * 4) = make_uint2(pack_l(v.x, v.y), pack_l(v.z, v.w));
}

__global__ void edge_aggr(const int* __restrict__ src, const int* __restrict__ dst,
                          const float* __restrict__ feat, float* __restrict__ aggr,
                          int E, int maxS, int maxD)
{
    long long idx = (long long)blockIdx.x * blockDim.x + threadIdx.x;
    int e = (int)(idx >> 5);
    if (e >= E) return;
    int c = (int)(idx & 31) << 2;
    int s = src[e], d = dst[e];
    if ((unsigned)s >= (unsigned)maxS || (unsigned)d >= (unsigned)maxD) return;
    float4 v = *(const float4*)(feat + (size_t)s * 128 + c);
    float* p = aggr + (size_t)d * 128 + c;
    atomicAdd(p + 0, v.x);
    atomicAdd(p + 1, v.y);
    atomicAdd(p + 2, v.z);
    atomicAdd(p + 3, v.w);
}

// GRU pointwise from fused gates: [rz_sum(256) | i_n(128) | h_n(128)]
__global__ void gru_pointwise3(const float* __restrict__ g, const float* __restrict__ h,
                               float* __restrict__ hout,
                               __nv_bfloat16* __restrict__ hh, __nv_bfloat16* __restrict__ hl,
                               int N)
{
    long long idx = (long long)blockIdx.x * blockDim.x + threadIdx.x;
    if (idx >= (long long)N * 32) return;
    int n = (int)(idx >> 5);
    int j = (int)(idx & 31) << 2;
    const float* gp = g + (size_t)n * 512;
    float4 R  = *(const float4*)(gp + j);
    float4 Z  = *(const float4*)(gp + 128 + j);
    float4 I  = *(const float4*)(gp + 256 + j);
    float4 Hn = *(const float4*)(gp + 384 + j);
    float4 hv = *(const float4*)(h + (size_t)n * 128 + j);

    float4 o;
    {
        float r = 1.f / (1.f + expf(-R.x)), z = 1.f / (1.f + expf(-Z.x));
        o.x = (1.f - z) * tanhf(I.x + r * Hn.x) + z * hv.x;
    }
    {
        float r = 1.f / (1.f + expf(-R.y)), z = 1.f / (1.f + expf(-Z.y));
        o.y = (1.f - z) * tanhf(I.y + r * Hn.y) + z * hv.y;
    }
    {
        float r = 1.f / (1.f + expf(-R.z)), z = 1.f / (1.f + expf(-Z.z));
        o.z = (1.f - z) * tanhf(I.z + r * Hn.z) + z * hv.z;
    }
    {
        float r = 1.f / (1.f + expf(-R.w)), z = 1.f / (1.f + expf(-Z.w));
        o.w = (1.f - z) * tanhf(I.w + r * Hn.w) + z * hv.w;
    }
    *(float4*)(hout + (size_t)n * 128 + j) = o;
    *(uint2*)(hh + (size_t)n * 128 + j) = make_uint2(pack_h(o.x, o.y), pack_h(o.z, o.w));
    *(uint2*)(hl + (size_t)n * 128 + j) = make_uint2(pack_l(o.x, o.y), pack_l(o.z, o.w));
}

// =================== host side ===================
extern "C" void kernel_launch(void* const* d_in, const int* in_sizes, int n_in,
                              void* d_out, int out_size)
{
    int base = (n_in >= 26) ? 2 : 0;

    const void*  l_ei_raw = d_in[base + 0];
    const void*  c_ei_raw = d_in[base + 1];
    const float* l_emb0   = (const float*)d_in[base + 2];
    const float* c_emb0   = (const float*)d_in[base + 3];

    const float* l2c_W1 = (const float*)d_in[base + 4];
    const float* l2c_b1 = (const float*)d_in[base + 5];
    const float* l2c_W2 = (const float*)d_in[base + 6];
    const float* l2c_b2 = (const float*)d_in[base + 7];
    const float* c2l_W1 = (const float*)d_in[base + 8];
    const float* c2l_b1 = (const float*)d_in[base + 9];
    const float* c2l_W2 = (const float*)d_in[base + 10];
    const float* c2l_b2 = (const float*)d_in[base + 11];
    const float* l2l_W1 = (const float*)d_in[base + 12];
    const float* l2l_b1 = (const float*)d_in[base + 13];
    const float* l2l_W2 = (const float*)d_in[base + 14];
    const float* l2l_b2 = (const float*)d_in[base + 15];
    const float* cgru_Wih = (const float*)d_in[base + 16];
    const float* cgru_Whh = (const float*)d_in[base + 17];
    const float* cgru_bih = (const float*)d_in[base + 18];
    const float* cgru_bhh = (const float*)d_in[base + 19];
    const float* lgru_Wih = (const float*)d_in[base + 20];
    const float* lgru_Whh = (const float*)d_in[base + 21];
    const float* lgru_bih = (const float*)d_in[base + 22];
    const float* lgru_bhh = (const float*)d_in[base + 23];

    const int E = in_sizes[base + 0];
    const int L = in_sizes[base + 2] / DIM;
    const int C = in_sizes[base + 3] / DIM;

    float* out   = (float*)d_out;
    float* l_out = out;
    float* c_out = out + (size_t)(NITER + 1) * L * DIM;

    float *lfeat, *cfeat, *caggr, *lx0, *l2lm, *gates, *bcc, *bcl;
    int *lei, *cei;
    __nv_bfloat16 *lch, *lcl, *cch, *ccl, *mwh, *mwl, *wcch, *wccl, *wclh, *wcll;
    cudaGetSymbolAddress((void**)&lfeat, g_lfeat);
    cudaGetSymbolAddress((void**)&cfeat, g_cfeat);
    cudaGetSymbolAddress((void**)&caggr, g_caggr);
    cudaGetSymbolAddress((void**)&lx0,   g_lx0);
    cudaGetSymbolAddress((void**)&l2lm,  g_l2lm);
    cudaGetSymbolAddress((void**)&gates, g_gates);
    cudaGetSymbolAddress((void**)&lei,   g_lei32);
    cudaGetSymbolAddress((void**)&cei,   g_cei32);
    cudaGetSymbolAddress((void**)&lch,   g_lcur_h);
    cudaGetSymbolAddress((void**)&lcl,   g_lcur_l);
    cudaGetSymbolAddress((void**)&cch,   g_ccur_h);
    cudaGetSymbolAddress((void**)&ccl,   g_ccur_l);
    cudaGetSymbolAddress((void**)&mwh,   g_mw_h);
    cudaGetSymbolAddress((void**)&mwl,   g_mw_l);
    cudaGetSymbolAddress((void**)&wcch,  g_wcc_h);
    cudaGetSymbolAddress((void**)&wccl,  g_wcc_l);
    cudaGetSymbolAddress((void**)&wclh,  g_wcl_h);
    cudaGetSymbolAddress((void**)&wcll,  g_wcl_l);
    cudaGetSymbolAddress((void**)&bcc,   g_bcat_c);
    cudaGetSymbolAddress((void**)&bcl,   g_bcat_l);

    cudaFuncSetAttribute((const void*)fused_mlp<0>, cudaFuncAttributeMaxDynamicSharedMemorySize, SMEM_MLP);
    cudaFuncSetAttribute((const void*)fused_mlp<1>, cudaFuncAttributeMaxDynamicSharedMemorySize, SMEM_MLP);
    cudaFuncSetAttribute((const void*)gates_gemm<1>, cudaFuncAttributeMaxDynamicSharedMemorySize, SMEM_GATES);
    cudaFuncSetAttribute((const void*)gates_gemm<2>, cudaFuncAttributeMaxDynamicSharedMemorySize, SMEM_GATES);

    // ---- prelude: exactly 5 kernels before first GEMM ----
    detect_idx64<<<1, 1>>>((const unsigned int*)l_ei_raw, (const unsigned int*)c_ei_raw, E);
    convert_idx<<<(E + 255) / 256, 256>>>(l_ei_raw, c_ei_raw, lei, cei, E);

    PrepArgs pa;
    pa.mlp[0] = (const float4*)l2c_W1; pa.mlp[1] = (const float4*)l2c_W2;
    pa.mlp[2] = (const float4*)c2l_W1; pa.mlp[3] = (const float4*)c2l_W2;
    pa.mlp[4] = (const float4*)l2l_W1; pa.mlp[5] = (const float4*)l2l_W2;
    pa.cWih = cgru_Wih; pa.cWhh = cgru_Whh;
    pa.lWih = lgru_Wih; pa.lWhh = lgru_Whh;
    pa.cbih = cgru_bih; pa.cbhh = cgru_bhh;
    pa.lbih = lgru_bih; pa.lbhh = lgru_bhh;
    prep_all<<<(PREP_TOT + 255) / 256, 256>>>(pa, mwh, mwl, wcch, wccl, wclh, wcll, bcc, bcl);

    split_pair<<<(int)(((long long)L * 32 + 255) / 256), 256>>>(l_emb0, lch, lcl, (long long)L * 32);
    split_pair<<<(int)(((long long)C * 32 + 255) / 256), 256>>>(c_emb0, cch, ccl, (long long)C * 32);

    cudaMemcpyAsync(l_out, l_emb0, (size_t)L * DIM * sizeof(float), cudaMemcpyDeviceToDevice, 0);
    cudaMemcpyAsync(c_out, c_emb0, (size_t)C * DIM * sizeof(float), cudaMemcpyDeviceToDevice, 0);

    // MLP weight pool offsets (each 16384 elems)
    __nv_bfloat16 *W_[6], *Wl_[6];
    for (int i = 0; i < 6; i++) { W_[i] = mwh + (size_t)i * 16384; Wl_[i] = mwl + (size_t)i * 16384; }

    const int edge_blocks = (int)(((long long)E * 32 + 255) / 256);

    for (int it = 0; it < NITER; it++) {
        const float* lcur = l_out + (size_t)it * L * DIM;
        const float* ccur = c_out + (size_t)it * C * DIM;
        float* lnext = l_out + (size_t)(it + 1) * L * DIM;
        float* cnext = c_out + (size_t)(it + 1) * C * DIM;

        dim3 gl((L + 127) / 128), gc((C + 127) / 128);
        dim3 gl4((L + 127) / 128, 4), gc4((C + 127) / 128, 4);

        // --- 3 fused MLPs ---
        fused_mlp<0><<<gl, 256, SMEM_MLP>>>(lch, lcl, W_[0], Wl_[0], l2c_b1, W_[1], Wl_[1], l2c_b2, lfeat, L);
        fused_mlp<0><<<gc, 256, SMEM_MLP>>>(cch, ccl, W_[2], Wl_[2], c2l_b1, W_[3], Wl_[3], c2l_b2, cfeat, C);
        fused_mlp<1><<<gl, 256, SMEM_MLP>>>(lch, lcl, W_[4], Wl_[4], l2l_b1, W_[5], Wl_[5], l2l_b2, l2lm, L);

        // --- gather + segment sums ---
        cudaMemsetAsync(caggr, 0, (size_t)C * 128 * sizeof(float), 0);
        cudaMemsetAsync(lx0,   0, (size_t)L * 128 * sizeof(float), 0);
        edge_aggr<<<edge_blocks, 256>>>(lei, cei, lfeat, caggr, E, L, C);
        edge_aggr<<<edge_blocks, 256>>>(cei, lei, cfeat, lx0,   E, C, L);

        // --- clause GRU: gates = [caggr | ccur] @ Wcat_c^T + bcat_c ---
        gates_gemm<1><<<gc4, 256, SMEM_GATES>>>(caggr, nullptr, cch, ccl, wcch, wccl, bcc,
                                                gates, C, 256);
        gru_pointwise3<<<(int)(((long long)C * 32 + 255) / 256), 256>>>(gates, ccur, cnext, cch, ccl, C);

        // --- literal GRU: gates = [lx0 | l2lm | lcur] @ Wcat_l^T + bcat_l ---
        gates_gemm<2><<<gl4, 256, SMEM_GATES>>>(lx0, l2lm, lch, lcl, wclh, wcll, bcl,
                                                gates, L, 384);
        gru_pointwise3<<<(int)(((long long)L * 32 + 255) / 256), 256>>>(gates, lcur, lnext, lch, lcl, L);
    }
}

// round 8
// speedup vs baseline: 1.1068x; 1.1068x over previous
#include <cuda_runtime.h>
#include <cuda_bf16.h>
#include <math.h>
#include <stdint.h>

#define DIM 128
#define NITER 8

#define MAXL 100096ull
#define MAXC 150016ull
#define MAXN 150016ull
#define MAXE 450048

// ---------------- fp32 scratch ----------------
__device__ float g_lfeat[MAXL * 128];
__device__ float g_cfeat[MAXC * 128];
__device__ float g_caggr[MAXC * 128];
__device__ float g_lx0  [MAXL * 128];
__device__ float g_l2lm [MAXL * 128];
__device__ float g_gates[MAXN * 512];   // [rz_sum(256) | i_n(128) | h_n(128)]
__device__ int   g_lei32[MAXE];
__device__ int   g_cei32[MAXE];
__device__ int   g_is64;

// ---------------- bf16 split scratch ----------------
__device__ __nv_bfloat16 g_lcur_h[MAXL * 128], g_lcur_l[MAXL * 128];
__device__ __nv_bfloat16 g_ccur_h[MAXC * 128], g_ccur_l[MAXC * 128];
__device__ __nv_bfloat16 g_mw_h[98304],  g_mw_l[98304];      // 6 MLP weights 128x128
__device__ __nv_bfloat16 g_gw_h[245760], g_gw_l[245760];     // GRU gate weights
__device__ float g_bcat_c[512], g_bcat_l[512];

// GRU weight pool offsets (elements)
#define OFF_WRZC 0
#define OFF_WINC 65536
#define OFF_WHNC 81920
#define OFF_WRZL 98304
#define OFF_WINL 196608
#define OFF_WHNL 229376

// =================== helpers ===================
__device__ __forceinline__ uint32_t smem_to_u32(const void* p) {
    uint32_t a;
    asm("{ .reg .u64 t; cvta.to.shared.u64 t, %1; cvt.u32.u64 %0, t; }"
        : "=r"(a) : "l"(p));
    return a;
}
__device__ __forceinline__ void ldx4(uint32_t* r, uint32_t addr) {
    asm volatile("ldmatrix.sync.aligned.m8n8.x4.shared.b16 {%0,%1,%2,%3}, [%4];"
                 : "=r"(r[0]), "=r"(r[1]), "=r"(r[2]), "=r"(r[3]) : "r"(addr));
}
__device__ __forceinline__ void ldx2(uint32_t* r, uint32_t addr) {
    asm volatile("ldmatrix.sync.aligned.m8n8.x2.shared.b16 {%0,%1}, [%2];"
                 : "=r"(r[0]), "=r"(r[1]) : "r"(addr));
}
__device__ __forceinline__ void mma_bf16(float* d, const uint32_t* a, const uint32_t* b) {
    asm volatile("mma.sync.aligned.m16n8k16.row.col.f32.bf16.bf16.f32 "
                 "{%0,%1,%2,%3}, {%4,%5,%6,%7}, {%8,%9}, {%0,%1,%2,%3};"
                 : "+f"(d[0]), "+f"(d[1]), "+f"(d[2]), "+f"(d[3])
                 : "r"(a[0]), "r"(a[1]), "r"(a[2]), "r"(a[3]), "r"(b[0]), "r"(b[1]));
}
__device__ __forceinline__ uint32_t pack_h(float x, float y) {
    __nv_bfloat162 p(__float2bfloat16(x), __float2bfloat16(y));
    return *(uint32_t*)&p;
}
__device__ __forceinline__ uint32_t pack_l(float x, float y) {
    __nv_bfloat16 hx = __float2bfloat16(x), hy = __float2bfloat16(y);
    __nv_bfloat162 p(__float2bfloat16(x - __bfloat162float(hx)),
                     __float2bfloat16(y - __bfloat162float(hy)));
    return *(uint32_t*)&p;
}

#define MAT_BYTES 18432
#define SMEM_GATES 73728
#define SMEM_MLP   110592

// =================== fused 2-layer MLP (unchanged from R7) ===================
template<int XORROW>
__global__ __launch_bounds__(256, 2)
void fused_mlp(const __nv_bfloat16* __restrict__ Ah, const __nv_bfloat16* __restrict__ Al,
               const __nv_bfloat16* __restrict__ W1h, const __nv_bfloat16* __restrict__ W1l,
               const float* __restrict__ b1,
               const __nv_bfloat16* __restrict__ W2h, const __nv_bfloat16* __restrict__ W2l,
               const float* __restrict__ b2,
               float* __restrict__ out, int N)
{
    extern __shared__ char smem[];
    const uint32_t sb = smem_to_u32(smem);
    const int tid  = threadIdx.x;
    const int lane = tid & 31;
    const int wid  = tid >> 5;
    const int wm   = wid >> 2;
    const int wn   = wid & 3;
    const int bm   = blockIdx.x * 128;

    const uint32_t aOff = (uint32_t)(wm * 64 + (lane & 15)) * 144 + ((lane >> 4) << 4);
    const uint32_t bOff = (uint32_t)(wn * 32 + (lane & 7)) * 144 + (((lane >> 3) & 1) << 4);

    float acc[4][4][4] = {};

    #pragma unroll
    for (int kc = 0; kc < 2; kc++) {
        if (kc) __syncthreads();
        const int k0 = kc << 6;
        #pragma unroll
        for (int t = 0; t < 4; t++) {
            int i = tid + (t << 8);
            int row = i >> 3, unit = i & 7;
            char* dst = smem + (size_t)row * 144 + (unit << 4);
            int grow = bm + row;
            uint4 vh = make_uint4(0, 0, 0, 0), vl = vh;
            if (grow < N) {
                int sr = XORROW ? (grow ^ 1) : grow;
                vh = ((const uint4*)(Ah + (size_t)sr * 128 + k0))[unit];
                vl = ((const uint4*)(Al + (size_t)sr * 128 + k0))[unit];
            }
            *(uint4*)dst               = vh;
            *(uint4*)(dst + MAT_BYTES) = vl;
            *(uint4*)(dst + 4 * MAT_BYTES) = ((const uint4*)(W1h + (size_t)row * 128 + k0))[unit];
            *(uint4*)(dst + 5 * MAT_BYTES) = ((const uint4*)(W1l + (size_t)row * 128 + k0))[unit];
        }
        __syncthreads();
        #pragma unroll
        for (int k16 = 0; k16 < 4; k16++) {
            const uint32_t kb = k16 << 5;
            uint32_t ah[4][4], al[4][4];
            #pragma unroll
            for (int mi = 0; mi < 4; mi++) {
                ldx4(ah[mi], sb + aOff + mi * (16 * 144) + kb);
                ldx4(al[mi], sb + MAT_BYTES + aOff + mi * (16 * 144) + kb);
            }
            #pragma unroll
            for (int ni = 0; ni < 4; ni++) {
                uint32_t bh[2], bl[2];
                ldx2(bh, sb + 4 * MAT_BYTES + bOff + ni * (8 * 144) + kb);
                ldx2(bl, sb + 5 * MAT_BYTES + bOff + ni * (8 * 144) + kb);
                #pragma unroll
                for (int mi = 0; mi < 4; mi++) {
                    mma_bf16(acc[mi][ni], ah[mi], bh);
                    mma_bf16(acc[mi][ni], al[mi], bh);
                    mma_bf16(acc[mi][ni], ah[mi], bl);
                }
            }
        }
    }
    __syncthreads();

    #pragma unroll
    for (int ni = 0; ni < 4; ni++) {
        int c = wn * 32 + ni * 8 + ((lane & 3) << 1);
        float2 bv = *(const float2*)(b1 + c);
        uint32_t roff = (uint32_t)(c >> 6) * MAT_BYTES + (uint32_t)(c & 63) * 2;
        #pragma unroll
        for (int mi = 0; mi < 4; mi++) {
            int rl0 = wm * 64 + mi * 16 + (lane >> 2);
            float vx0 = fmaxf(acc[mi][ni][0] + bv.x, 0.f);
            float vy0 = fmaxf(acc[mi][ni][1] + bv.y, 0.f);
            float vx1 = fmaxf(acc[mi][ni][2] + bv.x, 0.f);
            float vy1 = fmaxf(acc[mi][ni][3] + bv.y, 0.f);
            uint32_t o0 = roff + (uint32_t)rl0 * 144;
            uint32_t o1 = roff + (uint32_t)(rl0 + 8) * 144;
            *(uint32_t*)(smem + o0) = pack_h(vx0, vy0);
            *(uint32_t*)(smem + o0 + 2 * MAT_BYTES) = pack_l(vx0, vy0);
            *(uint32_t*)(smem + o1) = pack_h(vx1, vy1);
            *(uint32_t*)(smem + o1 + 2 * MAT_BYTES) = pack_l(vx1, vy1);
            acc[mi][ni][0] = acc[mi][ni][1] = acc[mi][ni][2] = acc[mi][ni][3] = 0.f;
        }
    }
    __syncthreads();

    #pragma unroll
    for (int kc = 0; kc < 2; kc++) {
        if (kc) __syncthreads();
        const int k0 = kc << 6;
        #pragma unroll
        for (int t = 0; t < 4; t++) {
            int i = tid + (t << 8);
            int row = i >> 3, unit = i & 7;
            char* dst = smem + (size_t)row * 144 + (unit << 4);
            *(uint4*)(dst + 4 * MAT_BYTES) = ((const uint4*)(W2h + (size_t)row * 128 + k0))[unit];
            *(uint4*)(dst + 5 * MAT_BYTES) = ((const uint4*)(W2l + (size_t)row * 128 + k0))[unit];
        }
        __syncthreads();
        const uint32_t ahBase = sb + (uint32_t)kc * MAT_BYTES + aOff;
        const uint32_t alBase = sb + (uint32_t)(2 + kc) * MAT_BYTES + aOff;
        #pragma unroll
        for (int k16 = 0; k16 < 4; k16++) {
            const uint32_t kb = k16 << 5;
            uint32_t ah[4][4], al[4][4];
            #pragma unroll
            for (int mi = 0; mi < 4; mi++) {
                ldx4(ah[mi], ahBase + mi * (16 * 144) + kb);
                ldx4(al[mi], alBase + mi * (16 * 144) + kb);
            }
            #pragma unroll
            for (int ni = 0; ni < 4; ni++) {
                uint32_t bh[2], bl[2];
                ldx2(bh, sb + 4 * MAT_BYTES + bOff + ni * (8 * 144) + kb);
                ldx2(bl, sb + 5 * MAT_BYTES + bOff + ni * (8 * 144) + kb);
                #pragma unroll
                for (int mi = 0; mi < 4; mi++) {
                    mma_bf16(acc[mi][ni], ah[mi], bh);
                    mma_bf16(acc[mi][ni], al[mi], bh);
                    mma_bf16(acc[mi][ni], ah[mi], bl);
                }
            }
        }
    }

    #pragma unroll
    for (int ni = 0; ni < 4; ni++) {
        int c = wn * 32 + ni * 8 + ((lane & 3) << 1);
        float2 bv = *(const float2*)(b2 + c);
        #pragma unroll
        for (int mi = 0; mi < 4; mi++) {
            int r0 = bm + wm * 64 + mi * 16 + (lane >> 2);
            if (r0 < N)
                *(float2*)(out + (size_t)r0 * 128 + c) =
                    make_float2(acc[mi][ni][0] + bv.x, acc[mi][ni][1] + bv.y);
            if (r0 + 8 < N)
                *(float2*)(out + (size_t)(r0 + 8) * 128 + c) =
                    make_float2(acc[mi][ni][2] + bv.x, acc[mi][ni][3] + bv.y);
        }
    }
}

// =================== GRU gate GEMM (dense, no zero pad) ===================
// gates[N, ccol : ccol+M] = A @ W^T + bias[ccol..]; A = NF32 fp32 sources
// (128 cols each, fused split) then optional split-bf16 source (128 cols).
// grid = (ceil(N/128), M/128). gates ld = 512.
template<int NF32>
__global__ __launch_bounds__(256, 2)
void gates_gemm(const float* __restrict__ Af0, const float* __restrict__ Af1,
                const __nv_bfloat16* __restrict__ Ah, const __nv_bfloat16* __restrict__ Al,
                const __nv_bfloat16* __restrict__ Wh, const __nv_bfloat16* __restrict__ Wl,
                const float* __restrict__ bias,
                float* __restrict__ gates, int ccol, int N, int K)
{
    extern __shared__ char smem[];
    const uint32_t sb = smem_to_u32(smem);
    const int tid  = threadIdx.x;
    const int lane = tid & 31;
    const int wid  = tid >> 5;
    const int wm   = wid >> 2;
    const int wn   = wid & 3;
    const int bm   = blockIdx.x * 128;
    const int bn   = blockIdx.y * 128;
    const int nchunk = K >> 6;

    float acc[4][4][4] = {};
    const uint32_t aOff = (uint32_t)(wm * 64 + (lane & 15)) * 144 + ((lane >> 4) << 4);
    const uint32_t bOff = (uint32_t)(wn * 32 + (lane & 7)) * 144 + (((lane >> 3) & 1) << 4);

    for (int kc = 0; kc < nchunk; kc++) {
        if (kc) __syncthreads();
        const int k0 = kc << 6;
        const int s  = kc >> 1;
        #pragma unroll
        for (int t = 0; t < 4; t++) {
            int i = tid + (t << 8);
            int row = i >> 3, unit = i & 7;
            char* dst = smem + (size_t)row * 144 + (unit << 4);
            int grow = bm + row;
            uint4 vh = make_uint4(0, 0, 0, 0), vl = vh;
            if (grow < N) {
                if (s < NF32) {
                    const float* src = (s == 0 ? Af0 : Af1)
                                     + (size_t)grow * 128 + ((kc & 1) << 6) + unit * 8;
                    float4 f0 = *(const float4*)src;
                    float4 f1 = *(const float4*)(src + 4);
                    vh.x = pack_h(f0.x, f0.y); vl.x = pack_l(f0.x, f0.y);
                    vh.y = pack_h(f0.z, f0.w); vl.y = pack_l(f0.z, f0.w);
                    vh.z = pack_h(f1.x, f1.y); vl.z = pack_l(f1.x, f1.y);
                    vh.w = pack_h(f1.z, f1.w); vl.w = pack_l(f1.z, f1.w);
                } else {
                    const int kb16 = kc - 2 * NF32;   // chunk within bf16 source
                    const __nv_bfloat16* sa = Ah + (size_t)grow * 128 + (kb16 << 6);
                    const __nv_bfloat16* sl = Al + (size_t)grow * 128 + (kb16 << 6);
                    vh = ((const uint4*)sa)[unit];
                    vl = ((const uint4*)sl)[unit];
                }
            }
            *(uint4*)dst               = vh;
            *(uint4*)(dst + MAT_BYTES) = vl;
            *(uint4*)(dst + 2 * MAT_BYTES) = ((const uint4*)(Wh + (size_t)(bn + row) * K + k0))[unit];
            *(uint4*)(dst + 3 * MAT_BYTES) = ((const uint4*)(Wl + (size_t)(bn + row) * K + k0))[unit];
        }
        __syncthreads();

        #pragma unroll
        for (int k16 = 0; k16 < 4; k16++) {
            const uint32_t kb = k16 << 5;
            uint32_t ah[4][4], al[4][4];
            #pragma unroll
            for (int mi = 0; mi < 4; mi++) {
                ldx4(ah[mi], sb + aOff + mi * (16 * 144) + kb);
                ldx4(al[mi], sb + MAT_BYTES + aOff + mi * (16 * 144) + kb);
            }
            #pragma unroll
            for (int ni = 0; ni < 4; ni++) {
                uint32_t bh[2], bl[2];
                ldx2(bh, sb + 2 * MAT_BYTES + bOff + ni * (8 * 144) + kb);
                ldx2(bl, sb + 3 * MAT_BYTES + bOff + ni * (8 * 144) + kb);
                #pragma unroll
                for (int mi = 0; mi < 4; mi++) {
                    mma_bf16(acc[mi][ni], ah[mi], bh);
                    mma_bf16(acc[mi][ni], al[mi], bh);
                    mma_bf16(acc[mi][ni], ah[mi], bl);
                }
            }
        }
    }

    #pragma unroll
    for (int ni = 0; ni < 4; ni++) {
        int gcol = ccol + bn + wn * 32 + ni * 8 + ((lane & 3) << 1);
        float2 bv = *(const float2*)(bias + gcol);
        #pragma unroll
        for (int mi = 0; mi < 4; mi++) {
            int r0 = bm + wm * 64 + mi * 16 + (lane >> 2);
            if (r0 < N)
                *(float2*)(gates + (size_t)r0 * 512 + gcol) =
                    make_float2(acc[mi][ni][0] + bv.x, acc[mi][ni][1] + bv.y);
            if (r0 + 8 < N)
                *(float2*)(gates + (size_t)(r0 + 8) * 512 + gcol) =
                    make_float2(acc[mi][ni][2] + bv.x, acc[mi][ni][3] + bv.y);
        }
    }
}

// =================== support kernels ===================
__global__ void detect_idx64(const unsigned int* __restrict__ a,
                             const unsigned int* __restrict__ b, int E)
{
    int n = E < 32 ? E : 32;
    int is64 = 1;
    for (int i = 0; i < n; i++) {
        if (a[2 * i + 1] != 0u) is64 = 0;
        if (b[2 * i + 1] != 0u) is64 = 0;
    }
    g_is64 = is64;
}

__global__ void convert_idx(const void* __restrict__ srcA, const void* __restrict__ srcB,
                            int* __restrict__ dstA, int* __restrict__ dstB, int E)
{
    int e = blockIdx.x * blockDim.x + threadIdx.x;
    if (e >= E) return;
    if (g_is64) {
        dstA[e] = (int)((const long long*)srcA)[e];
        dstB[e] = (int)((const long long*)srcB)[e];
    } else {
        dstA[e] = ((const int*)srcA)[e];
        dstB[e] = ((const int*)srcB)[e];
    }
}

struct PrepArgs {
    const float4* mlp[6];
    const float* cWih; const float* cWhh;
    const float* lWih; const float* lWhh;
    const float* cbih; const float* cbhh;
    const float* lbih; const float* lbhh;
};

// dense gate weight elements (no zero padding anywhere)
__device__ __forceinline__ float wrz_c(const PrepArgs& a, int m, int k) {
    return (k < 128) ? a.cWih[m * 128 + k] : a.cWhh[m * 128 + (k - 128)];
}
__device__ __forceinline__ float wrz_l(const PrepArgs& a, int m, int k) {
    return (k < 256) ? a.lWih[m * 256 + k] : a.lWhh[m * 128 + (k - 256)];
}

#define PQ_MLP  24576
#define PQ_WRZC 16384
#define PQ_WINC 4096
#define PQ_WHNC 4096
#define PQ_WRZL 24576
#define PQ_WINL 8192
#define PQ_WHNL 4096
#define PREP_TOT (PQ_MLP + PQ_WRZC + PQ_WINC + PQ_WHNC + PQ_WRZL + PQ_WINL + PQ_WHNL + 1024)

__global__ void prep_all(PrepArgs a,
                         __nv_bfloat16* __restrict__ mwh, __nv_bfloat16* __restrict__ mwl,
                         __nv_bfloat16* __restrict__ gwh, __nv_bfloat16* __restrict__ gwl,
                         float* __restrict__ bcc, float* __restrict__ bcl)
{
    int i = blockIdx.x * blockDim.x + threadIdx.x;
    if (i >= PREP_TOT) return;

    float v0, v1, v2, v3;
    __nv_bfloat16 *oh, *ol;
    long long obase;

    if (i < PQ_MLP) {
        int midx = i >> 12;
        float4 v = a.mlp[midx][i & 4095];
        v0 = v.x; v1 = v.y; v2 = v.z; v3 = v.w;
        oh = mwh; ol = mwl; obase = (long long)i * 4;
    } else if (i < PQ_MLP + PQ_WRZC) {
        int base = (i - PQ_MLP) * 4, m = base >> 8, k = base & 255;
        v0 = wrz_c(a, m, k);     v1 = wrz_c(a, m, k + 1);
        v2 = wrz_c(a, m, k + 2); v3 = wrz_c(a, m, k + 3);
        oh = gwh; ol = gwl; obase = OFF_WRZC + base;
    } else if (i < PQ_MLP + PQ_WRZC + PQ_WINC) {
        int base = (i - PQ_MLP - PQ_WRZC) * 4, m = base >> 7, k = base & 127;
        const float* s = a.cWih + (256 + m) * 128 + k;
        v0 = s[0]; v1 = s[1]; v2 = s[2]; v3 = s[3];
        oh = gwh; ol = gwl; obase = OFF_WINC + base;
    } else if (i < PQ_MLP + PQ_WRZC + PQ_WINC + PQ_WHNC) {
        int base = (i - PQ_MLP - PQ_WRZC - PQ_WINC) * 4, m = base >> 7, k = base & 127;
        const float* s = a.cWhh + (256 + m) * 128 + k;
        v0 = s[0]; v1 = s[1]; v2 = s[2]; v3 = s[3];
        oh = gwh; ol = gwl; obase = OFF_WHNC + base;
    } else if (i < PQ_MLP + PQ_WRZC + PQ_WINC + PQ_WHNC + PQ_WRZL) {
        int base = (i - PQ_MLP - PQ_WRZC - PQ_WINC - PQ_WHNC) * 4;
        int m = base / 384, k = base % 384;
        v0 = wrz_l(a, m, k);     v1 = wrz_l(a, m, k + 1);
        v2 = wrz_l(a, m, k + 2); v3 = wrz_l(a, m, k + 3);
        oh = gwh; ol = gwl; obase = OFF_WRZL + base;
    } else if (i < PQ_MLP + PQ_WRZC + PQ_WINC + PQ_WHNC + PQ_WRZL + PQ_WINL) {
        int base = (i - PQ_MLP - PQ_WRZC - PQ_WINC - PQ_WHNC - PQ_WRZL) * 4;
        int m = base >> 8, k = base & 255;
        const float* s = a.lWih + (256 + m) * 256 + k;
        v0 = s[0]; v1 = s[1]; v2 = s[2]; v3 = s[3];
        oh = gwh; ol = gwl; obase = OFF_WINL + base;
    } else if (i < PREP_TOT - 1024) {
        int base = (i - (PREP_TOT - 1024 - PQ_WHNL)) * 4, m = base >> 7, k = base & 127;
        const float* s = a.lWhh + (256 + m) * 128 + k;
        v0 = s[0]; v1 = s[1]; v2 = s[2]; v3 = s[3];
        oh = gwh; ol = gwl; obase = OFF_WHNL + base;
    } else {
        int j = i - (PREP_TOT - 1024);
        if (j < 512) {
            bcc[j] = (j < 256) ? a.cbih[j] + a.cbhh[j]
                   : (j < 384) ? a.cbih[j] : a.cbhh[j - 128];
        } else {
            int m = j - 512;
            bcl[m] = (m < 256) ? a.lbih[m] + a.lbhh[m]
                   : (m < 384) ? a.lbih[m] : a.lbhh[m - 128];
        }
        return;
    }
    *(uint2*)(oh + obase) = make_uint2(pack_h(v0, v1), pack_h(v2, v3));
    *(uint2*)(ol + obase) = make_uint2(pack_l(v0, v1), pack_l(v2, v3));
}

__global__ void split_pair(const float* __restrict__ x,
                           __nv_bfloat16* __restrict__ xh,
                           __nv_bfloat16* __restrict__ xl, long long n4)
{
    long long i = (long long)blockIdx.x * blockDim.x + threadIdx.x;
    if (i >= n4) return;
    float4 v = *(const float4*)(x + i * 4);
    *(uint2*)(xh + i * 4) = make_uint2(pack_h(v.x, v.y), pack_h(v.z, v.w));
    *(uint2*)(xl + i * 4) = make_uint2(pack_l(v.x, v.y), pack_l(v.z, v.w));
}

__global__ void edge_aggr(const int* __restrict__ src, const int* __restrict__ dst,
                          const float* __restrict__ feat, float* __restrict__ aggr,
                          int E, int maxS, int maxD)
{
    long long idx = (long long)blockIdx.x * blockDim.x + threadIdx.x;
    int e = (int)(idx >> 5);
    if (e >= E) return;
    int c = (int)(idx & 31) << 2;
    int s = src[e], d = dst[e];
    if ((unsigned)s >= (unsigned)maxS || (unsigned)d >= (unsigned)maxD) return;
    float4 v = *(const float4*)(feat + (size_t)s * 128 + c);
    float* p = aggr + (size_t)d * 128 + c;
    atomicAdd(p + 0, v.x);
    atomicAdd(p + 1, v.y);
    atomicAdd(p + 2, v.z);
    atomicAdd(p + 3, v.w);
}

// GRU pointwise: gates = [rz_sum(256) | i_n(128) | h_n(128)]
__global__ void gru_pointwise3(const float* __restrict__ g, const float* __restrict__ h,
                               float* __restrict__ hout,
                               __nv_bfloat16* __restrict__ hh, __nv_bfloat16* __restrict__ hl,
                               int N)
{
    long long idx = (long long)blockIdx.x * blockDim.x + threadIdx.x;
    if (idx >= (long long)N * 32) return;
    int n = (int)(idx >> 5);
    int j = (int)(idx & 31) << 2;
    const float* gp = g + (size_t)n * 512;
    float4 R  = *(const float4*)(gp + j);
    float4 Z  = *(const float4*)(gp + 128 + j);
    float4 I  = *(const float4*)(gp + 256 + j);
    float4 Hn = *(const float4*)(gp + 384 + j);
    float4 hv = *(const float4*)(h + (size_t)n * 128 + j);

    float4 o;
    {
        float r = 1.f / (1.f + expf(-R.x)), z = 1.f / (1.f + expf(-Z.x));
        o.x = (1.f - z) * tanhf(I.x + r * Hn.x) + z * hv.x;
    }
    {
        float r = 1.f / (1.f + expf(-R.y)), z = 1.f / (1.f + expf(-Z.y));
        o.y = (1.f - z) * tanhf(I.y + r * Hn.y) + z * hv.y;
    }
    {
        float r = 1.f / (1.f + expf(-R.z)), z = 1.f / (1.f + expf(-Z.z));
        o.z = (1.f - z) * tanhf(I.z + r * Hn.z) + z * hv.z;
    }
    {
        float r = 1.f / (1.f + expf(-R.w)), z = 1.f / (1.f + expf(-Z.w));
        o.w = (1.f - z) * tanhf(I.w + r * Hn.w) + z * hv.w;
    }
    *(float4*)(hout + (size_t)n * 128 + j) = o;
    *(uint2*)(hh + (size_t)n * 128 + j) = make_uint2(pack_h(o.x, o.y), pack_h(o.z, o.w));
    *(uint2*)(hl + (size_t)n * 128 + j) = make_uint2(pack_l(o.x, o.y), pack_l(o.z, o.w));
}

// =================== host side ===================
extern "C" void kernel_launch(void* const* d_in, const int* in_sizes, int n_in,
                              void* d_out, int out_size)
{
    int base = (n_in >= 26) ? 2 : 0;

    const void*  l_ei_raw = d_in[base + 0];
    const void*  c_ei_raw = d_in[base + 1];
    const float* l_emb0   = (const float*)d_in[base + 2];
    const float* c_emb0   = (const float*)d_in[base + 3];

    const float* l2c_W1 = (const float*)d_in[base + 4];
    const float* l2c_b1 = (const float*)d_in[base + 5];
    const float* l2c_W2 = (const float*)d_in[base + 6];
    const float* l2c_b2 = (const float*)d_in[base + 7];
    const float* c2l_W1 = (const float*)d_in[base + 8];
    const float* c2l_b1 = (const float*)d_in[base + 9];
    const float* c2l_W2 = (const float*)d_in[base + 10];
    const float* c2l_b2 = (const float*)d_in[base + 11];
    const float* l2l_W1 = (const float*)d_in[base + 12];
    const float* l2l_b1 = (const float*)d_in[base + 13];
    const float* l2l_W2 = (const float*)d_in[base + 14];
    const float* l2l_b2 = (const float*)d_in[base + 15];
    const float* cgru_Wih = (const float*)d_in[base + 16];
    const float* cgru_Whh = (const float*)d_in[base + 17];
    const float* cgru_bih = (const float*)d_in[base + 18];
    const float* cgru_bhh = (const float*)d_in[base + 19];
    const float* lgru_Wih = (const float*)d_in[base + 20];
    const float* lgru_Whh = (const float*)d_in[base + 21];
    const float* lgru_bih = (const float*)d_in[base + 22];
    const float* lgru_bhh = (const float*)d_in[base + 23];

    const int E = in_sizes[base + 0];
    const int L = in_sizes[base + 2] / DIM;
    const int C = in_sizes[base + 3] / DIM;

    float* out   = (float*)d_out;
    float* l_out = out;
    float* c_out = out + (size_t)(NITER + 1) * L * DIM;

    float *lfeat, *cfeat, *caggr, *lx0, *l2lm, *gates, *bcc, *bcl;
    int *lei, *cei;
    __nv_bfloat16 *lch, *lcl, *cch, *ccl, *mwh, *mwl, *gwh, *gwl;
    cudaGetSymbolAddress((void**)&lfeat, g_lfeat);
    cudaGetSymbolAddress((void**)&cfeat, g_cfeat);
    cudaGetSymbolAddress((void**)&caggr, g_caggr);
    cudaGetSymbolAddress((void**)&lx0,   g_lx0);
    cudaGetSymbolAddress((void**)&l2lm,  g_l2lm);
    cudaGetSymbolAddress((void**)&gates, g_gates);
    cudaGetSymbolAddress((void**)&lei,   g_lei32);
    cudaGetSymbolAddress((void**)&cei,   g_cei32);
    cudaGetSymbolAddress((void**)&lch,   g_lcur_h);
    cudaGetSymbolAddress((void**)&lcl,   g_lcur_l);
    cudaGetSymbolAddress((void**)&cch,   g_ccur_h);
    cudaGetSymbolAddress((void**)&ccl,   g_ccur_l);
    cudaGetSymbolAddress((void**)&mwh,   g_mw_h);
    cudaGetSymbolAddress((void**)&mwl,   g_mw_l);
    cudaGetSymbolAddress((void**)&gwh,   g_gw_h);
    cudaGetSymbolAddress((void**)&gwl,   g_gw_l);
    cudaGetSymbolAddress((void**)&bcc,   g_bcat_c);
    cudaGetSymbolAddress((void**)&bcl,   g_bcat_l);

    cudaFuncSetAttribute((const void*)fused_mlp<0>, cudaFuncAttributeMaxDynamicSharedMemorySize, SMEM_MLP);
    cudaFuncSetAttribute((const void*)fused_mlp<1>, cudaFuncAttributeMaxDynamicSharedMemorySize, SMEM_MLP);
    cudaFuncSetAttribute((const void*)gates_gemm<0>, cudaFuncAttributeMaxDynamicSharedMemorySize, SMEM_GATES);
    cudaFuncSetAttribute((const void*)gates_gemm<1>, cudaFuncAttributeMaxDynamicSharedMemorySize, SMEM_GATES);
    cudaFuncSetAttribute((const void*)gates_gemm<2>, cudaFuncAttributeMaxDynamicSharedMemorySize, SMEM_GATES);

    // ---- prelude: exactly 5 kernels before first GEMM ----
    detect_idx64<<<1, 1>>>((const unsigned int*)l_ei_raw, (const unsigned int*)c_ei_raw, E);
    convert_idx<<<(E + 255) / 256, 256>>>(l_ei_raw, c_ei_raw, lei, cei, E);

    PrepArgs pa;
    pa.mlp[0] = (const float4*)l2c_W1; pa.mlp[1] = (const float4*)l2c_W2;
    pa.mlp[2] = (const float4*)c2l_W1; pa.mlp[3] = (const float4*)c2l_W2;
    pa.mlp[4] = (const float4*)l2l_W1; pa.mlp[5] = (const float4*)l2l_W2;
    pa.cWih = cgru_Wih; pa.cWhh = cgru_Whh;
    pa.lWih = lgru_Wih; pa.lWhh = lgru_Whh;
    pa.cbih = cgru_bih; pa.cbhh = cgru_bhh;
    pa.lbih = lgru_bih; pa.lbhh = lgru_bhh;
    prep_all<<<(PREP_TOT + 255) / 256, 256>>>(pa, mwh, mwl, gwh, gwl, bcc, bcl);

    split_pair<<<(int)(((long long)L * 32 + 255) / 256), 256>>>(l_emb0, lch, lcl, (long long)L * 32);
    split_pair<<<(int)(((long long)C * 32 + 255) / 256), 256>>>(c_emb0, cch, ccl, (long long)C * 32);

    cudaMemcpyAsync(l_out, l_emb0, (size_t)L * DIM * sizeof(float), cudaMemcpyDeviceToDevice, 0);
    cudaMemcpyAsync(c_out, c_emb0, (size_t)C * DIM * sizeof(float), cudaMemcpyDeviceToDevice, 0);

    __nv_bfloat16 *W_[6], *Wl_[6];
    for (int i = 0; i < 6; i++) { W_[i] = mwh + (size_t)i * 16384; Wl_[i] = mwl + (size_t)i * 16384; }

    const int edge_blocks = (int)(((long long)E * 32 + 255) / 256);
    const float* nfp = nullptr;
    const __nv_bfloat16* nbp = nullptr;

    for (int it = 0; it < NITER; it++) {
        const float* lcur = l_out + (size_t)it * L * DIM;
        const float* ccur = c_out + (size_t)it * C * DIM;
        float* lnext = l_out + (size_t)(it + 1) * L * DIM;
        float* cnext = c_out + (size_t)(it + 1) * C * DIM;

        dim3 gl((L + 127) / 128), gc((C + 127) / 128);
        dim3 gl2((L + 127) / 128, 2), gc2((C + 127) / 128, 2);

        // --- 3 fused MLPs ---
        fused_mlp<0><<<gl, 256, SMEM_MLP>>>(lch, lcl, W_[0], Wl_[0], l2c_b1, W_[1], Wl_[1], l2c_b2, lfeat, L);
        fused_mlp<0><<<gc, 256, SMEM_MLP>>>(cch, ccl, W_[2], Wl_[2], c2l_b1, W_[3], Wl_[3], c2l_b2, cfeat, C);
        fused_mlp<1><<<gl, 256, SMEM_MLP>>>(lch, lcl, W_[4], Wl_[4], l2l_b1, W_[5], Wl_[5], l2l_b2, l2lm, L);

        // --- gather + segment sums ---
        cudaMemsetAsync(caggr, 0, (size_t)C * 128 * sizeof(float), 0);
        cudaMemsetAsync(lx0,   0, (size_t)L * 128 * sizeof(float), 0);
        edge_aggr<<<edge_blocks, 256>>>(lei, cei, lfeat, caggr, E, L, C);
        edge_aggr<<<edge_blocks, 256>>>(cei, lei, cfeat, lx0,   E, C, L);

        // --- clause GRU: rz (M=256,K=256) + i_n (M=128,K=128) + h_n (M=128,K=128) ---
        gates_gemm<1><<<gc2, 256, SMEM_GATES>>>(caggr, nfp, cch, ccl,
                                                gwh + OFF_WRZC, gwl + OFF_WRZC, bcc, gates, 0,   C, 256);
        gates_gemm<1><<<gc,  256, SMEM_GATES>>>(caggr, nfp, nbp, nbp,
                                                gwh + OFF_WINC, gwl + OFF_WINC, bcc, gates, 256, C, 128);
        gates_gemm<0><<<gc,  256, SMEM_GATES>>>(nfp, nfp, cch, ccl,
                                                gwh + OFF_WHNC, gwl + OFF_WHNC, bcc, gates, 384, C, 128);
        gru_pointwise3<<<(int)(((long long)C * 32 + 255) / 256), 256>>>(gates, ccur, cnext, cch, ccl, C);

        // --- literal GRU: rz (M=256,K=384) + i_n (M=128,K=256) + h_n (M=128,K=128) ---
        gates_gemm<2><<<gl2, 256, SMEM_GATES>>>(lx0, l2lm, lch, lcl,
                                                gwh + OFF_WRZL, gwl + OFF_WRZL, bcl, gates, 0,   L, 384);
        gates_gemm<2><<<gl,  256, SMEM_GATES>>>(lx0, l2lm, nbp, nbp,
                                                gwh + OFF_WINL, gwl + OFF_WINL, bcl, gates, 256, L, 256);
        gates_gemm<0><<<gl,  256, SMEM_GATES>>>(nfp, nfp, lch, lcl,
                                                gwh + OFF_WHNL, gwl + OFF_WHNL, bcl, gates, 384, L, 128);
        gru_pointwise3<<<(int)(((long long)L * 32 + 255) / 256), 256>>>(gates, lcur, lnext, lch, lcl, L);
    }
}

// round 9
// speedup vs baseline: 1.1132x; 1.0058x over previous
#include <cuda_runtime.h>
#include <cuda_bf16.h>
#include <math.h>
#include <stdint.h>

#define DIM 128
#define NITER 8

#define MAXL 100096ull
#define MAXC 150016ull
#define MAXN 150016ull
#define MAXE 450048

// ---------------- fp32 scratch ----------------
__device__ float g_lfeat[MAXL * 128];
__device__ float g_cfeat[MAXC * 128];
__device__ float g_caggr[MAXC * 128];
__device__ float g_lx0  [MAXL * 128];
__device__ float g_l2lm [MAXL * 128];
__device__ float g_gates[MAXN * 384];   // [rz_sum(256) | i_n(128)]
__device__ int   g_lei32[MAXE];
__device__ int   g_cei32[MAXE];
__device__ int   g_is64;

// ---------------- CSR scratch ----------------
#define MAXT (MAXC + MAXL + 2)
__device__ int g_cnt [MAXT];
__device__ int g_off [MAXT];
__device__ int g_cur [MAXT];
__device__ int g_bsum[1024];
__device__ int g_permc[MAXE];
__device__ int g_perml[MAXE];

// ---------------- bf16 split scratch ----------------
__device__ __nv_bfloat16 g_lcur_h[MAXL * 128], g_lcur_l[MAXL * 128];
__device__ __nv_bfloat16 g_ccur_h[MAXC * 128], g_ccur_l[MAXC * 128];
__device__ __nv_bfloat16 g_mw_h[98304],  g_mw_l[98304];
__device__ __nv_bfloat16 g_gw_h[245760], g_gw_l[245760];
__device__ float g_bcat_c[512], g_bcat_l[512];

#define OFF_WRZC 0
#define OFF_WINC 65536
#define OFF_WHNC 81920
#define OFF_WRZL 98304
#define OFF_WINL 196608
#define OFF_WHNL 229376

// =================== helpers ===================
__device__ __forceinline__ uint32_t smem_to_u32(const void* p) {
    uint32_t a;
    asm("{ .reg .u64 t; cvta.to.shared.u64 t, %1; cvt.u32.u64 %0, t; }"
        : "=r"(a) : "l"(p));
    return a;
}
__device__ __forceinline__ void ldx4(uint32_t* r, uint32_t addr) {
    asm volatile("ldmatrix.sync.aligned.m8n8.x4.shared.b16 {%0,%1,%2,%3}, [%4];"
                 : "=r"(r[0]), "=r"(r[1]), "=r"(r[2]), "=r"(r[3]) : "r"(addr));
}
__device__ __forceinline__ void ldx2(uint32_t* r, uint32_t addr) {
    asm volatile("ldmatrix.sync.aligned.m8n8.x2.shared.b16 {%0,%1}, [%2];"
                 : "=r"(r[0]), "=r"(r[1]) : "r"(addr));
}
__device__ __forceinline__ void mma_bf16(float* d, const uint32_t* a, const uint32_t* b) {
    asm volatile("mma.sync.aligned.m16n8k16.row.col.f32.bf16.bf16.f32 "
                 "{%0,%1,%2,%3}, {%4,%5,%6,%7}, {%8,%9}, {%0,%1,%2,%3};"
                 : "+f"(d[0]), "+f"(d[1]), "+f"(d[2]), "+f"(d[3])
                 : "r"(a[0]), "r"(a[1]), "r"(a[2]), "r"(a[3]), "r"(b[0]), "r"(b[1]));
}
__device__ __forceinline__ uint32_t pack_h(float x, float y) {
    __nv_bfloat162 p(__float2bfloat16(x), __float2bfloat16(y));
    return *(uint32_t*)&p;
}
__device__ __forceinline__ uint32_t pack_l(float x, float y) {
    __nv_bfloat16 hx = __float2bfloat16(x), hy = __float2bfloat16(y);
    __nv_bfloat162 p(__float2bfloat16(x - __bfloat162float(hx)),
                     __float2bfloat16(y - __bfloat162float(hy)));
    return *(uint32_t*)&p;
}
__device__ __forceinline__ float sigm(float x) { return 1.f / (1.f + expf(-x)); }

#define MAT_BYTES 18432
#define SMEM_GATES 73728
#define SMEM_MLP   110592

// =================== fused 2-layer MLP (unchanged) ===================
template<int XORROW>
__global__ __launch_bounds__(256, 2)
void fused_mlp(const __nv_bfloat16* __restrict__ Ah, const __nv_bfloat16* __restrict__ Al,
               const __nv_bfloat16* __restrict__ W1h, const __nv_bfloat16* __restrict__ W1l,
               const float* __restrict__ b1,
               const __nv_bfloat16* __restrict__ W2h, const __nv_bfloat16* __restrict__ W2l,
               const float* __restrict__ b2,
               float* __restrict__ out, int N)
{
    extern __shared__ char smem[];
    const uint32_t sb = smem_to_u32(smem);
    const int tid  = threadIdx.x;
    const int lane = tid & 31;
    const int wid  = tid >> 5;
    const int wm   = wid >> 2;
    const int wn   = wid & 3;
    const int bm   = blockIdx.x * 128;

    const uint32_t aOff = (uint32_t)(wm * 64 + (lane & 15)) * 144 + ((lane >> 4) << 4);
    const uint32_t bOff = (uint32_t)(wn * 32 + (lane & 7)) * 144 + (((lane >> 3) & 1) << 4);

    float acc[4][4][4] = {};

    #pragma unroll
    for (int kc = 0; kc < 2; kc++) {
        if (kc) __syncthreads();
        const int k0 = kc << 6;
        #pragma unroll
        for (int t = 0; t < 4; t++) {
            int i = tid + (t << 8);
            int row = i >> 3, unit = i & 7;
            char* dst = smem + (size_t)row * 144 + (unit << 4);
            int grow = bm + row;
            uint4 vh = make_uint4(0, 0, 0, 0), vl = vh;
            if (grow < N) {
                int sr = XORROW ? (grow ^ 1) : grow;
                vh = ((const uint4*)(Ah + (size_t)sr * 128 + k0))[unit];
                vl = ((const uint4*)(Al + (size_t)sr * 128 + k0))[unit];
            }
            *(uint4*)dst               = vh;
            *(uint4*)(dst + MAT_BYTES) = vl;
            *(uint4*)(dst + 4 * MAT_BYTES) = ((const uint4*)(W1h + (size_t)row * 128 + k0))[unit];
            *(uint4*)(dst + 5 * MAT_BYTES) = ((const uint4*)(W1l + (size_t)row * 128 + k0))[unit];
        }
        __syncthreads();
        #pragma unroll
        for (int k16 = 0; k16 < 4; k16++) {
            const uint32_t kb = k16 << 5;
            uint32_t ah[4][4], al[4][4];
            #pragma unroll
            for (int mi = 0; mi < 4; mi++) {
                ldx4(ah[mi], sb + aOff + mi * (16 * 144) + kb);
                ldx4(al[mi], sb + MAT_BYTES + aOff + mi * (16 * 144) + kb);
            }
            #pragma unroll
            for (int ni = 0; ni < 4; ni++) {
                uint32_t bh[2], bl[2];
                ldx2(bh, sb + 4 * MAT_BYTES + bOff + ni * (8 * 144) + kb);
                ldx2(bl, sb + 5 * MAT_BYTES + bOff + ni * (8 * 144) + kb);
                #pragma unroll
                for (int mi = 0; mi < 4; mi++) {
                    mma_bf16(acc[mi][ni], ah[mi], bh);
                    mma_bf16(acc[mi][ni], al[mi], bh);
                    mma_bf16(acc[mi][ni], ah[mi], bl);
                }
            }
        }
    }
    __syncthreads();

    #pragma unroll
    for (int ni = 0; ni < 4; ni++) {
        int c = wn * 32 + ni * 8 + ((lane & 3) << 1);
        float2 bv = *(const float2*)(b1 + c);
        uint32_t roff = (uint32_t)(c >> 6) * MAT_BYTES + (uint32_t)(c & 63) * 2;
        #pragma unroll
        for (int mi = 0; mi < 4; mi++) {
            int rl0 = wm * 64 + mi * 16 + (lane >> 2);
            float vx0 = fmaxf(acc[mi][ni][0] + bv.x, 0.f);
            float vy0 = fmaxf(acc[mi][ni][1] + bv.y, 0.f);
            float vx1 = fmaxf(acc[mi][ni][2] + bv.x, 0.f);
            float vy1 = fmaxf(acc[mi][ni][3] + bv.y, 0.f);
            uint32_t o0 = roff + (uint32_t)rl0 * 144;
            uint32_t o1 = roff + (uint32_t)(rl0 + 8) * 144;
            *(uint32_t*)(smem + o0) = pack_h(vx0, vy0);
            *(uint32_t*)(smem + o0 + 2 * MAT_BYTES) = pack_l(vx0, vy0);
            *(uint32_t*)(smem + o1) = pack_h(vx1, vy1);
            *(uint32_t*)(smem + o1 + 2 * MAT_BYTES) = pack_l(vx1, vy1);
            acc[mi][ni][0] = acc[mi][ni][1] = acc[mi][ni][2] = acc[mi][ni][3] = 0.f;
        }
    }
    __syncthreads();

    #pragma unroll
    for (int kc = 0; kc < 2; kc++) {
        if (kc) __syncthreads();
        const int k0 = kc << 6;
        #pragma unroll
        for (int t = 0; t < 4; t++) {
            int i = tid + (t << 8);
            int row = i >> 3, unit = i & 7;
            char* dst = smem + (size_t)row * 144 + (unit << 4);
            *(uint4*)(dst + 4 * MAT_BYTES) = ((const uint4*)(W2h + (size_t)row * 128 + k0))[unit];
            *(uint4*)(dst + 5 * MAT_BYTES) = ((const uint4*)(W2l + (size_t)row * 128 + k0))[unit];
        }
        __syncthreads();
        const uint32_t ahBase = sb + (uint32_t)kc * MAT_BYTES + aOff;
        const uint32_t alBase = sb + (uint32_t)(2 + kc) * MAT_BYTES + aOff;
        #pragma unroll
        for (int k16 = 0; k16 < 4; k16++) {
            const uint32_t kb = k16 << 5;
            uint32_t ah[4][4], al[4][4];
            #pragma unroll
            for (int mi = 0; mi < 4; mi++) {
                ldx4(ah[mi], ahBase + mi * (16 * 144) + kb);
                ldx4(al[mi], alBase + mi * (16 * 144) + kb);
            }
            #pragma unroll
            for (int ni = 0; ni < 4; ni++) {
                uint32_t bh[2], bl[2];
                ldx2(bh, sb + 4 * MAT_BYTES + bOff + ni * (8 * 144) + kb);
                ldx2(bl, sb + 5 * MAT_BYTES + bOff + ni * (8 * 144) + kb);
                #pragma unroll
                for (int mi = 0; mi < 4; mi++) {
                    mma_bf16(acc[mi][ni], ah[mi], bh);
                    mma_bf16(acc[mi][ni], al[mi], bh);
                    mma_bf16(acc[mi][ni], ah[mi], bl);
                }
            }
        }
    }

    #pragma unroll
    for (int ni = 0; ni < 4; ni++) {
        int c = wn * 32 + ni * 8 + ((lane & 3) << 1);
        float2 bv = *(const float2*)(b2 + c);
        #pragma unroll
        for (int mi = 0; mi < 4; mi++) {
            int r0 = bm + wm * 64 + mi * 16 + (lane >> 2);
            if (r0 < N)
                *(float2*)(out + (size_t)r0 * 128 + c) =
                    make_float2(acc[mi][ni][0] + bv.x, acc[mi][ni][1] + bv.y);
            if (r0 + 8 < N)
                *(float2*)(out + (size_t)(r0 + 8) * 128 + c) =
                    make_float2(acc[mi][ni][2] + bv.x, acc[mi][ni][3] + bv.y);
        }
    }
}

// =================== GRU gate GEMM (+optional fused pointwise) ===================
// Non-PW: gates[N, ccol:ccol+M] = A @ W^T + bias[ccol..]  (gates ld = 384)
// PW (NF32=0, K=128, grid y=1): Hn = h_split @ W^T + bias; then
//   h' = (1-sig(Z))*tanh(I + sig(R)*Hn) + sig(Z)*h ; writes hout + bf16 split.
template<int NF32, int PW>
__global__ __launch_bounds__(256, 2)
void gates_gemm(const float* __restrict__ Af0, const float* __restrict__ Af1,
                const __nv_bfloat16* __restrict__ Ah, const __nv_bfloat16* __restrict__ Al,
                const __nv_bfloat16* __restrict__ Wh, const __nv_bfloat16* __restrict__ Wl,
                const float* __restrict__ bias,
                float* __restrict__ gates, int ccol, int N, int K,
                const float* __restrict__ hcur, float* __restrict__ hout,
                __nv_bfloat16* __restrict__ hh, __nv_bfloat16* __restrict__ hl)
{
    extern __shared__ char smem[];
    const uint32_t sb = smem_to_u32(smem);
    const int tid  = threadIdx.x;
    const int lane = tid & 31;
    const int wid  = tid >> 5;
    const int wm   = wid >> 2;
    const int wn   = wid & 3;
    const int bm   = blockIdx.x * 128;
    const int bn   = blockIdx.y * 128;
    const int nchunk = K >> 6;

    float acc[4][4][4] = {};
    const uint32_t aOff = (uint32_t)(wm * 64 + (lane & 15)) * 144 + ((lane >> 4) << 4);
    const uint32_t bOff = (uint32_t)(wn * 32 + (lane & 7)) * 144 + (((lane >> 3) & 1) << 4);

    for (int kc = 0; kc < nchunk; kc++) {
        if (kc) __syncthreads();
        const int k0 = kc << 6;
        const int s  = kc >> 1;
        #pragma unroll
        for (int t = 0; t < 4; t++) {
            int i = tid + (t << 8);
            int row = i >> 3, unit = i & 7;
            char* dst = smem + (size_t)row * 144 + (unit << 4);
            int grow = bm + row;
            uint4 vh = make_uint4(0, 0, 0, 0), vl = vh;
            if (grow < N) {
                if (s < NF32) {
                    const float* src = (s == 0 ? Af0 : Af1)
                                     + (size_t)grow * 128 + ((kc & 1) << 6) + unit * 8;
                    float4 f0 = *(const float4*)src;
                    float4 f1 = *(const float4*)(src + 4);
                    vh.x = pack_h(f0.x, f0.y); vl.x = pack_l(f0.x, f0.y);
                    vh.y = pack_h(f0.z, f0.w); vl.y = pack_l(f0.z, f0.w);
                    vh.z = pack_h(f1.x, f1.y); vl.z = pack_l(f1.x, f1.y);
                    vh.w = pack_h(f1.z, f1.w); vl.w = pack_l(f1.z, f1.w);
                } else {
                    const int kb16 = kc - 2 * NF32;
                    const __nv_bfloat16* sa = Ah + (size_t)grow * 128 + (kb16 << 6);
                    const __nv_bfloat16* sl = Al + (size_t)grow * 128 + (kb16 << 6);
                    vh = ((const uint4*)sa)[unit];
                    vl = ((const uint4*)sl)[unit];
                }
            }
            *(uint4*)dst               = vh;
            *(uint4*)(dst + MAT_BYTES) = vl;
            *(uint4*)(dst + 2 * MAT_BYTES) = ((const uint4*)(Wh + (size_t)(bn + row) * K + k0))[unit];
            *(uint4*)(dst + 3 * MAT_BYTES) = ((const uint4*)(Wl + (size_t)(bn + row) * K + k0))[unit];
        }
        __syncthreads();

        #pragma unroll
        for (int k16 = 0; k16 < 4; k16++) {
            const uint32_t kb = k16 << 5;
            uint32_t ah[4][4], al[4][4];
            #pragma unroll
            for (int mi = 0; mi < 4; mi++) {
                ldx4(ah[mi], sb + aOff + mi * (16 * 144) + kb);
                ldx4(al[mi], sb + MAT_BYTES + aOff + mi * (16 * 144) + kb);
            }
            #pragma unroll
            for (int ni = 0; ni < 4; ni++) {
                uint32_t bh[2], bl[2];
                ldx2(bh, sb + 2 * MAT_BYTES + bOff + ni * (8 * 144) + kb);
                ldx2(bl, sb + 3 * MAT_BYTES + bOff + ni * (8 * 144) + kb);
                #pragma unroll
                for (int mi = 0; mi < 4; mi++) {
                    mma_bf16(acc[mi][ni], ah[mi], bh);
                    mma_bf16(acc[mi][ni], al[mi], bh);
                    mma_bf16(acc[mi][ni], ah[mi], bl);
                }
            }
        }
    }

    #pragma unroll
    for (int ni = 0; ni < 4; ni++) {
        int col  = wn * 32 + ni * 8 + ((lane & 3) << 1);   // 0..127 local
        float2 bv = *(const float2*)(bias + (PW ? col : (ccol + bn + col)));
        #pragma unroll
        for (int mi = 0; mi < 4; mi++) {
            int r0 = bm + wm * 64 + mi * 16 + (lane >> 2);
            #pragma unroll
            for (int half = 0; half < 2; half++) {
                int r = r0 + half * 8;
                if (r >= N) continue;
                float vx = acc[mi][ni][half * 2 + 0] + bv.x;
                float vy = acc[mi][ni][half * 2 + 1] + bv.y;
                if (!PW) {
                    *(float2*)(gates + (size_t)r * 384 + ccol + bn + col) = make_float2(vx, vy);
                } else {
                    const float* gp = gates + (size_t)r * 384 + col;
                    float2 Rv = *(const float2*)(gp);
                    float2 Zv = *(const float2*)(gp + 128);
                    float2 Iv = *(const float2*)(gp + 256);
                    float2 hv = *(const float2*)(hcur + (size_t)r * 128 + col);
                    float zx = sigm(Zv.x), zy = sigm(Zv.y);
                    float ox = (1.f - zx) * tanhf(Iv.x + sigm(Rv.x) * vx) + zx * hv.x;
                    float oy = (1.f - zy) * tanhf(Iv.y + sigm(Rv.y) * vy) + zy * hv.y;
                    *(float2*)(hout + (size_t)r * 128 + col) = make_float2(ox, oy);
                    *(uint32_t*)(hh + (size_t)r * 128 + col) = pack_h(ox, oy);
                    *(uint32_t*)(hl + (size_t)r * 128 + col) = pack_l(ox, oy);
                }
            }
        }
    }
}

// =================== CSR build kernels ===================
__global__ void detect_idx64(const unsigned int* __restrict__ a,
                             const unsigned int* __restrict__ b, int E)
{
    int n = E < 32 ? E : 32;
    int is64 = 1;
    for (int i = 0; i < n; i++) {
        if (a[2 * i + 1] != 0u) is64 = 0;
        if (b[2 * i + 1] != 0u) is64 = 0;
    }
    g_is64 = is64;
}

__global__ void convert_hist(const void* __restrict__ srcA, const void* __restrict__ srcB,
                             int* __restrict__ dstA, int* __restrict__ dstB,
                             int* __restrict__ cnt, int C, int L, int E)
{
    int e = blockIdx.x * blockDim.x + threadIdx.x;
    if (e >= E) return;
    int la, ca;
    if (g_is64) {
        la = (int)((const long long*)srcA)[e];
        ca = (int)((const long long*)srcB)[e];
    } else {
        la = ((const int*)srcA)[e];
        ca = ((const int*)srcB)[e];
    }
    dstA[e] = la; dstB[e] = ca;
    if ((unsigned)la < (unsigned)L && (unsigned)ca < (unsigned)C) {
        atomicAdd(&cnt[ca], 1);
        atomicAdd(&cnt[C + la], 1);
    }
}

__device__ __forceinline__ int block_scan_incl(int v, int* ws) {
    int lane = threadIdx.x & 31, w = threadIdx.x >> 5;
    int x = v;
    #pragma unroll
    for (int d = 1; d < 32; d <<= 1) {
        int y = __shfl_up_sync(0xffffffffu, x, d);
        if (lane >= d) x += y;
    }
    if (lane == 31) ws[w] = x;
    __syncthreads();
    if (w == 0) {
        int y = ws[lane];
        #pragma unroll
        for (int d = 1; d < 32; d <<= 1) {
            int z = __shfl_up_sync(0xffffffffu, y, d);
            if (lane >= d) y += z;
        }
        ws[lane] = y;
    }
    __syncthreads();
    return x + (w > 0 ? ws[w - 1] : 0);
}

__global__ void scanA(const int* __restrict__ cnt, int* __restrict__ off,
                      int* __restrict__ bsum, int T)
{
    __shared__ int ws[32];
    int i = blockIdx.x * 1024 + threadIdx.x;
    int v = (i < T) ? cnt[i] : 0;
    int incl = block_scan_incl(v, ws);
    if (i < T) off[i] = incl - v;
    if (threadIdx.x == 1023) bsum[blockIdx.x] = incl;
}

__global__ void scanB(int* __restrict__ bsum, int nb)
{
    __shared__ int ws[32];
    int v = (threadIdx.x < nb) ? bsum[threadIdx.x] : 0;
    int incl = block_scan_incl(v, ws);
    if (threadIdx.x < nb) bsum[threadIdx.x] = incl - v;
}

__global__ void scanC(int* __restrict__ off, int* __restrict__ cur,
                      const int* __restrict__ cnt, const int* __restrict__ bsum, int T)
{
    int i = blockIdx.x * 1024 + threadIdx.x;
    if (i >= T) return;
    int o = off[i] + bsum[i >> 10];
    off[i] = o;
    cur[i] = o;
    if (i == T - 1) off[T] = o + cnt[i];
}

__global__ void scatter_edges(const int* __restrict__ lei, const int* __restrict__ cei,
                              int* __restrict__ cur, const int* __restrict__ off,
                              int* __restrict__ permc, int* __restrict__ perml,
                              int C, int L, int E)
{
    int e = blockIdx.x * blockDim.x + threadIdx.x;
    if (e >= E) return;
    int la = lei[e], ca = cei[e];
    if ((unsigned)la >= (unsigned)L || (unsigned)ca >= (unsigned)C) return;
    int p1 = atomicAdd(&cur[ca], 1);
    permc[p1] = la;
    int baseL = off[C];
    int p2 = atomicAdd(&cur[C + la], 1);
    perml[p2 - baseL] = ca;
}

// segment sum via CSR: one warp per destination row, no atomics.
__global__ void seg_sum(const int* __restrict__ perm, const int* __restrict__ off,
                        const float* __restrict__ feat, float* __restrict__ out, int ndst)
{
    int w = (int)(((long long)blockIdx.x * blockDim.x + threadIdx.x) >> 5);
    int lane = threadIdx.x & 31;
    if (w >= ndst) return;
    int base = off[0];
    int s = off[w] - base, t = off[w + 1] - base;
    float4 acc = make_float4(0.f, 0.f, 0.f, 0.f);
    for (int i = s; i < t; i++) {
        int src = perm[i];
        float4 v = *(const float4*)(feat + (size_t)src * 128 + lane * 4);
        acc.x += v.x; acc.y += v.y; acc.z += v.z; acc.w += v.w;
    }
    *(float4*)(out + (size_t)w * 128 + lane * 4) = acc;
}

// =================== weight + embedding prep ===================
struct PrepArgs {
    const float4* mlp[6];
    const float* cWih; const float* cWhh;
    const float* lWih; const float* lWhh;
    const float* cbih; const float* cbhh;
    const float* lbih; const float* lbhh;
    const float4* lemb; const float4* cemb;
    int L32, C32;
};

__device__ __forceinline__ float wrz_c(const PrepArgs& a, int m, int k) {
    return (k < 128) ? a.cWih[m * 128 + k] : a.cWhh[m * 128 + (k - 128)];
}
__device__ __forceinline__ float wrz_l(const PrepArgs& a, int m, int k) {
    return (k < 256) ? a.lWih[m * 256 + k] : a.lWhh[m * 128 + (k - 256)];
}

#define PQ_MLP  24576
#define PQ_WRZC 16384
#define PQ_WINC 4096
#define PQ_WHNC 4096
#define PQ_WRZL 24576
#define PQ_WINL 8192
#define PQ_WHNL 4096
#define PREP_TOT (PQ_MLP + PQ_WRZC + PQ_WINC + PQ_WHNC + PQ_WRZL + PQ_WINL + PQ_WHNL + 1024)

__global__ void prep_all(PrepArgs a,
                         __nv_bfloat16* __restrict__ mwh, __nv_bfloat16* __restrict__ mwl,
                         __nv_bfloat16* __restrict__ gwh, __nv_bfloat16* __restrict__ gwl,
                         float* __restrict__ bcc, float* __restrict__ bcl,
                         __nv_bfloat16* __restrict__ lch, __nv_bfloat16* __restrict__ lcl,
                         __nv_bfloat16* __restrict__ cch, __nv_bfloat16* __restrict__ ccl)
{
    int i = blockIdx.x * blockDim.x + threadIdx.x;

    if (i >= PREP_TOT) {
        long long j = i - PREP_TOT;
        if (j < a.L32) {
            float4 v = a.lemb[j];
            *(uint2*)(lch + j * 4) = make_uint2(pack_h(v.x, v.y), pack_h(v.z, v.w));
            *(uint2*)(lcl + j * 4) = make_uint2(pack_l(v.x, v.y), pack_l(v.z, v.w));
        } else if (j < (long long)a.L32 + a.C32) {
            long long q = j - a.L32;
            float4 v = a.cemb[q];
            *(uint2*)(cch + q * 4) = make_uint2(pack_h(v.x, v.y), pack_h(v.z, v.w));
            *(uint2*)(ccl + q * 4) = make_uint2(pack_l(v.x, v.y), pack_l(v.z, v.w));
        }
        return;
    }

    float v0, v1, v2, v3;
    __nv_bfloat16 *oh, *ol;
    long long obase;

    if (i < PQ_MLP) {
        int midx = i >> 12;
        float4 v = a.mlp[midx][i & 4095];
        v0 = v.x; v1 = v.y; v2 = v.z; v3 = v.w;
        oh = mwh; ol = mwl; obase = (long long)i * 4;
    } else if (i < PQ_MLP + PQ_WRZC) {
        int base = (i - PQ_MLP) * 4, m = base >> 8, k = base & 255;
        v0 = wrz_c(a, m, k);     v1 = wrz_c(a, m, k + 1);
        v2 = wrz_c(a, m, k + 2); v3 = wrz_c(a, m, k + 3);
        oh = gwh; ol = gwl; obase = OFF_WRZC + base;
    } else if (i < PQ_MLP + PQ_WRZC + PQ_WINC) {
        int base = (i - PQ_MLP - PQ_WRZC) * 4, m = base >> 7, k = base & 127;
        const float* s = a.cWih + (256 + m) * 128 + k;
        v0 = s[0]; v1 = s[1]; v2 = s[2]; v3 = s[3];
        oh = gwh; ol = gwl; obase = OFF_WINC + base;
    } else if (i < PQ_MLP + PQ_WRZC + PQ_WINC + PQ_WHNC) {
        int base = (i - PQ_MLP - PQ_WRZC - PQ_WINC) * 4, m = base >> 7, k = base & 127;
        const float* s = a.cWhh + (256 + m) * 128 + k;
        v0 = s[0]; v1 = s[1]; v2 = s[2]; v3 = s[3];
        oh = gwh; ol = gwl; obase = OFF_WHNC + base;
    } else if (i < PQ_MLP + PQ_WRZC + PQ_WINC + PQ_WHNC + PQ_WRZL) {
        int base = (i - PQ_MLP - PQ_WRZC - PQ_WINC - PQ_WHNC) * 4;
        int m = base / 384, k = base % 384;
        v0 = wrz_l(a, m, k);     v1 = wrz_l(a, m, k + 1);
        v2 = wrz_l(a, m, k + 2); v3 = wrz_l(a, m, k + 3);
        oh = gwh; ol = gwl; obase = OFF_WRZL + base;
    } else if (i < PQ_MLP + PQ_WRZC + PQ_WINC + PQ_WHNC + PQ_WRZL + PQ_WINL) {
        int base = (i - PQ_MLP - PQ_WRZC - PQ_WINC - PQ_WHNC - PQ_WRZL) * 4;
        int m = base >> 8, k = base & 255;
        const float* s = a.lWih + (256 + m) * 256 + k;
        v0 = s[0]; v1 = s[1]; v2 = s[2]; v3 = s[3];
        oh = gwh; ol = gwl; obase = OFF_WINL + base;
    } else if (i < PREP_TOT - 1024) {
        int base = (i - (PREP_TOT - 1024 - PQ_WHNL)) * 4, m = base >> 7, k = base & 127;
        const float* s = a.lWhh + (256 + m) * 128 + k;
        v0 = s[0]; v1 = s[1]; v2 = s[2]; v3 = s[3];
        oh = gwh; ol = gwl; obase = OFF_WHNL + base;
    } else {
        int j = i - (PREP_TOT - 1024);
        if (j < 512) {
            bcc[j] = (j < 256) ? a.cbih[j] + a.cbhh[j]
                   : (j < 384) ? a.cbih[j] : a.cbhh[j - 128];
        } else {
            int m = j - 512;
            bcl[m] = (m < 256) ? a.lbih[m] + a.lbhh[m]
                   : (m < 384) ? a.lbih[m] : a.lbhh[m - 128];
        }
        return;
    }
    *(uint2*)(oh + obase) = make_uint2(pack_h(v0, v1), pack_h(v2, v3));
    *(uint2*)(ol + obase) = make_uint2(pack_l(v0, v1), pack_l(v2, v3));
}

// =================== host side ===================
extern "C" void kernel_launch(void* const* d_in, const int* in_sizes, int n_in,
                              void* d_out, int out_size)
{
    int base = (n_in >= 26) ? 2 : 0;

    const void*  l_ei_raw = d_in[base + 0];
    const void*  c_ei_raw = d_in[base + 1];
    const float* l_emb0   = (const float*)d_in[base + 2];
    const float* c_emb0   = (const float*)d_in[base + 3];

    const float* l2c_W1 = (const float*)d_in[base + 4];
    const float* l2c_b1 = (const float*)d_in[base + 5];
    const float* l2c_W2 = (const float*)d_in[base + 6];
    const float* l2c_b2 = (const float*)d_in[base + 7];
    const float* c2l_W1 = (const float*)d_in[base + 8];
    const float* c2l_b1 = (const float*)d_in[base + 9];
    const float* c2l_W2 = (const float*)d_in[base + 10];
    const float* c2l_b2 = (const float*)d_in[base + 11];
    const float* l2l_W1 = (const float*)d_in[base + 12];
    const float* l2l_b1 = (const float*)d_in[base + 13];
    const float* l2l_W2 = (const float*)d_in[base + 14];
    const float* l2l_b2 = (const float*)d_in[base + 15];
    const float* cgru_Wih = (const float*)d_in[base + 16];
    const float* cgru_Whh = (const float*)d_in[base + 17];
    const float* cgru_bih = (const float*)d_in[base + 18];
    const float* cgru_bhh = (const float*)d_in[base + 19];
    const float* lgru_Wih = (const float*)d_in[base + 20];
    const float* lgru_Whh = (const float*)d_in[base + 21];
    const float* lgru_bih = (const float*)d_in[base + 22];
    const float* lgru_bhh = (const float*)d_in[base + 23];

    const int E = in_sizes[base + 0];
    const int L = in_sizes[base + 2] / DIM;
    const int C = in_sizes[base + 3] / DIM;
    const int T = C + L;

    float* out   = (float*)d_out;
    float* l_out = out;
    float* c_out = out + (size_t)(NITER + 1) * L * DIM;

    float *lfeat, *cfeat, *caggr, *lx0, *l2lm, *gates, *bcc, *bcl;
    int *lei, *cei, *cnt, *off, *cur, *bsum, *permc, *perml;
    __nv_bfloat16 *lch, *lcl, *cch, *ccl, *mwh, *mwl, *gwh, *gwl;
    cudaGetSymbolAddress((void**)&lfeat, g_lfeat);
    cudaGetSymbolAddress((void**)&cfeat, g_cfeat);
    cudaGetSymbolAddress((void**)&caggr, g_caggr);
    cudaGetSymbolAddress((void**)&lx0,   g_lx0);
    cudaGetSymbolAddress((void**)&l2lm,  g_l2lm);
    cudaGetSymbolAddress((void**)&gates, g_gates);
    cudaGetSymbolAddress((void**)&lei,   g_lei32);
    cudaGetSymbolAddress((void**)&cei,   g_cei32);
    cudaGetSymbolAddress((void**)&cnt,   g_cnt);
    cudaGetSymbolAddress((void**)&off,   g_off);
    cudaGetSymbolAddress((void**)&cur,   g_cur);
    cudaGetSymbolAddress((void**)&bsum,  g_bsum);
    cudaGetSymbolAddress((void**)&permc, g_permc);
    cudaGetSymbolAddress((void**)&perml, g_perml);
    cudaGetSymbolAddress((void**)&lch,   g_lcur_h);
    cudaGetSymbolAddress((void**)&lcl,   g_lcur_l);
    cudaGetSymbolAddress((void**)&cch,   g_ccur_h);
    cudaGetSymbolAddress((void**)&ccl,   g_ccur_l);
    cudaGetSymbolAddress((void**)&mwh,   g_mw_h);
    cudaGetSymbolAddress((void**)&mwl,   g_mw_l);
    cudaGetSymbolAddress((void**)&gwh,   g_gw_h);
    cudaGetSymbolAddress((void**)&gwl,   g_gw_l);
    cudaGetSymbolAddress((void**)&bcc,   g_bcat_c);
    cudaGetSymbolAddress((void**)&bcl,   g_bcat_l);

    cudaFuncSetAttribute((const void*)fused_mlp<0>, cudaFuncAttributeMaxDynamicSharedMemorySize, SMEM_MLP);
    cudaFuncSetAttribute((const void*)fused_mlp<1>, cudaFuncAttributeMaxDynamicSharedMemorySize, SMEM_MLP);
    cudaFuncSetAttribute((const void*)gates_gemm<0, 0>, cudaFuncAttributeMaxDynamicSharedMemorySize, SMEM_GATES);
    cudaFuncSetAttribute((const void*)gates_gemm<1, 0>, cudaFuncAttributeMaxDynamicSharedMemorySize, SMEM_GATES);
    cudaFuncSetAttribute((const void*)gates_gemm<2, 0>, cudaFuncAttributeMaxDynamicSharedMemorySize, SMEM_GATES);
    cudaFuncSetAttribute((const void*)gates_gemm<0, 1>, cudaFuncAttributeMaxDynamicSharedMemorySize, SMEM_GATES);

    // ---- prelude: CSR build + weight prep ----
    const int nb = (T + 1023) / 1024;
    cudaMemsetAsync(cnt, 0, (size_t)T * sizeof(int), 0);
    detect_idx64<<<1, 1>>>((const unsigned int*)l_ei_raw, (const unsigned int*)c_ei_raw, E);
    convert_hist<<<(E + 255) / 256, 256>>>(l_ei_raw, c_ei_raw, lei, cei, cnt, C, L, E);
    scanA<<<nb, 1024>>>(cnt, off, bsum, T);
    scanB<<<1, 1024>>>(bsum, nb);
    scanC<<<nb, 1024>>>(off, cur, cnt, bsum, T);
    scatter_edges<<<(E + 255) / 256, 256>>>(lei, cei, cur, off, permc, perml, C, L, E);

    PrepArgs pa;
    pa.mlp[0] = (const float4*)l2c_W1; pa.mlp[1] = (const float4*)l2c_W2;
    pa.mlp[2] = (const float4*)c2l_W1; pa.mlp[3] = (const float4*)c2l_W2;
    pa.mlp[4] = (const float4*)l2l_W1; pa.mlp[5] = (const float4*)l2l_W2;
    pa.cWih = cgru_Wih; pa.cWhh = cgru_Whh;
    pa.lWih = lgru_Wih; pa.lWhh = lgru_Whh;
    pa.cbih = cgru_bih; pa.cbhh = cgru_bhh;
    pa.lbih = lgru_bih; pa.lbhh = lgru_bhh;
    pa.lemb = (const float4*)l_emb0; pa.cemb = (const float4*)c_emb0;
    pa.L32 = L * 32; pa.C32 = C * 32;
    const int prepN = PREP_TOT + pa.L32 + pa.C32;
    prep_all<<<(prepN + 255) / 256, 256>>>(pa, mwh, mwl, gwh, gwl, bcc, bcl, lch, lcl, cch, ccl);

    cudaMemcpyAsync(l_out, l_emb0, (size_t)L * DIM * sizeof(float), cudaMemcpyDeviceToDevice, 0);
    cudaMemcpyAsync(c_out, c_emb0, (size_t)C * DIM * sizeof(float), cudaMemcpyDeviceToDevice, 0);

    __nv_bfloat16 *W_[6], *Wl_[6];
    for (int i = 0; i < 6; i++) { W_[i] = mwh + (size_t)i * 16384; Wl_[i] = mwl + (size_t)i * 16384; }

    const float* nfp = nullptr;
    const __nv_bfloat16* nbp = nullptr;
    float* nfw = nullptr;
    __nv_bfloat16* nbw = nullptr;

    for (int it = 0; it < NITER; it++) {
        const float* lcur = l_out + (size_t)it * L * DIM;
        const float* ccur = c_out + (size_t)it * C * DIM;
        float* lnext = l_out + (size_t)(it + 1) * L * DIM;
        float* cnext = c_out + (size_t)(it + 1) * C * DIM;

        dim3 gl((L + 127) / 128), gc((C + 127) / 128);
        dim3 gl2((L + 127) / 128, 2), gc2((C + 127) / 128, 2);

        // --- 3 fused MLPs ---
        fused_mlp<0><<<gl, 256, SMEM_MLP>>>(lch, lcl, W_[0], Wl_[0], l2c_b1, W_[1], Wl_[1], l2c_b2, lfeat, L);
        fused_mlp<0><<<gc, 256, SMEM_MLP>>>(cch, ccl, W_[2], Wl_[2], c2l_b1, W_[3], Wl_[3], c2l_b2, cfeat, C);
        fused_mlp<1><<<gl, 256, SMEM_MLP>>>(lch, lcl, W_[4], Wl_[4], l2l_b1, W_[5], Wl_[5], l2l_b2, l2lm, L);

        // --- CSR segment sums (no atomics, no memsets) ---
        seg_sum<<<(int)(((long long)C * 32 + 255) / 256), 256>>>(permc, off,     lfeat, caggr, C);
        seg_sum<<<(int)(((long long)L * 32 + 255) / 256), 256>>>(perml, off + C, cfeat, lx0,   L);

        // --- clause GRU ---
        gates_gemm<1, 0><<<gc2, 256, SMEM_GATES>>>(caggr, nfp, cch, ccl,
            gwh + OFF_WRZC, gwl + OFF_WRZC, bcc, gates, 0,   C, 256, nfp, nfw, nbw, nbw);
        gates_gemm<1, 0><<<gc,  256, SMEM_GATES>>>(caggr, nfp, nbp, nbp,
            gwh + OFF_WINC, gwl + OFF_WINC, bcc, gates, 256, C, 128, nfp, nfw, nbw, nbw);
        gates_gemm<0, 1><<<gc,  256, SMEM_GATES>>>(nfp, nfp, cch, ccl,
            gwh + OFF_WHNC, gwl + OFF_WHNC, bcc + 384, gates, 0, C, 128, ccur, cnext, cch, ccl);

        // --- literal GRU ---
        gates_gemm<2, 0><<<gl2, 256, SMEM_GATES>>>(lx0, l2lm, lch, lcl,
            gwh + OFF_WRZL, gwl + OFF_WRZL, bcl, gates, 0,   L, 384, nfp, nfw, nbw, nbw);
        gates_gemm<2, 0><<<gl,  256, SMEM_GATES>>>(lx0, l2lm, nbp, nbp,
            gwh + OFF_WINL, gwl + OFF_WINL, bcl, gates, 256, L, 256, nfp, nfw, nbw, nbw);
        gates_gemm<0, 1><<<gl,  256, SMEM_GATES>>>(nfp, nfp, lch, lcl,
            gwh + OFF_WHNL, gwl + OFF_WHNL, bcl + 384, gates, 0, L, 128, lcur, lnext, lch, lcl);
    }
}

// round 10
// speedup vs baseline: 1.7697x; 1.5897x over previous
#include <cuda_runtime.h>
#include <cuda_fp16.h>
#include <math.h>
#include <stdint.h>

#define DIM 128
#define NITER 8

#define MAXL 100096ull
#define MAXC 150016ull
#define MAXN 150016ull
#define MAXE 450048

// ---------------- fp32 scratch ----------------
__device__ float g_lfeat[MAXL * 128];
__device__ float g_cfeat[MAXC * 128];
__device__ float g_caggr[MAXC * 128];
__device__ float g_lx0  [MAXL * 128];
__device__ float g_l2lm [MAXL * 128];
__device__ float g_gates[MAXN * 384];   // [rz_sum(256) | i_n(128)]
__device__ int   g_lei32[MAXE];
__device__ int   g_cei32[MAXE];

// ---------------- CSR scratch ----------------
#define MAXT (MAXC + MAXL + 2)
__device__ int g_cnt [MAXT];
__device__ int g_off [MAXT];
__device__ int g_cur [MAXT];
__device__ int g_permc[MAXE];
__device__ int g_perml[MAXE];

// ---------------- fp16 scratch ----------------
__device__ __half g_l16[MAXL * 128];
__device__ __half g_c16[MAXC * 128];
__device__ __half g_mw16[98304];       // 6 MLP weights 128x128
__device__ __half g_gw16[245760];      // GRU gate weights (dense blocks)
__device__ float  g_bcat_c[512], g_bcat_l[512];

#define OFF_WRZC 0
#define OFF_WINC 65536
#define OFF_WHNC 81920
#define OFF_WRZL 98304
#define OFF_WINL 196608
#define OFF_WHNL 229376

// =================== helpers ===================
__device__ __forceinline__ uint32_t smem_to_u32(const void* p) {
    uint32_t a;
    asm("{ .reg .u64 t; cvta.to.shared.u64 t, %1; cvt.u32.u64 %0, t; }"
        : "=r"(a) : "l"(p));
    return a;
}
__device__ __forceinline__ void ldx4(uint32_t* r, uint32_t addr) {
    asm volatile("ldmatrix.sync.aligned.m8n8.x4.shared.b16 {%0,%1,%2,%3}, [%4];"
                 : "=r"(r[0]), "=r"(r[1]), "=r"(r[2]), "=r"(r[3]) : "r"(addr));
}
__device__ __forceinline__ void ldx2(uint32_t* r, uint32_t addr) {
    asm volatile("ldmatrix.sync.aligned.m8n8.x2.shared.b16 {%0,%1}, [%2];"
                 : "=r"(r[0]), "=r"(r[1]) : "r"(addr));
}
__device__ __forceinline__ void mma_f16(float* d, const uint32_t* a, const uint32_t* b) {
    asm volatile("mma.sync.aligned.m16n8k16.row.col.f32.f16.f16.f32 "
                 "{%0,%1,%2,%3}, {%4,%5,%6,%7}, {%8,%9}, {%0,%1,%2,%3};"
                 : "+f"(d[0]), "+f"(d[1]), "+f"(d[2]), "+f"(d[3])
                 : "r"(a[0]), "r"(a[1]), "r"(a[2]), "r"(a[3]), "r"(b[0]), "r"(b[1]));
}
__device__ __forceinline__ uint32_t packh2(float x, float y) {
    __half2 p = __floats2half2_rn(x, y);
    return *(uint32_t*)&p;
}
__device__ __forceinline__ float sigm(float x) { return 1.f / (1.f + expf(-x)); }

#define MAT_BYTES 18432
#define SMEM_GATES 36864        // 2 regions: A, W
#define SMEM_MLP   73728        // 4 regions: A, W, hid0, hid1

// =================== fused 2-layer MLP (fp16, single MMA) ===================
// out[N,128] = relu(x@W1^T + b1) @ W2^T + b2
template<int XORROW>
__global__ __launch_bounds__(256, 2)
void fused_mlp(const __half* __restrict__ A16,
               const __half* __restrict__ W1, const float* __restrict__ b1,
               const __half* __restrict__ W2, const float* __restrict__ b2,
               float* __restrict__ out, int N)
{
    extern __shared__ char smem[];
    const uint32_t sb = smem_to_u32(smem);
    const int tid  = threadIdx.x;
    const int lane = tid & 31;
    const int wid  = tid >> 5;
    const int wm   = wid >> 2;
    const int wn   = wid & 3;
    const int bm   = blockIdx.x * 128;

    const uint32_t aOff = (uint32_t)(wm * 64 + (lane & 15)) * 144 + ((lane >> 4) << 4);
    const uint32_t bOff = (uint32_t)(wn * 32 + (lane & 7)) * 144 + (((lane >> 3) & 1) << 4);

    float acc[4][4][4] = {};

    // ---- stage 1 ----
    #pragma unroll
    for (int kc = 0; kc < 2; kc++) {
        if (kc) __syncthreads();
        const int k0 = kc << 6;
        #pragma unroll
        for (int t = 0; t < 2; t++) {
            int i = tid + (t << 8);               // 0..511
            int row = i >> 2, unit = i & 3;       // wrong split; need 1024 units
            (void)row; (void)unit;
        }
        // loader: 1024 16B units per matrix, 2 matrices (A, W) -> each thread 4+4? No:
        // 1024 units / 256 threads = 4 units; do A and W in same pass (t<4).
        #pragma unroll
        for (int t = 0; t < 4; t++) {
            int i = tid + (t << 8);               // 0..1023
            int row = i >> 3, unit = i & 7;
            char* dst = smem + (size_t)row * 144 + (unit << 4);
            int grow = bm + row;
            uint4 va = make_uint4(0, 0, 0, 0);
            if (grow < N) {
                int sr = XORROW ? (grow ^ 1) : grow;
                va = ((const uint4*)(A16 + (size_t)sr * 128 + k0))[unit];
            }
            *(uint4*)dst = va;
            *(uint4*)(dst + MAT_BYTES) = ((const uint4*)(W1 + (size_t)row * 128 + k0))[unit];
        }
        __syncthreads();
        #pragma unroll
        for (int k16 = 0; k16 < 4; k16++) {
            const uint32_t kb = k16 << 5;
            uint32_t af[4][4];
            #pragma unroll
            for (int mi = 0; mi < 4; mi++)
                ldx4(af[mi], sb + aOff + mi * (16 * 144) + kb);
            #pragma unroll
            for (int ni = 0; ni < 4; ni++) {
                uint32_t bf[2];
                ldx2(bf, sb + MAT_BYTES + bOff + ni * (8 * 144) + kb);
                #pragma unroll
                for (int mi = 0; mi < 4; mi++)
                    mma_f16(acc[mi][ni], af[mi], bf);
            }
        }
    }
    __syncthreads();

    // ---- epilogue 1: relu + fp16 -> hid regions R2/R3 ----
    #pragma unroll
    for (int ni = 0; ni < 4; ni++) {
        int c = wn * 32 + ni * 8 + ((lane & 3) << 1);
        float2 bv = *(const float2*)(b1 + c);
        uint32_t roff = (uint32_t)(2 + (c >> 6)) * MAT_BYTES + (uint32_t)(c & 63) * 2;
        #pragma unroll
        for (int mi = 0; mi < 4; mi++) {
            int rl0 = wm * 64 + mi * 16 + (lane >> 2);
            float vx0 = fmaxf(acc[mi][ni][0] + bv.x, 0.f);
            float vy0 = fmaxf(acc[mi][ni][1] + bv.y, 0.f);
            float vx1 = fmaxf(acc[mi][ni][2] + bv.x, 0.f);
            float vy1 = fmaxf(acc[mi][ni][3] + bv.y, 0.f);
            *(uint32_t*)(smem + roff + (uint32_t)rl0 * 144)       = packh2(vx0, vy0);
            *(uint32_t*)(smem + roff + (uint32_t)(rl0 + 8) * 144) = packh2(vx1, vy1);
            acc[mi][ni][0] = acc[mi][ni][1] = acc[mi][ni][2] = acc[mi][ni][3] = 0.f;
        }
    }
    __syncthreads();

    // ---- stage 2 ----
    #pragma unroll
    for (int kc = 0; kc < 2; kc++) {
        if (kc) __syncthreads();
        const int k0 = kc << 6;
        #pragma unroll
        for (int t = 0; t < 4; t++) {
            int i = tid + (t << 8);
            int row = i >> 3, unit = i & 7;
            char* dst = smem + (size_t)row * 144 + (unit << 4);
            *(uint4*)(dst + MAT_BYTES) = ((const uint4*)(W2 + (size_t)row * 128 + k0))[unit];
        }
        __syncthreads();
        const uint32_t ahBase = sb + (uint32_t)(2 + kc) * MAT_BYTES + aOff;
        #pragma unroll
        for (int k16 = 0; k16 < 4; k16++) {
            const uint32_t kb = k16 << 5;
            uint32_t af[4][4];
            #pragma unroll
            for (int mi = 0; mi < 4; mi++)
                ldx4(af[mi], ahBase + mi * (16 * 144) + kb);
            #pragma unroll
            for (int ni = 0; ni < 4; ni++) {
                uint32_t bf[2];
                ldx2(bf, sb + MAT_BYTES + bOff + ni * (8 * 144) + kb);
                #pragma unroll
                for (int mi = 0; mi < 4; mi++)
                    mma_f16(acc[mi][ni], af[mi], bf);
            }
        }
    }

    #pragma unroll
    for (int ni = 0; ni < 4; ni++) {
        int c = wn * 32 + ni * 8 + ((lane & 3) << 1);
        float2 bv = *(const float2*)(b2 + c);
        #pragma unroll
        for (int mi = 0; mi < 4; mi++) {
            int r0 = bm + wm * 64 + mi * 16 + (lane >> 2);
            if (r0 < N)
                *(float2*)(out + (size_t)r0 * 128 + c) =
                    make_float2(acc[mi][ni][0] + bv.x, acc[mi][ni][1] + bv.y);
            if (r0 + 8 < N)
                *(float2*)(out + (size_t)(r0 + 8) * 128 + c) =
                    make_float2(acc[mi][ni][2] + bv.x, acc[mi][ni][3] + bv.y);
        }
    }
}

// =================== merged rz + i_n gates GEMM ===================
// grid (ceilN/128, 3): y=0,1 -> rz block (M=256, K=Krz, W=Wrz);
//                      y=2   -> i_n block (M=128, K=Kin, W=Win).
// A = NF32 fp32 sources (128 cols each, converted) then fp16 source.
template<int NF32>
__global__ __launch_bounds__(256, 2)
void gates_rz_in(const float* __restrict__ Af0, const float* __restrict__ Af1,
                 const __half* __restrict__ A16,
                 const __half* __restrict__ Wrz, const __half* __restrict__ Win,
                 const float* __restrict__ bias,
                 float* __restrict__ gates, int N, int Krz, int Kin)
{
    extern __shared__ char smem[];
    const uint32_t sb = smem_to_u32(smem);
    const int tid  = threadIdx.x;
    const int lane = tid & 31;
    const int wid  = tid >> 5;
    const int wm   = wid >> 2;
    const int wn   = wid & 3;
    const int bm   = blockIdx.x * 128;
    const int bn   = blockIdx.y * 128;
    const int isIn = (blockIdx.y == 2);
    const __half* W = isIn ? Win : Wrz;
    const int K = isIn ? Kin : Krz;
    const int wrow = isIn ? 0 : bn;
    const int nchunk = K >> 6;

    float acc[4][4][4] = {};
    const uint32_t aOff = (uint32_t)(wm * 64 + (lane & 15)) * 144 + ((lane >> 4) << 4);
    const uint32_t bOff = (uint32_t)(wn * 32 + (lane & 7)) * 144 + (((lane >> 3) & 1) << 4);

    for (int kc = 0; kc < nchunk; kc++) {
        if (kc) __syncthreads();
        const int k0 = kc << 6;
        const int s  = kc >> 1;
        #pragma unroll
        for (int t = 0; t < 4; t++) {
            int i = tid + (t << 8);
            int row = i >> 3, unit = i & 7;
            char* dst = smem + (size_t)row * 144 + (unit << 4);
            int grow = bm + row;
            uint4 va = make_uint4(0, 0, 0, 0);
            if (grow < N) {
                if (s < NF32) {
                    const float* src = (s == 0 ? Af0 : Af1)
                                     + (size_t)grow * 128 + ((kc & 1) << 6);
                    float4 f0 = ((const float4*)src)[unit * 2];
                    float4 f1 = ((const float4*)src)[unit * 2 + 1];
                    va.x = packh2(f0.x, f0.y);
                    va.y = packh2(f0.z, f0.w);
                    va.z = packh2(f1.x, f1.y);
                    va.w = packh2(f1.z, f1.w);
                } else {
                    const int kb16 = kc - 2 * NF32;
                    va = ((const uint4*)(A16 + (size_t)grow * 128 + (kb16 << 6)))[unit];
                }
            }
            *(uint4*)dst = va;
            *(uint4*)(dst + MAT_BYTES) = ((const uint4*)(W + (size_t)(wrow + row) * K + k0))[unit];
        }
        __syncthreads();

        #pragma unroll
        for (int k16 = 0; k16 < 4; k16++) {
            const uint32_t kb = k16 << 5;
            uint32_t af[4][4];
            #pragma unroll
            for (int mi = 0; mi < 4; mi++)
                ldx4(af[mi], sb + aOff + mi * (16 * 144) + kb);
            #pragma unroll
            for (int ni = 0; ni < 4; ni++) {
                uint32_t bf[2];
                ldx2(bf, sb + MAT_BYTES + bOff + ni * (8 * 144) + kb);
                #pragma unroll
                for (int mi = 0; mi < 4; mi++)
                    mma_f16(acc[mi][ni], af[mi], bf);
            }
        }
    }

    #pragma unroll
    for (int ni = 0; ni < 4; ni++) {
        int gcol = bn + wn * 32 + ni * 8 + ((lane & 3) << 1);
        float2 bv = *(const float2*)(bias + gcol);
        #pragma unroll
        for (int mi = 0; mi < 4; mi++) {
            int r0 = bm + wm * 64 + mi * 16 + (lane >> 2);
            if (r0 < N)
                *(float2*)(gates + (size_t)r0 * 384 + gcol) =
                    make_float2(acc[mi][ni][0] + bv.x, acc[mi][ni][1] + bv.y);
            if (r0 + 8 < N)
                *(float2*)(gates + (size_t)(r0 + 8) * 384 + gcol) =
                    make_float2(acc[mi][ni][2] + bv.x, acc[mi][ni][3] + bv.y);
        }
    }
}

// =================== h_n GEMM + fused GRU pointwise ===================
// Hn = h16 @ Whn^T + bias; h' = (1-sig(Z))*tanh(I + sig(R)*Hn) + sig(Z)*h.
__global__ __launch_bounds__(256, 2)
void gru_hn_pw(const __half* __restrict__ A16,
               const __half* __restrict__ Whn, const float* __restrict__ bias,
               const float* __restrict__ gates,
               const float* __restrict__ hcur, float* __restrict__ hout,
               __half* __restrict__ h16out, int N)
{
    extern __shared__ char smem[];
    const uint32_t sb = smem_to_u32(smem);
    const int tid  = threadIdx.x;
    const int lane = tid & 31;
    const int wid  = tid >> 5;
    const int wm   = wid >> 2;
    const int wn   = wid & 3;
    const int bm   = blockIdx.x * 128;

    float acc[4][4][4] = {};
    const uint32_t aOff = (uint32_t)(wm * 64 + (lane & 15)) * 144 + ((lane >> 4) << 4);
    const uint32_t bOff = (uint32_t)(wn * 32 + (lane & 7)) * 144 + (((lane >> 3) & 1) << 4);

    #pragma unroll
    for (int kc = 0; kc < 2; kc++) {
        if (kc) __syncthreads();
        const int k0 = kc << 6;
        #pragma unroll
        for (int t = 0; t < 4; t++) {
            int i = tid + (t << 8);
            int row = i >> 3, unit = i & 7;
            char* dst = smem + (size_t)row * 144 + (unit << 4);
            int grow = bm + row;
            uint4 va = make_uint4(0, 0, 0, 0);
            if (grow < N)
                va = ((const uint4*)(A16 + (size_t)grow * 128 + k0))[unit];
            *(uint4*)dst = va;
            *(uint4*)(dst + MAT_BYTES) = ((const uint4*)(Whn + (size_t)row * 128 + k0))[unit];
        }
        __syncthreads();
        #pragma unroll
        for (int k16 = 0; k16 < 4; k16++) {
            const uint32_t kb = k16 << 5;
            uint32_t af[4][4];
            #pragma unroll
            for (int mi = 0; mi < 4; mi++)
                ldx4(af[mi], sb + aOff + mi * (16 * 144) + kb);
            #pragma unroll
            for (int ni = 0; ni < 4; ni++) {
                uint32_t bf[2];
                ldx2(bf, sb + MAT_BYTES + bOff + ni * (8 * 144) + kb);
                #pragma unroll
                for (int mi = 0; mi < 4; mi++)
                    mma_f16(acc[mi][ni], af[mi], bf);
            }
        }
    }

    #pragma unroll
    for (int ni = 0; ni < 4; ni++) {
        int col = wn * 32 + ni * 8 + ((lane & 3) << 1);
        float2 bv = *(const float2*)(bias + col);
        #pragma unroll
        for (int mi = 0; mi < 4; mi++) {
            int r0 = bm + wm * 64 + mi * 16 + (lane >> 2);
            #pragma unroll
            for (int half = 0; half < 2; half++) {
                int r = r0 + half * 8;
                if (r >= N) continue;
                float vx = acc[mi][ni][half * 2 + 0] + bv.x;
                float vy = acc[mi][ni][half * 2 + 1] + bv.y;
                const float* gp = gates + (size_t)r * 384 + col;
                float2 Rv = *(const float2*)(gp);
                float2 Zv = *(const float2*)(gp + 128);
                float2 Iv = *(const float2*)(gp + 256);
                float2 hv = *(const float2*)(hcur + (size_t)r * 128 + col);
                float zx = sigm(Zv.x), zy = sigm(Zv.y);
                float ox = (1.f - zx) * tanhf(Iv.x + sigm(Rv.x) * vx) + zx * hv.x;
                float oy = (1.f - zy) * tanhf(Iv.y + sigm(Rv.y) * vy) + zy * hv.y;
                *(float2*)(hout + (size_t)r * 128 + col) = make_float2(ox, oy);
                *(uint32_t*)(h16out + (size_t)r * 128 + col) = packh2(ox, oy);
            }
        }
    }
}

// =================== CSR build ===================
__global__ void convert_hist(const void* __restrict__ srcA, const void* __restrict__ srcB,
                             int* __restrict__ dstA, int* __restrict__ dstB,
                             int* __restrict__ cnt, int C, int L, int E)
{
    __shared__ int s_is64;
    if (threadIdx.x == 0) {
        const unsigned* ua = (const unsigned*)srcA;
        const unsigned* ub = (const unsigned*)srcB;
        int n = E < 32 ? E : 32;
        int is64 = 1;
        for (int i = 0; i < n; i++)
            if (ua[2 * i + 1] | ub[2 * i + 1]) { is64 = 0; break; }
        s_is64 = is64;
    }
    __syncthreads();
    int e = blockIdx.x * blockDim.x + threadIdx.x;
    if (e >= E) return;
    int la, ca;
    if (s_is64) {
        la = (int)((const long long*)srcA)[e];
        ca = (int)((const long long*)srcB)[e];
    } else {
        la = ((const int*)srcA)[e];
        ca = ((const int*)srcB)[e];
    }
    dstA[e] = la; dstB[e] = ca;
    if ((unsigned)la < (unsigned)L && (unsigned)ca < (unsigned)C) {
        atomicAdd(&cnt[ca], 1);
        atomicAdd(&cnt[C + la], 1);
    }
}

// single-block scan over T counts -> off (exclusive), cur, off[T]
__global__ void scan_all(const int* __restrict__ cnt, int* __restrict__ off,
                         int* __restrict__ cur, int T)
{
    __shared__ int ws[32];
    int chunk = (T + 1023) >> 10;
    int s = threadIdx.x * chunk;
    int e = min(T, s + chunk);
    int sum = 0;
    for (int i = s; i < e; i++) sum += cnt[i];

    // inclusive block scan over thread sums
    int lane = threadIdx.x & 31, w = threadIdx.x >> 5;
    int x = sum;
    #pragma unroll
    for (int d = 1; d < 32; d <<= 1) {
        int y = __shfl_up_sync(0xffffffffu, x, d);
        if (lane >= d) x += y;
    }
    if (lane == 31) ws[w] = x;
    __syncthreads();
    if (w == 0) {
        int y = (lane < 32) ? ws[lane] : 0;
        #pragma unroll
        for (int d = 1; d < 32; d <<= 1) {
            int z = __shfl_up_sync(0xffffffffu, y, d);
            if (lane >= d) y += z;
        }
        ws[lane] = y;
    }
    __syncthreads();
    int excl = x - sum + (w > 0 ? ws[w - 1] : 0);

    int run = excl;
    for (int i = s; i < e; i++) {
        off[i] = run; cur[i] = run;
        run += cnt[i];
    }
    if (s < T && e == T) off[T] = run;
}

__global__ void scatter_edges(const int* __restrict__ lei, const int* __restrict__ cei,
                              int* __restrict__ cur, const int* __restrict__ off,
                              int* __restrict__ permc, int* __restrict__ perml,
                              int C, int L, int E)
{
    int e = blockIdx.x * blockDim.x + threadIdx.x;
    if (e >= E) return;
    int la = lei[e], ca = cei[e];
    if ((unsigned)la >= (unsigned)L || (unsigned)ca >= (unsigned)C) return;
    int p1 = atomicAdd(&cur[ca], 1);
    permc[p1] = la;
    int baseL = off[C];
    int p2 = atomicAdd(&cur[C + la], 1);
    perml[p2 - baseL] = ca;
}

// segment sum via CSR: one warp per destination row.
__global__ void seg_sum(const int* __restrict__ perm, const int* __restrict__ off,
                        const float* __restrict__ feat, float* __restrict__ out, int ndst)
{
    int w = (int)(((long long)blockIdx.x * blockDim.x + threadIdx.x) >> 5);
    int lane = threadIdx.x & 31;
    if (w >= ndst) return;
    int base = off[0];
    int s = off[w] - base, t = off[w + 1] - base;
    float4 acc = make_float4(0.f, 0.f, 0.f, 0.f);
    for (int i = s; i < t; i++) {
        int src = perm[i];
        float4 v = *(const float4*)(feat + (size_t)src * 128 + lane * 4);
        acc.x += v.x; acc.y += v.y; acc.z += v.z; acc.w += v.w;
    }
    *(float4*)(out + (size_t)w * 128 + lane * 4) = acc;
}

// =================== weight + embedding prep ===================
struct PrepArgs {
    const float4* mlp[6];
    const float* cWih; const float* cWhh;
    const float* lWih; const float* lWhh;
    const float* cbih; const float* cbhh;
    const float* lbih; const float* lbhh;
    const float4* lemb; const float4* cemb;
    float* lout0; float* cout0;
    int L32, C32;
};

__device__ __forceinline__ float wrz_c(const PrepArgs& a, int m, int k) {
    return (k < 128) ? a.cWih[m * 128 + k] : a.cWhh[m * 128 + (k - 128)];
}
__device__ __forceinline__ float wrz_l(const PrepArgs& a, int m, int k) {
    return (k < 256) ? a.lWih[m * 256 + k] : a.lWhh[m * 128 + (k - 256)];
}

#define PQ_MLP  24576
#define PQ_WRZC 16384
#define PQ_WINC 4096
#define PQ_WHNC 4096
#define PQ_WRZL 24576
#define PQ_WINL 8192
#define PQ_WHNL 4096
#define PREP_W  (PQ_MLP + PQ_WRZC + PQ_WINC + PQ_WHNC + PQ_WRZL + PQ_WINL + PQ_WHNL)
#define PREP_TOT (PREP_W + 1024)

__global__ void prep_all(PrepArgs a,
                         __half* __restrict__ mw, __half* __restrict__ gw,
                         float* __restrict__ bcc, float* __restrict__ bcl,
                         __half* __restrict__ l16, __half* __restrict__ c16)
{
    int i = blockIdx.x * blockDim.x + threadIdx.x;

    if (i >= PREP_TOT) {
        long long j = i - PREP_TOT;
        if (j < a.L32) {
            float4 v = a.lemb[j];
            *(uint2*)(l16 + j * 4) = make_uint2(packh2(v.x, v.y), packh2(v.z, v.w));
            ((float4*)a.lout0)[j] = v;
        } else if (j < (long long)a.L32 + a.C32) {
            long long q = j - a.L32;
            float4 v = a.cemb[q];
            *(uint2*)(c16 + q * 4) = make_uint2(packh2(v.x, v.y), packh2(v.z, v.w));
            ((float4*)a.cout0)[q] = v;
        }
        return;
    }

    float v0, v1, v2, v3;
    __half* o;
    long long obase;

    if (i < PQ_MLP) {
        int midx = i >> 12;
        float4 v = a.mlp[midx][i & 4095];
        v0 = v.x; v1 = v.y; v2 = v.z; v3 = v.w;
        o = mw; obase = (long long)i * 4;
    } else if (i < PQ_MLP + PQ_WRZC) {
        int base = (i - PQ_MLP) * 4, m = base >> 8, k = base & 255;
        v0 = wrz_c(a, m, k);     v1 = wrz_c(a, m, k + 1);
        v2 = wrz_c(a, m, k + 2); v3 = wrz_c(a, m, k + 3);
        o = gw; obase = OFF_WRZC + base;
    } else if (i < PQ_MLP + PQ_WRZC + PQ_WINC) {
        int base = (i - PQ_MLP - PQ_WRZC) * 4, m = base >> 7, k = base & 127;
        const float* s = a.cWih + (256 + m) * 128 + k;
        v0 = s[0]; v1 = s[1]; v2 = s[2]; v3 = s[3];
        o = gw; obase = OFF_WINC + base;
    } else if (i < PQ_MLP + PQ_WRZC + PQ_WINC + PQ_WHNC) {
        int base = (i - PQ_MLP - PQ_WRZC - PQ_WINC) * 4, m = base >> 7, k = base & 127;
        const float* s = a.cWhh + (256 + m) * 128 + k;
        v0 = s[0]; v1 = s[1]; v2 = s[2]; v3 = s[3];
        o = gw; obase = OFF_WHNC + base;
    } else if (i < PQ_MLP + PQ_WRZC + PQ_WINC + PQ_WHNC + PQ_WRZL) {
        int base = (i - PQ_MLP - PQ_WRZC - PQ_WINC - PQ_WHNC) * 4;
        int m = base / 384, k = base % 384;
        v0 = wrz_l(a, m, k);     v1 = wrz_l(a, m, k + 1);
        v2 = wrz_l(a, m, k + 2); v3 = wrz_l(a, m, k + 3);
        o = gw; obase = OFF_WRZL + base;
    } else if (i < PQ_MLP + PQ_WRZC + PQ_WINC + PQ_WHNC + PQ_WRZL + PQ_WINL) {
        int base = (i - PQ_MLP - PQ_WRZC - PQ_WINC - PQ_WHNC - PQ_WRZL) * 4;
        int m = base >> 8, k = base & 255;
        const float* s = a.lWih + (256 + m) * 256 + k;
        v0 = s[0]; v1 = s[1]; v2 = s[2]; v3 = s[3];
        o = gw; obase = OFF_WINL + base;
    } else if (i < PREP_W) {
        int base = (i - (PREP_W - PQ_WHNL)) * 4, m = base >> 7, k = base & 127;
        const float* s = a.lWhh + (256 + m) * 128 + k;
        v0 = s[0]; v1 = s[1]; v2 = s[2]; v3 = s[3];
        o = gw; obase = OFF_WHNL + base;
    } else {
        int j = i - PREP_W;
        if (j < 512) {
            bcc[j] = (j < 256) ? a.cbih[j] + a.cbhh[j]
                   : (j < 384) ? a.cbih[j] : a.cbhh[j - 128];
        } else {
            int m = j - 512;
            bcl[m] = (m < 256) ? a.lbih[m] + a.lbhh[m]
                   : (m < 384) ? a.lbih[m] : a.lbhh[m - 128];
        }
        return;
    }
    *(uint2*)(o + obase) = make_uint2(packh2(v0, v1), packh2(v2, v3));
}

// =================== host side ===================
extern "C" void kernel_launch(void* const* d_in, const int* in_sizes, int n_in,
                              void* d_out, int out_size)
{
    int base = (n_in >= 26) ? 2 : 0;

    const void*  l_ei_raw = d_in[base + 0];
    const void*  c_ei_raw = d_in[base + 1];
    const float* l_emb0   = (const float*)d_in[base + 2];
    const float* c_emb0   = (const float*)d_in[base + 3];

    const float* l2c_W1 = (const float*)d_in[base + 4];
    const float* l2c_b1 = (const float*)d_in[base + 5];
    const float* l2c_W2 = (const float*)d_in[base + 6];
    const float* l2c_b2 = (const float*)d_in[base + 7];
    const float* c2l_W1 = (const float*)d_in[base + 8];
    const float* c2l_b1 = (const float*)d_in[base + 9];
    const float* c2l_W2 = (const float*)d_in[base + 10];
    const float* c2l_b2 = (const float*)d_in[base + 11];
    const float* l2l_W1 = (const float*)d_in[base + 12];
    const float* l2l_b1 = (const float*)d_in[base + 13];
    const float* l2l_W2 = (const float*)d_in[base + 14];
    const float* l2l_b2 = (const float*)d_in[base + 15];
    const float* cgru_Wih = (const float*)d_in[base + 16];
    const float* cgru_Whh = (const float*)d_in[base + 17];
    const float* cgru_bih = (const float*)d_in[base + 18];
    const float* cgru_bhh = (const float*)d_in[base + 19];
    const float* lgru_Wih = (const float*)d_in[base + 20];
    const float* lgru_Whh = (const float*)d_in[base + 21];
    const float* lgru_bih = (const float*)d_in[base + 22];
    const float* lgru_bhh = (const float*)d_in[base + 23];

    const int E = in_sizes[base + 0];
    const int L = in_sizes[base + 2] / DIM;
    const int C = in_sizes[base + 3] / DIM;
    const int T = C + L;

    float* out   = (float*)d_out;
    float* l_out = out;
    float* c_out = out + (size_t)(NITER + 1) * L * DIM;

    float *lfeat, *cfeat, *caggr, *lx0, *l2lm, *gates, *bcc, *bcl;
    int *lei, *cei, *cnt, *off, *cur, *permc, *perml;
    __half *l16, *c16, *mw, *gw;
    cudaGetSymbolAddress((void**)&lfeat, g_lfeat);
    cudaGetSymbolAddress((void**)&cfeat, g_cfeat);
    cudaGetSymbolAddress((void**)&caggr, g_caggr);
    cudaGetSymbolAddress((void**)&lx0,   g_lx0);
    cudaGetSymbolAddress((void**)&l2lm,  g_l2lm);
    cudaGetSymbolAddress((void**)&gates, g_gates);
    cudaGetSymbolAddress((void**)&lei,   g_lei32);
    cudaGetSymbolAddress((void**)&cei,   g_cei32);
    cudaGetSymbolAddress((void**)&cnt,   g_cnt);
    cudaGetSymbolAddress((void**)&off,   g_off);
    cudaGetSymbolAddress((void**)&cur,   g_cur);
    cudaGetSymbolAddress((void**)&permc, g_permc);
    cudaGetSymbolAddress((void**)&perml, g_perml);
    cudaGetSymbolAddress((void**)&l16,   g_l16);
    cudaGetSymbolAddress((void**)&c16,   g_c16);
    cudaGetSymbolAddress((void**)&mw,    g_mw16);
    cudaGetSymbolAddress((void**)&gw,    g_gw16);
    cudaGetSymbolAddress((void**)&bcc,   g_bcat_c);
    cudaGetSymbolAddress((void**)&bcl,   g_bcat_l);

    cudaFuncSetAttribute((const void*)fused_mlp<0>, cudaFuncAttributeMaxDynamicSharedMemorySize, SMEM_MLP);
    cudaFuncSetAttribute((const void*)fused_mlp<1>, cudaFuncAttributeMaxDynamicSharedMemorySize, SMEM_MLP);
    cudaFuncSetAttribute((const void*)gates_rz_in<1>, cudaFuncAttributeMaxDynamicSharedMemorySize, SMEM_GATES);
    cudaFuncSetAttribute((const void*)gates_rz_in<2>, cudaFuncAttributeMaxDynamicSharedMemorySize, SMEM_GATES);
    cudaFuncSetAttribute((const void*)gru_hn_pw, cudaFuncAttributeMaxDynamicSharedMemorySize, SMEM_GATES);

    // ---- prelude (5 kernels + 1 memset) ----
    cudaMemsetAsync(cnt, 0, (size_t)T * sizeof(int), 0);
    convert_hist<<<(E + 255) / 256, 256>>>(l_ei_raw, c_ei_raw, lei, cei, cnt, C, L, E);
    scan_all<<<1, 1024>>>(cnt, off, cur, T);
    scatter_edges<<<(E + 255) / 256, 256>>>(lei, cei, cur, off, permc, perml, C, L, E);

    PrepArgs pa;
    pa.mlp[0] = (const float4*)l2c_W1; pa.mlp[1] = (const float4*)l2c_W2;
    pa.mlp[2] = (const float4*)c2l_W1; pa.mlp[3] = (const float4*)c2l_W2;
    pa.mlp[4] = (const float4*)l2l_W1; pa.mlp[5] = (const float4*)l2l_W2;
    pa.cWih = cgru_Wih; pa.cWhh = cgru_Whh;
    pa.lWih = lgru_Wih; pa.lWhh = lgru_Whh;
    pa.cbih = cgru_bih; pa.cbhh = cgru_bhh;
    pa.lbih = lgru_bih; pa.lbhh = lgru_bhh;
    pa.lemb = (const float4*)l_emb0; pa.cemb = (const float4*)c_emb0;
    pa.lout0 = l_out; pa.cout0 = c_out;
    pa.L32 = L * 32; pa.C32 = C * 32;
    const int prepN = PREP_TOT + pa.L32 + pa.C32;
    prep_all<<<(prepN + 255) / 256, 256>>>(pa, mw, gw, bcc, bcl, l16, c16);

    __half *W_[6];
    for (int i = 0; i < 6; i++) W_[i] = mw + (size_t)i * 16384;
    const float* nfp = nullptr;

    for (int it = 0; it < NITER; it++) {
        const float* lcur = l_out + (size_t)it * L * DIM;
        const float* ccur = c_out + (size_t)it * C * DIM;
        float* lnext = l_out + (size_t)(it + 1) * L * DIM;
        float* cnext = c_out + (size_t)(it + 1) * C * DIM;

        dim3 gl((L + 127) / 128), gc((C + 127) / 128);
        dim3 gl3((L + 127) / 128, 3), gc3((C + 127) / 128, 3);

        // --- 3 fused MLPs ---
        fused_mlp<0><<<gl, 256, SMEM_MLP>>>(l16, W_[0], l2c_b1, W_[1], l2c_b2, lfeat, L);
        fused_mlp<0><<<gc, 256, SMEM_MLP>>>(c16, W_[2], c2l_b1, W_[3], c2l_b2, cfeat, C);
        fused_mlp<1><<<gl, 256, SMEM_MLP>>>(l16, W_[4], l2l_b1, W_[5], l2l_b2, l2lm, L);

        // --- CSR segment sums ---
        seg_sum<<<(int)(((long long)C * 32 + 255) / 256), 256>>>(permc, off,     lfeat, caggr, C);
        seg_sum<<<(int)(((long long)L * 32 + 255) / 256), 256>>>(perml, off + C, cfeat, lx0,   L);

        // --- clause GRU: merged rz+i_n, then h_n + pointwise ---
        gates_rz_in<1><<<gc3, 256, SMEM_GATES>>>(caggr, nfp, c16,
            gw + OFF_WRZC, gw + OFF_WINC, bcc, gates, C, 256, 128);
        gru_hn_pw<<<gc, 256, SMEM_GATES>>>(c16, gw + OFF_WHNC, bcc + 384,
            gates, ccur, cnext, c16, C);

        // --- literal GRU ---
        gates_rz_in<2><<<gl3, 256, SMEM_GATES>>>(lx0, l2lm, l16,
            gw + OFF_WRZL, gw + OFF_WINL, bcl, gates, L, 384, 256);
        gru_hn_pw<<<gl, 256, SMEM_GATES>>>(l16, gw + OFF_WHNL, bcl + 384,
            gates, lcur, lnext, l16, L);
    }
}

// round 11
// speedup vs baseline: 1.8943x; 1.0704x over previous
#include <cuda_runtime.h>
#include <cuda_fp16.h>
#include <math.h>
#include <stdint.h>

#define DIM 128
#define NITER 8

#define MAXL 100096ull
#define MAXC 150016ull
#define MAXN 150016ull
#define MAXE 450048

// ---------------- fp16 intermediates ----------------
__device__ __half g_lfeat[MAXL * 128];
__device__ __half g_cfeat[MAXC * 128];
__device__ __half g_caggr[MAXC * 128];
__device__ __half g_lx0  [MAXL * 128];
__device__ __half g_l2lm [MAXL * 128];
__device__ __half g_gates[MAXN * 384];  // [rz_sum(256) | i_n(128)] fp16
__device__ int   g_lei32[MAXE];
__device__ int   g_cei32[MAXE];

// ---------------- CSR scratch ----------------
#define MAXT (MAXC + MAXL + 2)
__device__ int g_cnt [MAXT];
__device__ int g_off [MAXT];
__device__ int g_cur [MAXT];
__device__ int g_permc[MAXE];
__device__ int g_perml[MAXE];

// ---------------- fp16 state + weights ----------------
__device__ __half g_l16[MAXL * 128];
__device__ __half g_c16[MAXC * 128];
__device__ __half g_mw16[98304];
__device__ __half g_gw16[245760];
__device__ float  g_bcat_c[512], g_bcat_l[512];

#define OFF_WRZC 0
#define OFF_WINC 65536
#define OFF_WHNC 81920
#define OFF_WRZL 98304
#define OFF_WINL 196608
#define OFF_WHNL 229376

// =================== helpers ===================
__device__ __forceinline__ uint32_t smem_to_u32(const void* p) {
    uint32_t a;
    asm("{ .reg .u64 t; cvta.to.shared.u64 t, %1; cvt.u32.u64 %0, t; }"
        : "=r"(a) : "l"(p));
    return a;
}
__device__ __forceinline__ void ldx4(uint32_t* r, uint32_t addr) {
    asm volatile("ldmatrix.sync.aligned.m8n8.x4.shared.b16 {%0,%1,%2,%3}, [%4];"
                 : "=r"(r[0]), "=r"(r[1]), "=r"(r[2]), "=r"(r[3]) : "r"(addr));
}
__device__ __forceinline__ void ldx2(uint32_t* r, uint32_t addr) {
    asm volatile("ldmatrix.sync.aligned.m8n8.x2.shared.b16 {%0,%1}, [%2];"
                 : "=r"(r[0]), "=r"(r[1]) : "r"(addr));
}
__device__ __forceinline__ void mma_f16(float* d, const uint32_t* a, const uint32_t* b) {
    asm volatile("mma.sync.aligned.m16n8k16.row.col.f32.f16.f16.f32 "
                 "{%0,%1,%2,%3}, {%4,%5,%6,%7}, {%8,%9}, {%0,%1,%2,%3};"
                 : "+f"(d[0]), "+f"(d[1]), "+f"(d[2]), "+f"(d[3])
                 : "r"(a[0]), "r"(a[1]), "r"(a[2]), "r"(a[3]), "r"(b[0]), "r"(b[1]));
}
__device__ __forceinline__ uint32_t packh2(float x, float y) {
    __half2 p = __floats2half2_rn(x, y);
    return *(uint32_t*)&p;
}
__device__ __forceinline__ float sigm(float x) { return 1.f / (1.f + expf(-x)); }

#define MAT_BYTES 18432
#define SMEM_GATES 36864
#define SMEM_MLP   73728

struct ASrc { const __half* p[3]; };

// =================== fused 2-layer MLP (fp16 in/out) ===================
template<int XORROW>
__global__ __launch_bounds__(256, 2)
void fused_mlp(const __half* __restrict__ A16,
               const __half* __restrict__ W1, const float* __restrict__ b1,
               const __half* __restrict__ W2, const float* __restrict__ b2,
               __half* __restrict__ out, int N)
{
    extern __shared__ char smem[];
    const uint32_t sb = smem_to_u32(smem);
    const int tid  = threadIdx.x;
    const int lane = tid & 31;
    const int wid  = tid >> 5;
    const int wm   = wid >> 2;
    const int wn   = wid & 3;
    const int bm   = blockIdx.x * 128;

    const uint32_t aOff = (uint32_t)(wm * 64 + (lane & 15)) * 144 + ((lane >> 4) << 4);
    const uint32_t bOff = (uint32_t)(wn * 32 + (lane & 7)) * 144 + (((lane >> 3) & 1) << 4);

    float acc[4][4][4] = {};

    // ---- stage 1 ----
    #pragma unroll
    for (int kc = 0; kc < 2; kc++) {
        if (kc) __syncthreads();
        const int k0 = kc << 6;
        #pragma unroll
        for (int t = 0; t < 4; t++) {
            int i = tid + (t << 8);
            int row = i >> 3, unit = i & 7;
            char* dst = smem + (size_t)row * 144 + (unit << 4);
            int grow = bm + row;
            uint4 va = make_uint4(0, 0, 0, 0);
            if (grow < N) {
                int sr = XORROW ? (grow ^ 1) : grow;
                va = ((const uint4*)(A16 + (size_t)sr * 128 + k0))[unit];
            }
            *(uint4*)dst = va;
            *(uint4*)(dst + MAT_BYTES) = ((const uint4*)(W1 + (size_t)row * 128 + k0))[unit];
        }
        __syncthreads();
        #pragma unroll
        for (int k16 = 0; k16 < 4; k16++) {
            const uint32_t kb = k16 << 5;
            uint32_t af[4][4];
            #pragma unroll
            for (int mi = 0; mi < 4; mi++)
                ldx4(af[mi], sb + aOff + mi * (16 * 144) + kb);
            #pragma unroll
            for (int ni = 0; ni < 4; ni++) {
                uint32_t bf[2];
                ldx2(bf, sb + MAT_BYTES + bOff + ni * (8 * 144) + kb);
                #pragma unroll
                for (int mi = 0; mi < 4; mi++)
                    mma_f16(acc[mi][ni], af[mi], bf);
            }
        }
    }
    __syncthreads();

    // ---- epilogue 1: relu + fp16 -> hid regions R2/R3 ----
    #pragma unroll
    for (int ni = 0; ni < 4; ni++) {
        int c = wn * 32 + ni * 8 + ((lane & 3) << 1);
        float2 bv = *(const float2*)(b1 + c);
        uint32_t roff = (uint32_t)(2 + (c >> 6)) * MAT_BYTES + (uint32_t)(c & 63) * 2;
        #pragma unroll
        for (int mi = 0; mi < 4; mi++) {
            int rl0 = wm * 64 + mi * 16 + (lane >> 2);
            float vx0 = fmaxf(acc[mi][ni][0] + bv.x, 0.f);
            float vy0 = fmaxf(acc[mi][ni][1] + bv.y, 0.f);
            float vx1 = fmaxf(acc[mi][ni][2] + bv.x, 0.f);
            float vy1 = fmaxf(acc[mi][ni][3] + bv.y, 0.f);
            *(uint32_t*)(smem + roff + (uint32_t)rl0 * 144)       = packh2(vx0, vy0);
            *(uint32_t*)(smem + roff + (uint32_t)(rl0 + 8) * 144) = packh2(vx1, vy1);
            acc[mi][ni][0] = acc[mi][ni][1] = acc[mi][ni][2] = acc[mi][ni][3] = 0.f;
        }
    }
    __syncthreads();

    // ---- stage 2 ----
    #pragma unroll
    for (int kc = 0; kc < 2; kc++) {
        if (kc) __syncthreads();
        const int k0 = kc << 6;
        #pragma unroll
        for (int t = 0; t < 4; t++) {
            int i = tid + (t << 8);
            int row = i >> 3, unit = i & 7;
            char* dst = smem + (size_t)row * 144 + (unit << 4);
            *(uint4*)(dst + MAT_BYTES) = ((const uint4*)(W2 + (size_t)row * 128 + k0))[unit];
        }
        __syncthreads();
        const uint32_t ahBase = sb + (uint32_t)(2 + kc) * MAT_BYTES + aOff;
        #pragma unroll
        for (int k16 = 0; k16 < 4; k16++) {
            const uint32_t kb = k16 << 5;
            uint32_t af[4][4];
            #pragma unroll
            for (int mi = 0; mi < 4; mi++)
                ldx4(af[mi], ahBase + mi * (16 * 144) + kb);
            #pragma unroll
            for (int ni = 0; ni < 4; ni++) {
                uint32_t bf[2];
                ldx2(bf, sb + MAT_BYTES + bOff + ni * (8 * 144) + kb);
                #pragma unroll
                for (int mi = 0; mi < 4; mi++)
                    mma_f16(acc[mi][ni], af[mi], bf);
            }
        }
    }

    #pragma unroll
    for (int ni = 0; ni < 4; ni++) {
        int c = wn * 32 + ni * 8 + ((lane & 3) << 1);
        float2 bv = *(const float2*)(b2 + c);
        #pragma unroll
        for (int mi = 0; mi < 4; mi++) {
            int r0 = bm + wm * 64 + mi * 16 + (lane >> 2);
            if (r0 < N)
                *(uint32_t*)(out + (size_t)r0 * 128 + c) =
                    packh2(acc[mi][ni][0] + bv.x, acc[mi][ni][1] + bv.y);
            if (r0 + 8 < N)
                *(uint32_t*)(out + (size_t)(r0 + 8) * 128 + c) =
                    packh2(acc[mi][ni][2] + bv.x, acc[mi][ni][3] + bv.y);
        }
    }
}

// =================== merged rz + i_n gates GEMM (all-fp16 A) ===================
// grid (ceilN/128, 3): y=0,1 -> rz (M=256, K=Krz); y=2 -> i_n (M=128, K=Kin).
// A sources: up to 3 fp16 arrays of 128 cols; source = kc>>1.
__global__ __launch_bounds__(256, 2)
void gates_rz_in(ASrc A,
                 const __half* __restrict__ Wrz, const __half* __restrict__ Win,
                 const float* __restrict__ bias,
                 __half* __restrict__ gates, int N, int Krz, int Kin)
{
    extern __shared__ char smem[];
    const uint32_t sb = smem_to_u32(smem);
    const int tid  = threadIdx.x;
    const int lane = tid & 31;
    const int wid  = tid >> 5;
    const int wm   = wid >> 2;
    const int wn   = wid & 3;
    const int bm   = blockIdx.x * 128;
    const int bn   = blockIdx.y * 128;
    const int isIn = (blockIdx.y == 2);
    const __half* W = isIn ? Win : Wrz;
    const int K = isIn ? Kin : Krz;
    const int wrow = isIn ? 0 : bn;
    const int nchunk = K >> 6;

    float acc[4][4][4] = {};
    const uint32_t aOff = (uint32_t)(wm * 64 + (lane & 15)) * 144 + ((lane >> 4) << 4);
    const uint32_t bOff = (uint32_t)(wn * 32 + (lane & 7)) * 144 + (((lane >> 3) & 1) << 4);

    for (int kc = 0; kc < nchunk; kc++) {
        if (kc) __syncthreads();
        const int k0 = kc << 6;
        const __half* srcBase = A.p[kc >> 1];
        const int colOfs = (kc & 1) << 6;
        #pragma unroll
        for (int t = 0; t < 4; t++) {
            int i = tid + (t << 8);
            int row = i >> 3, unit = i & 7;
            char* dst = smem + (size_t)row * 144 + (unit << 4);
            int grow = bm + row;
            uint4 va = make_uint4(0, 0, 0, 0);
            if (grow < N)
                va = ((const uint4*)(srcBase + (size_t)grow * 128 + colOfs))[unit];
            *(uint4*)dst = va;
            *(uint4*)(dst + MAT_BYTES) = ((const uint4*)(W + (size_t)(wrow + row) * K + k0))[unit];
        }
        __syncthreads();

        #pragma unroll
        for (int k16 = 0; k16 < 4; k16++) {
            const uint32_t kb = k16 << 5;
            uint32_t af[4][4];
            #pragma unroll
            for (int mi = 0; mi < 4; mi++)
                ldx4(af[mi], sb + aOff + mi * (16 * 144) + kb);
            #pragma unroll
            for (int ni = 0; ni < 4; ni++) {
                uint32_t bf[2];
                ldx2(bf, sb + MAT_BYTES + bOff + ni * (8 * 144) + kb);
                #pragma unroll
                for (int mi = 0; mi < 4; mi++)
                    mma_f16(acc[mi][ni], af[mi], bf);
            }
        }
    }

    #pragma unroll
    for (int ni = 0; ni < 4; ni++) {
        int gcol = bn + wn * 32 + ni * 8 + ((lane & 3) << 1);
        float2 bv = *(const float2*)(bias + gcol);
        #pragma unroll
        for (int mi = 0; mi < 4; mi++) {
            int r0 = bm + wm * 64 + mi * 16 + (lane >> 2);
            if (r0 < N)
                *(uint32_t*)(gates + (size_t)r0 * 384 + gcol) =
                    packh2(acc[mi][ni][0] + bv.x, acc[mi][ni][1] + bv.y);
            if (r0 + 8 < N)
                *(uint32_t*)(gates + (size_t)(r0 + 8) * 384 + gcol) =
                    packh2(acc[mi][ni][2] + bv.x, acc[mi][ni][3] + bv.y);
        }
    }
}

// =================== h_n GEMM + fused GRU pointwise ===================
__global__ __launch_bounds__(256, 2)
void gru_hn_pw(const __half* __restrict__ A16,
               const __half* __restrict__ Whn, const float* __restrict__ bias,
               const __half* __restrict__ gates,
               const float* __restrict__ hcur, float* __restrict__ hout,
               __half* __restrict__ h16out, int N)
{
    extern __shared__ char smem[];
    const uint32_t sb = smem_to_u32(smem);
    const int tid  = threadIdx.x;
    const int lane = tid & 31;
    const int wid  = tid >> 5;
    const int wm   = wid >> 2;
    const int wn   = wid & 3;
    const int bm   = blockIdx.x * 128;

    float acc[4][4][4] = {};
    const uint32_t aOff = (uint32_t)(wm * 64 + (lane & 15)) * 144 + ((lane >> 4) << 4);
    const uint32_t bOff = (uint32_t)(wn * 32 + (lane & 7)) * 144 + (((lane >> 3) & 1) << 4);

    #pragma unroll
    for (int kc = 0; kc < 2; kc++) {
        if (kc) __syncthreads();
        const int k0 = kc << 6;
        #pragma unroll
        for (int t = 0; t < 4; t++) {
            int i = tid + (t << 8);
            int row = i >> 3, unit = i & 7;
            char* dst = smem + (size_t)row * 144 + (unit << 4);
            int grow = bm + row;
            uint4 va = make_uint4(0, 0, 0, 0);
            if (grow < N)
                va = ((const uint4*)(A16 + (size_t)grow * 128 + k0))[unit];
            *(uint4*)dst = va;
            *(uint4*)(dst + MAT_BYTES) = ((const uint4*)(Whn + (size_t)row * 128 + k0))[unit];
        }
        __syncthreads();
        #pragma unroll
        for (int k16 = 0; k16 < 4; k16++) {
            const uint32_t kb = k16 << 5;
            uint32_t af[4][4];
            #pragma unroll
            for (int mi = 0; mi < 4; mi++)
                ldx4(af[mi], sb + aOff + mi * (16 * 144) + kb);
            #pragma unroll
            for (int ni = 0; ni < 4; ni++) {
                uint32_t bf[2];
                ldx2(bf, sb + MAT_BYTES + bOff + ni * (8 * 144) + kb);
                #pragma unroll
                for (int mi = 0; mi < 4; mi++)
                    mma_f16(acc[mi][ni], af[mi], bf);
            }
        }
    }

    #pragma unroll
    for (int ni = 0; ni < 4; ni++) {
        int col = wn * 32 + ni * 8 + ((lane & 3) << 1);
        float2 bv = *(const float2*)(bias + col);
        #pragma unroll
        for (int mi = 0; mi < 4; mi++) {
            int r0 = bm + wm * 64 + mi * 16 + (lane >> 2);
            #pragma unroll
            for (int half = 0; half < 2; half++) {
                int r = r0 + half * 8;
                if (r >= N) continue;
                float vx = acc[mi][ni][half * 2 + 0] + bv.x;
                float vy = acc[mi][ni][half * 2 + 1] + bv.y;
                const __half* gp = gates + (size_t)r * 384 + col;
                float2 Rv = __half22float2(*(const __half2*)(gp));
                float2 Zv = __half22float2(*(const __half2*)(gp + 128));
                float2 Iv = __half22float2(*(const __half2*)(gp + 256));
                float2 hv = *(const float2*)(hcur + (size_t)r * 128 + col);
                float zx = sigm(Zv.x), zy = sigm(Zv.y);
                float ox = (1.f - zx) * tanhf(Iv.x + sigm(Rv.x) * vx) + zx * hv.x;
                float oy = (1.f - zy) * tanhf(Iv.y + sigm(Rv.y) * vy) + zy * hv.y;
                *(float2*)(hout + (size_t)r * 128 + col) = make_float2(ox, oy);
                *(uint32_t*)(h16out + (size_t)r * 128 + col) = packh2(ox, oy);
            }
        }
    }
}

// =================== CSR build ===================
__global__ void convert_hist(const void* __restrict__ srcA, const void* __restrict__ srcB,
                             int* __restrict__ dstA, int* __restrict__ dstB,
                             int* __restrict__ cnt, int C, int L, int E)
{
    __shared__ int s_is64;
    if (threadIdx.x == 0) {
        const unsigned* ua = (const unsigned*)srcA;
        const unsigned* ub = (const unsigned*)srcB;
        int n = E < 32 ? E : 32;
        int is64 = 1;
        for (int i = 0; i < n; i++)
            if (ua[2 * i + 1] | ub[2 * i + 1]) { is64 = 0; break; }
        s_is64 = is64;
    }
    __syncthreads();
    int e = blockIdx.x * blockDim.x + threadIdx.x;
    if (e >= E) return;
    int la, ca;
    if (s_is64) {
        la = (int)((const long long*)srcA)[e];
        ca = (int)((const long long*)srcB)[e];
    } else {
        la = ((const int*)srcA)[e];
        ca = ((const int*)srcB)[e];
    }
    dstA[e] = la; dstB[e] = ca;
    if ((unsigned)la < (unsigned)L && (unsigned)ca < (unsigned)C) {
        atomicAdd(&cnt[ca], 1);
        atomicAdd(&cnt[C + la], 1);
    }
}

__global__ void scan_all(const int* __restrict__ cnt, int* __restrict__ off,
                         int* __restrict__ cur, int T)
{
    __shared__ int ws[32];
    int chunk = (T + 1023) >> 10;
    int s = threadIdx.x * chunk;
    int e = min(T, s + chunk);
    int sum = 0;
    for (int i = s; i < e; i++) sum += cnt[i];

    int lane = threadIdx.x & 31, w = threadIdx.x >> 5;
    int x = sum;
    #pragma unroll
    for (int d = 1; d < 32; d <<= 1) {
        int y = __shfl_up_sync(0xffffffffu, x, d);
        if (lane >= d) x += y;
    }
    if (lane == 31) ws[w] = x;
    __syncthreads();
    if (w == 0) {
        int y = ws[lane];
        #pragma unroll
        for (int d = 1; d < 32; d <<= 1) {
            int z = __shfl_up_sync(0xffffffffu, y, d);
            if (lane >= d) y += z;
        }
        ws[lane] = y;
    }
    __syncthreads();
    int excl = x - sum + (w > 0 ? ws[w - 1] : 0);

    int run = excl;
    for (int i = s; i < e; i++) {
        off[i] = run; cur[i] = run;
        run += cnt[i];
    }
    if (s < T && e == T) off[T] = run;
}

__global__ void scatter_edges(const int* __restrict__ lei, const int* __restrict__ cei,
                              int* __restrict__ cur, const int* __restrict__ off,
                              int* __restrict__ permc, int* __restrict__ perml,
                              int C, int L, int E)
{
    int e = blockIdx.x * blockDim.x + threadIdx.x;
    if (e >= E) return;
    int la = lei[e], ca = cei[e];
    if ((unsigned)la >= (unsigned)L || (unsigned)ca >= (unsigned)C) return;
    int p1 = atomicAdd(&cur[ca], 1);
    permc[p1] = la;
    int baseL = off[C];
    int p2 = atomicAdd(&cur[C + la], 1);
    perml[p2 - baseL] = ca;
}

// segment sum via CSR (fp16 in/out, fp32 accumulate): one warp per dest row.
__global__ void seg_sum(const int* __restrict__ perm, const int* __restrict__ off,
                        const __half* __restrict__ feat, __half* __restrict__ out, int ndst)
{
    int w = (int)(((long long)blockIdx.x * blockDim.x + threadIdx.x) >> 5);
    int lane = threadIdx.x & 31;
    if (w >= ndst) return;
    int base = off[0];
    int s = off[w] - base, t = off[w + 1] - base;
    float4 acc = make_float4(0.f, 0.f, 0.f, 0.f);
    for (int i = s; i < t; i++) {
        int src = perm[i];
        uint2 v = *(const uint2*)(feat + (size_t)src * 128 + lane * 4);
        float2 f0 = __half22float2(*(__half2*)&v.x);
        float2 f1 = __half22float2(*(__half2*)&v.y);
        acc.x += f0.x; acc.y += f0.y; acc.z += f1.x; acc.w += f1.y;
    }
    uint2 o;
    o.x = packh2(acc.x, acc.y);
    o.y = packh2(acc.z, acc.w);
    *(uint2*)(out + (size_t)w * 128 + lane * 4) = o;
}

// =================== weight + embedding prep ===================
struct PrepArgs {
    const float4* mlp[6];
    const float* cWih; const float* cWhh;
    const float* lWih; const float* lWhh;
    const float* cbih; const float* cbhh;
    const float* lbih; const float* lbhh;
    const float4* lemb; const float4* cemb;
    float* lout0; float* cout0;
    int L32, C32;
};

__device__ __forceinline__ float wrz_c(const PrepArgs& a, int m, int k) {
    return (k < 128) ? a.cWih[m * 128 + k] : a.cWhh[m * 128 + (k - 128)];
}
__device__ __forceinline__ float wrz_l(const PrepArgs& a, int m, int k) {
    return (k < 256) ? a.lWih[m * 256 + k] : a.lWhh[m * 128 + (k - 256)];
}

#define PQ_MLP  24576
#define PQ_WRZC 16384
#define PQ_WINC 4096
#define PQ_WHNC 4096
#define PQ_WRZL 24576
#define PQ_WINL 8192
#define PQ_WHNL 4096
#define PREP_W  (PQ_MLP + PQ_WRZC + PQ_WINC + PQ_WHNC + PQ_WRZL + PQ_WINL + PQ_WHNL)
#define PREP_TOT (PREP_W + 1024)

__global__ void prep_all(PrepArgs a,
                         __half* __restrict__ mw, __half* __restrict__ gw,
                         float* __restrict__ bcc, float* __restrict__ bcl,
                         __half* __restrict__ l16, __half* __restrict__ c16)
{
    int i = blockIdx.x * blockDim.x + threadIdx.x;

    if (i >= PREP_TOT) {
        long long j = i - PREP_TOT;
        if (j < a.L32) {
            float4 v = a.lemb[j];
            *(uint2*)(l16 + j * 4) = make_uint2(packh2(v.x, v.y), packh2(v.z, v.w));
            ((float4*)a.lout0)[j] = v;
        } else if (j < (long long)a.L32 + a.C32) {
            long long q = j - a.L32;
            float4 v = a.cemb[q];
            *(uint2*)(c16 + q * 4) = make_uint2(packh2(v.x, v.y), packh2(v.z, v.w));
            ((float4*)a.cout0)[q] = v;
        }
        return;
    }

    float v0, v1, v2, v3;
    __half* o;
    long long obase;

    if (i < PQ_MLP) {
        int midx = i >> 12;
        float4 v = a.mlp[midx][i & 4095];
        v0 = v.x; v1 = v.y; v2 = v.z; v3 = v.w;
        o = mw; obase = (long long)i * 4;
    } else if (i < PQ_MLP + PQ_WRZC) {
        int base = (i - PQ_MLP) * 4, m = base >> 8, k = base & 255;
        v0 = wrz_c(a, m, k);     v1 = wrz_c(a, m, k + 1);
        v2 = wrz_c(a, m, k + 2); v3 = wrz_c(a, m, k + 3);
        o = gw; obase = OFF_WRZC + base;
    } else if (i < PQ_MLP + PQ_WRZC + PQ_WINC) {
        int base = (i - PQ_MLP - PQ_WRZC) * 4, m = base >> 7, k = base & 127;
        const float* s = a.cWih + (256 + m) * 128 + k;
        v0 = s[0]; v1 = s[1]; v2 = s[2]; v3 = s[3];
        o = gw; obase = OFF_WINC + base;
    } else if (i < PQ_MLP + PQ_WRZC + PQ_WINC + PQ_WHNC) {
        int base = (i - PQ_MLP - PQ_WRZC - PQ_WINC) * 4, m = base >> 7, k = base & 127;
        const float* s = a.cWhh + (256 + m) * 128 + k;
        v0 = s[0]; v1 = s[1]; v2 = s[2]; v3 = s[3];
        o = gw; obase = OFF_WHNC + base;
    } else if (i < PQ_MLP + PQ_WRZC + PQ_WINC + PQ_WHNC + PQ_WRZL) {
        int base = (i - PQ_MLP - PQ_WRZC - PQ_WINC - PQ_WHNC) * 4;
        int m = base / 384, k = base % 384;
        v0 = wrz_l(a, m, k);     v1 = wrz_l(a, m, k + 1);
        v2 = wrz_l(a, m, k + 2); v3 = wrz_l(a, m, k + 3);
        o = gw; obase = OFF_WRZL + base;
    } else if (i < PQ_MLP + PQ_WRZC + PQ_WINC + PQ_WHNC + PQ_WRZL + PQ_WINL) {
        int base = (i - PQ_MLP - PQ_WRZC - PQ_WINC - PQ_WHNC - PQ_WRZL) * 4;
        int m = base >> 8, k = base & 255;
        const float* s = a.lWih + (256 + m) * 256 + k;
        v0 = s[0]; v1 = s[1]; v2 = s[2]; v3 = s[3];
        o = gw; obase = OFF_WINL + base;
    } else if (i < PREP_W) {
        int base = (i - (PREP_W - PQ_WHNL)) * 4, m = base >> 7, k = base & 127;
        const float* s = a.lWhh + (256 + m) * 128 + k;
        v0 = s[0]; v1 = s[1]; v2 = s[2]; v3 = s[3];
        o = gw; obase = OFF_WHNL + base;
    } else {
        int j = i - PREP_W;
        if (j < 512) {
            bcc[j] = (j < 256) ? a.cbih[j] + a.cbhh[j]
                   : (j < 384) ? a.cbih[j] : a.cbhh[j - 128];
        } else {
            int m = j - 512;
            bcl[m] = (m < 256) ? a.lbih[m] + a.lbhh[m]
                   : (m < 384) ? a.lbih[m] : a.lbhh[m - 128];
        }
        return;
    }
    *(uint2*)(o + obase) = make_uint2(packh2(v0, v1), packh2(v2, v3));
}

// =================== host side ===================
extern "C" void kernel_launch(void* const* d_in, const int* in_sizes, int n_in,
                              void* d_out, int out_size)
{
    int base = (n_in >= 26) ? 2 : 0;

    const void*  l_ei_raw = d_in[base + 0];
    const void*  c_ei_raw = d_in[base + 1];
    const float* l_emb0   = (const float*)d_in[base + 2];
    const float* c_emb0   = (const float*)d_in[base + 3];

    const float* l2c_W1 = (const float*)d_in[base + 4];
    const float* l2c_b1 = (const float*)d_in[base + 5];
    const float* l2c_W2 = (const float*)d_in[base + 6];
    const float* l2c_b2 = (const float*)d_in[base + 7];
    const float* c2l_W1 = (const float*)d_in[base + 8];
    const float* c2l_b1 = (const float*)d_in[base + 9];
    const float* c2l_W2 = (const float*)d_in[base + 10];
    const float* c2l_b2 = (const float*)d_in[base + 11];
    const float* l2l_W1 = (const float*)d_in[base + 12];
    const float* l2l_b1 = (const float*)d_in[base + 13];
    const float* l2l_W2 = (const float*)d_in[base + 14];
    const float* l2l_b2 = (const float*)d_in[base + 15];
    const float* cgru_Wih = (const float*)d_in[base + 16];
    const float* cgru_Whh = (const float*)d_in[base + 17];
    const float* cgru_bih = (const float*)d_in[base + 18];
    const float* cgru_bhh = (const float*)d_in[base + 19];
    const float* lgru_Wih = (const float*)d_in[base + 20];
    const float* lgru_Whh = (const float*)d_in[base + 21];
    const float* lgru_bih = (const float*)d_in[base + 22];
    const float* lgru_bhh = (const float*)d_in[base + 23];

    const int E = in_sizes[base + 0];
    const int L = in_sizes[base + 2] / DIM;
    const int C = in_sizes[base + 3] / DIM;
    const int T = C + L;

    float* out   = (float*)d_out;
    float* l_out = out;
    float* c_out = out + (size_t)(NITER + 1) * L * DIM;

    __half *lfeat, *cfeat, *caggr, *lx0, *l2lm, *gates, *l16, *c16, *mw, *gw;
    float *bcc, *bcl;
    int *lei, *cei, *cnt, *off, *cur, *permc, *perml;
    cudaGetSymbolAddress((void**)&lfeat, g_lfeat);
    cudaGetSymbolAddress((void**)&cfeat, g_cfeat);
    cudaGetSymbolAddress((void**)&caggr, g_caggr);
    cudaGetSymbolAddress((void**)&lx0,   g_lx0);
    cudaGetSymbolAddress((void**)&l2lm,  g_l2lm);
    cudaGetSymbolAddress((void**)&gates, g_gates);
    cudaGetSymbolAddress((void**)&lei,   g_lei32);
    cudaGetSymbolAddress((void**)&cei,   g_cei32);
    cudaGetSymbolAddress((void**)&cnt,   g_cnt);
    cudaGetSymbolAddress((void**)&off,   g_off);
    cudaGetSymbolAddress((void**)&cur,   g_cur);
    cudaGetSymbolAddress((void**)&permc, g_permc);
    cudaGetSymbolAddress((void**)&perml, g_perml);
    cudaGetSymbolAddress((void**)&l16,   g_l16);
    cudaGetSymbolAddress((void**)&c16,   g_c16);
    cudaGetSymbolAddress((void**)&mw,    g_mw16);
    cudaGetSymbolAddress((void**)&gw,    g_gw16);
    cudaGetSymbolAddress((void**)&bcc,   g_bcat_c);
    cudaGetSymbolAddress((void**)&bcl,   g_bcat_l);

    cudaFuncSetAttribute((const void*)fused_mlp<0>, cudaFuncAttributeMaxDynamicSharedMemorySize, SMEM_MLP);
    cudaFuncSetAttribute((const void*)fused_mlp<1>, cudaFuncAttributeMaxDynamicSharedMemorySize, SMEM_MLP);
    cudaFuncSetAttribute((const void*)gates_rz_in, cudaFuncAttributeMaxDynamicSharedMemorySize, SMEM_GATES);
    cudaFuncSetAttribute((const void*)gru_hn_pw, cudaFuncAttributeMaxDynamicSharedMemorySize, SMEM_GATES);

    // ---- prelude ----
    cudaMemsetAsync(cnt, 0, (size_t)T * sizeof(int), 0);
    convert_hist<<<(E + 255) / 256, 256>>>(l_ei_raw, c_ei_raw, lei, cei, cnt, C, L, E);
    scan_all<<<1, 1024>>>(cnt, off, cur, T);
    scatter_edges<<<(E + 255) / 256, 256>>>(lei, cei, cur, off, permc, perml, C, L, E);

    PrepArgs pa;
    pa.mlp[0] = (const float4*)l2c_W1; pa.mlp[1] = (const float4*)l2c_W2;
    pa.mlp[2] = (const float4*)c2l_W1; pa.mlp[3] = (const float4*)c2l_W2;
    pa.mlp[4] = (const float4*)l2l_W1; pa.mlp[5] = (const float4*)l2l_W2;
    pa.cWih = cgru_Wih; pa.cWhh = cgru_Whh;
    pa.lWih = lgru_Wih; pa.lWhh = lgru_Whh;
    pa.cbih = cgru_bih; pa.cbhh = cgru_bhh;
    pa.lbih = lgru_bih; pa.lbhh = lgru_bhh;
    pa.lemb = (const float4*)l_emb0; pa.cemb = (const float4*)c_emb0;
    pa.lout0 = l_out; pa.cout0 = c_out;
    pa.L32 = L * 32; pa.C32 = C * 32;
    const int prepN = PREP_TOT + pa.L32 + pa.C32;
    prep_all<<<(prepN + 255) / 256, 256>>>(pa, mw, gw, bcc, bcl, l16, c16);

    __half *W_[6];
    for (int i = 0; i < 6; i++) W_[i] = mw + (size_t)i * 16384;

    for (int it = 0; it < NITER; it++) {
        const float* lcur = l_out + (size_t)it * L * DIM;
        const float* ccur = c_out + (size_t)it * C * DIM;
        float* lnext = l_out + (size_t)(it + 1) * L * DIM;
        float* cnext = c_out + (size_t)(it + 1) * C * DIM;

        dim3 gl((L + 127) / 128), gc((C + 127) / 128);
        dim3 gl3((L + 127) / 128, 3), gc3((C + 127) / 128, 3);

        // --- 3 fused MLPs ---
        fused_mlp<0><<<gl, 256, SMEM_MLP>>>(l16, W_[0], l2c_b1, W_[1], l2c_b2, lfeat, L);
        fused_mlp<0><<<gc, 256, SMEM_MLP>>>(c16, W_[2], c2l_b1, W_[3], c2l_b2, cfeat, C);
        fused_mlp<1><<<gl, 256, SMEM_MLP>>>(l16, W_[4], l2l_b1, W_[5], l2l_b2, l2lm, L);

        // --- CSR segment sums (fp16) ---
        seg_sum<<<(int)(((long long)C * 32 + 255) / 256), 256>>>(permc, off,     lfeat, caggr, C);
        seg_sum<<<(int)(((long long)L * 32 + 255) / 256), 256>>>(perml, off + C, cfeat, lx0,   L);

        // --- clause GRU ---
        ASrc ac; ac.p[0] = caggr; ac.p[1] = c16; ac.p[2] = nullptr;
        gates_rz_in<<<gc3, 256, SMEM_GATES>>>(ac, gw + OFF_WRZC, gw + OFF_WINC, bcc,
                                              gates, C, 256, 128);
        gru_hn_pw<<<gc, 256, SMEM_GATES>>>(c16, gw + OFF_WHNC, bcc + 384,
                                           gates, ccur, cnext, c16, C);

        // --- literal GRU ---
        ASrc al; al.p[0] = lx0; al.p[1] = l2lm; al.p[2] = l16;
        gates_rz_in<<<gl3, 256, SMEM_GATES>>>(al, gw + OFF_WRZL, gw + OFF_WINL, bcl,
                                              gates, L, 384, 256);
        gru_hn_pw<<<gl, 256, SMEM_GATES>>>(l16, gw + OFF_WHNL, bcl + 384,
                                           gates, lcur, lnext, l16, L);
    }
}

// round 12
// speedup vs baseline: 2.2085x; 1.1658x over previous
#include <cuda_runtime.h>
#include <cuda_fp16.h>
#include <math.h>
#include <stdint.h>

#define DIM 128
#define NITER 8

#define MAXL 100096ull
#define MAXC 150016ull
#define MAXN 150016ull
#define MAXE 450048

// ---------------- fp16 intermediates ----------------
__device__ __half g_lfeat[MAXL * 128];
__device__ __half g_cfeat[MAXC * 128];
__device__ __half g_caggr[MAXC * 128];
__device__ __half g_lx0  [MAXL * 128];
__device__ __half g_l2lm [MAXL * 128];
__device__ __half g_gates[MAXN * 384];  // [rz_sum(256) | i_n(128)]
__device__ int   g_lei32[MAXE];
__device__ int   g_cei32[MAXE];

// ---------------- CSR scratch ----------------
#define MAXT (MAXC + MAXL + 2)
__device__ int g_cnt [MAXT];
__device__ int g_off [MAXT];
__device__ int g_cur [MAXT];
__device__ int g_permc[MAXE];
__device__ int g_perml[MAXE];

// ---------------- fp16 state + weights ----------------
__device__ __half g_l16[MAXL * 128];
__device__ __half g_c16[MAXC * 128];
__device__ __half g_mw16[98304];
__device__ __half g_gw16[245760];
__device__ float  g_bcat_c[512], g_bcat_l[512];

#define OFF_WRZC 0
#define OFF_WINC 65536
#define OFF_WHNC 81920
#define OFF_WRZL 98304
#define OFF_WINL 196608
#define OFF_WHNL 229376

// =================== helpers ===================
__device__ __forceinline__ uint32_t smem_to_u32(const void* p) {
    uint32_t a;
    asm("{ .reg .u64 t; cvta.to.shared.u64 t, %1; cvt.u32.u64 %0, t; }"
        : "=r"(a) : "l"(p));
    return a;
}
__device__ __forceinline__ void cp16(uint32_t dst, const void* src, int sz) {
    asm volatile("cp.async.cg.shared.global [%0], [%1], 16, %2;"
                 :: "r"(dst), "l"(src), "r"(sz));
}
#define CP_COMMIT() asm volatile("cp.async.commit_group;" ::: "memory")
#define CP_WAIT0()  asm volatile("cp.async.wait_group 0;" ::: "memory")
#define CP_WAIT1()  asm volatile("cp.async.wait_group 1;" ::: "memory")

__device__ __forceinline__ void ldx4(uint32_t* r, uint32_t addr) {
    asm volatile("ldmatrix.sync.aligned.m8n8.x4.shared.b16 {%0,%1,%2,%3}, [%4];"
                 : "=r"(r[0]), "=r"(r[1]), "=r"(r[2]), "=r"(r[3]) : "r"(addr));
}
__device__ __forceinline__ void ldx2(uint32_t* r, uint32_t addr) {
    asm volatile("ldmatrix.sync.aligned.m8n8.x2.shared.b16 {%0,%1}, [%2];"
                 : "=r"(r[0]), "=r"(r[1]) : "r"(addr));
}
__device__ __forceinline__ void mma_f16(float* d, const uint32_t* a, const uint32_t* b) {
    asm volatile("mma.sync.aligned.m16n8k16.row.col.f32.f16.f16.f32 "
                 "{%0,%1,%2,%3}, {%4,%5,%6,%7}, {%8,%9}, {%0,%1,%2,%3};"
                 : "+f"(d[0]), "+f"(d[1]), "+f"(d[2]), "+f"(d[3])
                 : "r"(a[0]), "r"(a[1]), "r"(a[2]), "r"(a[3]), "r"(b[0]), "r"(b[1]));
}
__device__ __forceinline__ uint32_t packh2(float x, float y) {
    __half2 p = __floats2half2_rn(x, y);
    return *(uint32_t*)&p;
}
__device__ __forceinline__ float sigm(float x) { return 1.f / (1.f + expf(-x)); }

#define REG 18432u              // one 128row x 64col fp16 region (144B stride)
#define SMEM_GATES (4 * REG)    // A0 A1 W0 W1
#define SMEM_MLP   (6 * REG)    // A0 A1 W0 W1 H0 H1

struct ASrc { const __half* p[3]; };

// compute one 64-col K-chunk: A region at aBase, W region at wBase
__device__ __forceinline__ void compute_chunk(float acc[4][4][4],
                                              uint32_t aBase, uint32_t wBase)
{
    #pragma unroll
    for (int k16 = 0; k16 < 4; k16++) {
        const uint32_t kb = k16 << 5;
        uint32_t af[4][4];
        #pragma unroll
        for (int mi = 0; mi < 4; mi++)
            ldx4(af[mi], aBase + mi * (16 * 144) + kb);
        #pragma unroll
        for (int ni = 0; ni < 4; ni++) {
            uint32_t bf[2];
            ldx2(bf, wBase + ni * (8 * 144) + kb);
            #pragma unroll
            for (int mi = 0; mi < 4; mi++)
                mma_f16(acc[mi][ni], af[mi], bf);
        }
    }
}

// =================== fused 2-layer MLP (cp.async pipelined) ===================
template<int XORROW>
__global__ __launch_bounds__(256, 2)
void fused_mlp(const __half* __restrict__ A16,
               const __half* __restrict__ W1, const float* __restrict__ b1,
               const __half* __restrict__ W2, const float* __restrict__ b2,
               __half* __restrict__ out, int N)
{
    extern __shared__ char smem[];
    const uint32_t sb = smem_to_u32(smem);
    const int tid  = threadIdx.x;
    const int lane = tid & 31;
    const int wid  = tid >> 5;
    const int wm   = wid >> 2;
    const int wn   = wid & 3;
    const int bm   = blockIdx.x * 128;

    const uint32_t aOff = (uint32_t)(wm * 64 + (lane & 15)) * 144 + ((lane >> 4) << 4);
    const uint32_t bOff = (uint32_t)(wn * 32 + (lane & 7)) * 144 + (((lane >> 3) & 1) << 4);

    // per-thread loader coords: 4 (row,unit) pairs
    const int lrow[4] = { tid >> 3, (tid + 256) >> 3, (tid + 512) >> 3, (tid + 768) >> 3 };
    const int lunit   = tid & 7;

    float acc[4][4][4] = {};

    // issue A+W chunk kc into buffers
    auto issue1 = [&](int kc) {
        const uint32_t aBuf = sb + (uint32_t)(kc & 1) * REG;
        const uint32_t wBuf = sb + (2u + (kc & 1)) * REG;
        const int k0 = kc << 6;
        #pragma unroll
        for (int t = 0; t < 4; t++) {
            int row = lrow[t];
            uint32_t so = (uint32_t)row * 144 + (lunit << 4);
            int grow = bm + row;
            int ok = grow < N;
            int sr = ok ? (XORROW ? (grow ^ 1) : grow) : 0;
            cp16(aBuf + so, A16 + (size_t)sr * 128 + k0 + lunit * 8, ok ? 16 : 0);
            cp16(wBuf + so, W1 + (size_t)row * 128 + k0 + lunit * 8, 16);
        }
        CP_COMMIT();
    };

    // ---- stage 1 ----
    issue1(0);
    issue1(1);
    CP_WAIT1(); __syncthreads();
    compute_chunk(acc, sb + aOff, sb + 2 * REG + bOff);
    CP_WAIT0(); __syncthreads();
    compute_chunk(acc, sb + REG + aOff, sb + 3 * REG + bOff);
    __syncthreads();   // all warps done reading W bufs before W2 prefetch

    // prefetch W2 chunks into W0/W1 while epilogue runs
    #pragma unroll
    for (int kc = 0; kc < 2; kc++) {
        const uint32_t wBuf = sb + (2u + kc) * REG;
        const int k0 = kc << 6;
        #pragma unroll
        for (int t = 0; t < 4; t++) {
            int row = lrow[t];
            uint32_t so = (uint32_t)row * 144 + (lunit << 4);
            cp16(wBuf + so, W2 + (size_t)row * 128 + k0 + lunit * 8, 16);
        }
    }
    CP_COMMIT();

    // ---- epilogue 1: relu + fp16 -> hid regions H0/H1 ----
    #pragma unroll
    for (int ni = 0; ni < 4; ni++) {
        int c = wn * 32 + ni * 8 + ((lane & 3) << 1);
        float2 bv = *(const float2*)(b1 + c);
        uint32_t roff = (4u + (uint32_t)(c >> 6)) * REG + (uint32_t)(c & 63) * 2;
        #pragma unroll
        for (int mi = 0; mi < 4; mi++) {
            int rl0 = wm * 64 + mi * 16 + (lane >> 2);
            float vx0 = fmaxf(acc[mi][ni][0] + bv.x, 0.f);
            float vy0 = fmaxf(acc[mi][ni][1] + bv.y, 0.f);
            float vx1 = fmaxf(acc[mi][ni][2] + bv.x, 0.f);
            float vy1 = fmaxf(acc[mi][ni][3] + bv.y, 0.f);
            *(uint32_t*)(smem + roff + (uint32_t)rl0 * 144)       = packh2(vx0, vy0);
            *(uint32_t*)(smem + roff + (uint32_t)(rl0 + 8) * 144) = packh2(vx1, vy1);
            acc[mi][ni][0] = acc[mi][ni][1] = acc[mi][ni][2] = acc[mi][ni][3] = 0.f;
        }
    }
    CP_WAIT0(); __syncthreads();

    // ---- stage 2: A = hid (H0/H1), W = W2 (W0/W1) ----
    compute_chunk(acc, sb + 4 * REG + aOff, sb + 2 * REG + bOff);
    compute_chunk(acc, sb + 5 * REG + aOff, sb + 3 * REG + bOff);

    #pragma unroll
    for (int ni = 0; ni < 4; ni++) {
        int c = wn * 32 + ni * 8 + ((lane & 3) << 1);
        float2 bv = *(const float2*)(b2 + c);
        #pragma unroll
        for (int mi = 0; mi < 4; mi++) {
            int r0 = bm + wm * 64 + mi * 16 + (lane >> 2);
            if (r0 < N)
                *(uint32_t*)(out + (size_t)r0 * 128 + c) =
                    packh2(acc[mi][ni][0] + bv.x, acc[mi][ni][1] + bv.y);
            if (r0 + 8 < N)
                *(uint32_t*)(out + (size_t)(r0 + 8) * 128 + c) =
                    packh2(acc[mi][ni][2] + bv.x, acc[mi][ni][3] + bv.y);
        }
    }
}

// =================== merged rz + i_n gates GEMM (pipelined) ===================
// grid (ceilN/128, 3): y=0,1 -> rz (M=256, K=Krz); y=2 -> i_n (M=128, K=Kin).
__global__ __launch_bounds__(256, 2)
void gates_rz_in(ASrc A,
                 const __half* __restrict__ Wrz, const __half* __restrict__ Win,
                 const float* __restrict__ bias,
                 __half* __restrict__ gates, int N, int Krz, int Kin)
{
    extern __shared__ char smem[];
    const uint32_t sb = smem_to_u32(smem);
    const int tid  = threadIdx.x;
    const int lane = tid & 31;
    const int wid  = tid >> 5;
    const int wm   = wid >> 2;
    const int wn   = wid & 3;
    const int bm   = blockIdx.x * 128;
    const int bn   = blockIdx.y * 128;
    const int isIn = (blockIdx.y == 2);
    const __half* W = isIn ? Win : Wrz;
    const int K = isIn ? Kin : Krz;
    const int wrow = isIn ? 0 : bn;
    const int nchunk = K >> 6;

    float acc[4][4][4] = {};
    const uint32_t aOff = (uint32_t)(wm * 64 + (lane & 15)) * 144 + ((lane >> 4) << 4);
    const uint32_t bOff = (uint32_t)(wn * 32 + (lane & 7)) * 144 + (((lane >> 3) & 1) << 4);

    const int lrow[4] = { tid >> 3, (tid + 256) >> 3, (tid + 512) >> 3, (tid + 768) >> 3 };
    const int lunit   = tid & 7;

    auto issue = [&](int kc) {
        const uint32_t aBuf = sb + (uint32_t)(kc & 1) * REG;
        const uint32_t wBuf = sb + (2u + (kc & 1)) * REG;
        const __half* srcBase = A.p[kc >> 1];
        const int colOfs = ((kc & 1) << 6) + lunit * 8;
        const int k0 = kc << 6;
        #pragma unroll
        for (int t = 0; t < 4; t++) {
            int row = lrow[t];
            uint32_t so = (uint32_t)row * 144 + (lunit << 4);
            int grow = bm + row;
            int ok = grow < N;
            cp16(aBuf + so, srcBase + (size_t)(ok ? grow : 0) * 128 + colOfs, ok ? 16 : 0);
            cp16(wBuf + so, W + (size_t)(wrow + row) * K + k0 + lunit * 8, 16);
        }
        CP_COMMIT();
    };

    issue(0);
    for (int kc = 0; kc < nchunk; kc++) {
        if (kc + 1 < nchunk) { issue(kc + 1); CP_WAIT1(); }
        else                 { CP_WAIT0(); }
        __syncthreads();
        compute_chunk(acc, sb + (uint32_t)(kc & 1) * REG + aOff,
                           sb + (2u + (kc & 1)) * REG + bOff);
        __syncthreads();
    }

    #pragma unroll
    for (int ni = 0; ni < 4; ni++) {
        int gcol = bn + wn * 32 + ni * 8 + ((lane & 3) << 1);
        float2 bv = *(const float2*)(bias + gcol);
        #pragma unroll
        for (int mi = 0; mi < 4; mi++) {
            int r0 = bm + wm * 64 + mi * 16 + (lane >> 2);
            if (r0 < N)
                *(uint32_t*)(gates + (size_t)r0 * 384 + gcol) =
                    packh2(acc[mi][ni][0] + bv.x, acc[mi][ni][1] + bv.y);
            if (r0 + 8 < N)
                *(uint32_t*)(gates + (size_t)(r0 + 8) * 384 + gcol) =
                    packh2(acc[mi][ni][2] + bv.x, acc[mi][ni][3] + bv.y);
        }
    }
}

// =================== h_n GEMM + fused GRU pointwise (pipelined) ===================
__global__ __launch_bounds__(256, 2)
void gru_hn_pw(const __half* __restrict__ A16,
               const __half* __restrict__ Whn, const float* __restrict__ bias,
               const __half* __restrict__ gates,
               const float* __restrict__ hcur, float* __restrict__ hout,
               __half* __restrict__ h16out, int N)
{
    extern __shared__ char smem[];
    const uint32_t sb = smem_to_u32(smem);
    const int tid  = threadIdx.x;
    const int lane = tid & 31;
    const int wid  = tid >> 5;
    const int wm   = wid >> 2;
    const int wn   = wid & 3;
    const int bm   = blockIdx.x * 128;

    float acc[4][4][4] = {};
    const uint32_t aOff = (uint32_t)(wm * 64 + (lane & 15)) * 144 + ((lane >> 4) << 4);
    const uint32_t bOff = (uint32_t)(wn * 32 + (lane & 7)) * 144 + (((lane >> 3) & 1) << 4);

    const int lrow[4] = { tid >> 3, (tid + 256) >> 3, (tid + 512) >> 3, (tid + 768) >> 3 };
    const int lunit   = tid & 7;

    auto issue = [&](int kc) {
        const uint32_t aBuf = sb + (uint32_t)(kc & 1) * REG;
        const uint32_t wBuf = sb + (2u + (kc & 1)) * REG;
        const int k0 = kc << 6;
        #pragma unroll
        for (int t = 0; t < 4; t++) {
            int row = lrow[t];
            uint32_t so = (uint32_t)row * 144 + (lunit << 4);
            int grow = bm + row;
            int ok = grow < N;
            cp16(aBuf + so, A16 + (size_t)(ok ? grow : 0) * 128 + k0 + lunit * 8, ok ? 16 : 0);
            cp16(wBuf + so, Whn + (size_t)row * 128 + k0 + lunit * 8, 16);
        }
        CP_COMMIT();
    };

    issue(0);
    issue(1);
    CP_WAIT1(); __syncthreads();
    compute_chunk(acc, sb + aOff, sb + 2 * REG + bOff);
    CP_WAIT0(); __syncthreads();
    compute_chunk(acc, sb + REG + aOff, sb + 3 * REG + bOff);

    #pragma unroll
    for (int ni = 0; ni < 4; ni++) {
        int col = wn * 32 + ni * 8 + ((lane & 3) << 1);
        float2 bv = *(const float2*)(bias + col);
        #pragma unroll
        for (int mi = 0; mi < 4; mi++) {
            int r0 = bm + wm * 64 + mi * 16 + (lane >> 2);
            #pragma unroll
            for (int half = 0; half < 2; half++) {
                int r = r0 + half * 8;
                if (r >= N) continue;
                float vx = acc[mi][ni][half * 2 + 0] + bv.x;
                float vy = acc[mi][ni][half * 2 + 1] + bv.y;
                const __half* gp = gates + (size_t)r * 384 + col;
                float2 Rv = __half22float2(*(const __half2*)(gp));
                float2 Zv = __half22float2(*(const __half2*)(gp + 128));
                float2 Iv = __half22float2(*(const __half2*)(gp + 256));
                float2 hv = *(const float2*)(hcur + (size_t)r * 128 + col);
                float zx = sigm(Zv.x), zy = sigm(Zv.y);
                float ox = (1.f - zx) * tanhf(Iv.x + sigm(Rv.x) * vx) + zx * hv.x;
                float oy = (1.f - zy) * tanhf(Iv.y + sigm(Rv.y) * vy) + zy * hv.y;
                *(float2*)(hout + (size_t)r * 128 + col) = make_float2(ox, oy);
                *(uint32_t*)(h16out + (size_t)r * 128 + col) = packh2(ox, oy);
            }
        }
    }
}

// =================== CSR build ===================
__global__ void convert_hist(const void* __restrict__ srcA, const void* __restrict__ srcB,
                             int* __restrict__ dstA, int* __restrict__ dstB,
                             int* __restrict__ cnt, int C, int L, int E)
{
    __shared__ int s_is64;
    if (threadIdx.x == 0) {
        const unsigned* ua = (const unsigned*)srcA;
        const unsigned* ub = (const unsigned*)srcB;
        int n = E < 32 ? E : 32;
        int is64 = 1;
        for (int i = 0; i < n; i++)
            if (ua[2 * i + 1] | ub[2 * i + 1]) { is64 = 0; break; }
        s_is64 = is64;
    }
    __syncthreads();
    int e = blockIdx.x * blockDim.x + threadIdx.x;
    if (e >= E) return;
    int la, ca;
    if (s_is64) {
        la = (int)((const long long*)srcA)[e];
        ca = (int)((const long long*)srcB)[e];
    } else {
        la = ((const int*)srcA)[e];
        ca = ((const int*)srcB)[e];
    }
    dstA[e] = la; dstB[e] = ca;
    if ((unsigned)la < (unsigned)L && (unsigned)ca < (unsigned)C) {
        atomicAdd(&cnt[ca], 1);
        atomicAdd(&cnt[C + la], 1);
    }
}

__global__ void scan_all(const int* __restrict__ cnt, int* __restrict__ off,
                         int* __restrict__ cur, int T)
{
    __shared__ int ws[32];
    int chunk = (T + 1023) >> 10;
    int s = threadIdx.x * chunk;
    int e = min(T, s + chunk);
    int sum = 0;
    for (int i = s; i < e; i++) sum += cnt[i];

    int lane = threadIdx.x & 31, w = threadIdx.x >> 5;
    int x = sum;
    #pragma unroll
    for (int d = 1; d < 32; d <<= 1) {
        int y = __shfl_up_sync(0xffffffffu, x, d);
        if (lane >= d) x += y;
    }
    if (lane == 31) ws[w] = x;
    __syncthreads();
    if (w == 0) {
        int y = ws[lane];
        #pragma unroll
        for (int d = 1; d < 32; d <<= 1) {
            int z = __shfl_up_sync(0xffffffffu, y, d);
            if (lane >= d) y += z;
        }
        ws[lane] = y;
    }
    __syncthreads();
    int excl = x - sum + (w > 0 ? ws[w - 1] : 0);

    int run = excl;
    for (int i = s; i < e; i++) {
        off[i] = run; cur[i] = run;
        run += cnt[i];
    }
    if (s < T && e == T) off[T] = run;
}

__global__ void scatter_edges(const int* __restrict__ lei, const int* __restrict__ cei,
                              int* __restrict__ cur, const int* __restrict__ off,
                              int* __restrict__ permc, int* __restrict__ perml,
                              int C, int L, int E)
{
    int e = blockIdx.x * blockDim.x + threadIdx.x;
    if (e >= E) return;
    int la = lei[e], ca = cei[e];
    if ((unsigned)la >= (unsigned)L || (unsigned)ca >= (unsigned)C) return;
    int p1 = atomicAdd(&cur[ca], 1);
    permc[p1] = la;
    int baseL = off[C];
    int p2 = atomicAdd(&cur[C + la], 1);
    perml[p2 - baseL] = ca;
}

// merged segment sums: destinations [0,C) clause path, [C,C+L) literal path.
__global__ void seg_sum2(const int* __restrict__ permc, const int* __restrict__ perml,
                         const int* __restrict__ off,
                         const __half* __restrict__ lfeat, const __half* __restrict__ cfeat,
                         __half* __restrict__ caggr, __half* __restrict__ lx0,
                         int C, int T)
{
    int w = (int)(((long long)blockIdx.x * blockDim.x + threadIdx.x) >> 5);
    int lane = threadIdx.x & 31;
    if (w >= T) return;

    const int* perm;
    const __half* feat;
    __half* out;
    int base, dst;
    if (w < C) {
        perm = permc; feat = lfeat; out = caggr; base = 0; dst = w;
    } else {
        perm = perml; feat = cfeat; out = lx0; base = off[C]; dst = w - C;
    }
    int s = off[w] - base, t = off[w + 1] - base;
    float4 acc = make_float4(0.f, 0.f, 0.f, 0.f);
    for (int i = s; i < t; i++) {
        int src = perm[i];
        uint2 v = *(const uint2*)(feat + (size_t)src * 128 + lane * 4);
        float2 f0 = __half22float2(*(__half2*)&v.x);
        float2 f1 = __half22float2(*(__half2*)&v.y);
        acc.x += f0.x; acc.y += f0.y; acc.z += f1.x; acc.w += f1.y;
    }
    uint2 o;
    o.x = packh2(acc.x, acc.y);
    o.y = packh2(acc.z, acc.w);
    *(uint2*)(out + (size_t)dst * 128 + lane * 4) = o;
}

// =================== weight + embedding prep ===================
struct PrepArgs {
    const float4* mlp[6];
    const float* cWih; const float* cWhh;
    const float* lWih; const float* lWhh;
    const float* cbih; const float* cbhh;
    const float* lbih; const float* lbhh;
    const float4* lemb; const float4* cemb;
    float* lout0; float* cout0;
    int L32, C32;
};

__device__ __forceinline__ float wrz_c(const PrepArgs& a, int m, int k) {
    return (k < 128) ? a.cWih[m * 128 + k] : a.cWhh[m * 128 + (k - 128)];
}
__device__ __forceinline__ float wrz_l(const PrepArgs& a, int m, int k) {
    return (k < 256) ? a.lWih[m * 256 + k] : a.lWhh[m * 128 + (k - 256)];
}

#define PQ_MLP  24576
#define PQ_WRZC 16384
#define PQ_WINC 4096
#define PQ_WHNC 4096
#define PQ_WRZL 24576
#define PQ_WINL 8192
#define PQ_WHNL 4096
#define PREP_W  (PQ_MLP + PQ_WRZC + PQ_WINC + PQ_WHNC + PQ_WRZL + PQ_WINL + PQ_WHNL)
#define PREP_TOT (PREP_W + 1024)

__global__ void prep_all(PrepArgs a,
                         __half* __restrict__ mw, __half* __restrict__ gw,
                         float* __restrict__ bcc, float* __restrict__ bcl,
                         __half* __restrict__ l16, __half* __restrict__ c16)
{
    int i = blockIdx.x * blockDim.x + threadIdx.x;

    if (i >= PREP_TOT) {
        long long j = i - PREP_TOT;
        if (j < a.L32) {
            float4 v = a.lemb[j];
            *(uint2*)(l16 + j * 4) = make_uint2(packh2(v.x, v.y), packh2(v.z, v.w));
            ((float4*)a.lout0)[j] = v;
        } else if (j < (long long)a.L32 + a.C32) {
            long long q = j - a.L32;
            float4 v = a.cemb[q];
            *(uint2*)(c16 + q * 4) = make_uint2(packh2(v.x, v.y), packh2(v.z, v.w));
            ((float4*)a.cout0)[q] = v;
        }
        return;
    }

    float v0, v1, v2, v3;
    __half* o;
    long long obase;

    if (i < PQ_MLP) {
        int midx = i >> 12;
        float4 v = a.mlp[midx][i & 4095];
        v0 = v.x; v1 = v.y; v2 = v.z; v3 = v.w;
        o = mw; obase = (long long)i * 4;
    } else if (i < PQ_MLP + PQ_WRZC) {
        int base = (i - PQ_MLP) * 4, m = base >> 8, k = base & 255;
        v0 = wrz_c(a, m, k);     v1 = wrz_c(a, m, k + 1);
        v2 = wrz_c(a, m, k + 2); v3 = wrz_c(a, m, k + 3);
        o = gw; obase = OFF_WRZC + base;
    } else if (i < PQ_MLP + PQ_WRZC + PQ_WINC) {
        int base = (i - PQ_MLP - PQ_WRZC) * 4, m = base >> 7, k = base & 127;
        const float* s = a.cWih + (256 + m) * 128 + k;
        v0 = s[0]; v1 = s[1]; v2 = s[2]; v3 = s[3];
        o = gw; obase = OFF_WINC + base;
    } else if (i < PQ_MLP + PQ_WRZC + PQ_WINC + PQ_WHNC) {
        int base = (i - PQ_MLP - PQ_WRZC - PQ_WINC) * 4, m = base >> 7, k = base & 127;
        const float* s = a.cWhh + (256 + m) * 128 + k;
        v0 = s[0]; v1 = s[1]; v2 = s[2]; v3 = s[3];
        o = gw; obase = OFF_WHNC + base;
    } else if (i < PQ_MLP + PQ_WRZC + PQ_WINC + PQ_WHNC + PQ_WRZL) {
        int base = (i - PQ_MLP - PQ_WRZC - PQ_WINC - PQ_WHNC) * 4;
        int m = base / 384, k = base % 384;
        v0 = wrz_l(a, m, k);     v1 = wrz_l(a, m, k + 1);
        v2 = wrz_l(a, m, k + 2); v3 = wrz_l(a, m, k + 3);
        o = gw; obase = OFF_WRZL + base;
    } else if (i < PQ_MLP + PQ_WRZC + PQ_WINC + PQ_WHNC + PQ_WRZL + PQ_WINL) {
        int base = (i - PQ_MLP - PQ_WRZC - PQ_WINC - PQ_WHNC - PQ_WRZL) * 4;
        int m = base >> 8, k = base & 255;
        const float* s = a.lWih + (256 + m) * 256 + k;
        v0 = s[0]; v1 = s[1]; v2 = s[2]; v3 = s[3];
        o = gw; obase = OFF_WINL + base;
    } else if (i < PREP_W) {
        int base = (i - (PREP_W - PQ_WHNL)) * 4, m = base >> 7, k = base & 127;
        const float* s = a.lWhh + (256 + m) * 128 + k;
        v0 = s[0]; v1 = s[1]; v2 = s[2]; v3 = s[3];
        o = gw; obase = OFF_WHNL + base;
    } else {
        int j = i - PREP_W;
        if (j < 512) {
            bcc[j] = (j < 256) ? a.cbih[j] + a.cbhh[j]
                   : (j < 384) ? a.cbih[j] : a.cbhh[j - 128];
        } else {
            int m = j - 512;
            bcl[m] = (m < 256) ? a.lbih[m] + a.lbhh[m]
                   : (m < 384) ? a.lbih[m] : a.lbhh[m - 128];
        }
        return;
    }
    *(uint2*)(o + obase) = make_uint2(packh2(v0, v1), packh2(v2, v3));
}

// =================== host side ===================
extern "C" void kernel_launch(void* const* d_in, const int* in_sizes, int n_in,
                              void* d_out, int out_size)
{
    int base = (n_in >= 26) ? 2 : 0;

    const void*  l_ei_raw = d_in[base + 0];
    const void*  c_ei_raw = d_in[base + 1];
    const float* l_emb0   = (const float*)d_in[base + 2];
    const float* c_emb0   = (const float*)d_in[base + 3];

    const float* l2c_W1 = (const float*)d_in[base + 4];
    const float* l2c_b1 = (const float*)d_in[base + 5];
    const float* l2c_W2 = (const float*)d_in[base + 6];
    const float* l2c_b2 = (const float*)d_in[base + 7];
    const float* c2l_W1 = (const float*)d_in[base + 8];
    const float* c2l_b1 = (const float*)d_in[base + 9];
    const float* c2l_W2 = (const float*)d_in[base + 10];
    const float* c2l_b2 = (const float*)d_in[base + 11];
    const float* l2l_W1 = (const float*)d_in[base + 12];
    const float* l2l_b1 = (const float*)d_in[base + 13];
    const float* l2l_W2 = (const float*)d_in[base + 14];
    const float* l2l_b2 = (const float*)d_in[base + 15];
    const float* cgru_Wih = (const float*)d_in[base + 16];
    const float* cgru_Whh = (const float*)d_in[base + 17];
    const float* cgru_bih = (const float*)d_in[base + 18];
    const float* cgru_bhh = (const float*)d_in[base + 19];
    const float* lgru_Wih = (const float*)d_in[base + 20];
    const float* lgru_Whh = (const float*)d_in[base + 21];
    const float* lgru_bih = (const float*)d_in[base + 22];
    const float* lgru_bhh = (const float*)d_in[base + 23];

    const int E = in_sizes[base + 0];
    const int L = in_sizes[base + 2] / DIM;
    const int C = in_sizes[base + 3] / DIM;
    const int T = C + L;

    float* out   = (float*)d_out;
    float* l_out = out;
    float* c_out = out + (size_t)(NITER + 1) * L * DIM;

    __half *lfeat, *cfeat, *caggr, *lx0, *l2lm, *gates, *l16, *c16, *mw, *gw;
    float *bcc, *bcl;
    int *lei, *cei, *cnt, *off, *cur, *permc, *perml;
    cudaGetSymbolAddress((void**)&lfeat, g_lfeat);
    cudaGetSymbolAddress((void**)&cfeat, g_cfeat);
    cudaGetSymbolAddress((void**)&caggr, g_caggr);
    cudaGetSymbolAddress((void**)&lx0,   g_lx0);
    cudaGetSymbolAddress((void**)&l2lm,  g_l2lm);
    cudaGetSymbolAddress((void**)&gates, g_gates);
    cudaGetSymbolAddress((void**)&lei,   g_lei32);
    cudaGetSymbolAddress((void**)&cei,   g_cei32);
    cudaGetSymbolAddress((void**)&cnt,   g_cnt);
    cudaGetSymbolAddress((void**)&off,   g_off);
    cudaGetSymbolAddress((void**)&cur,   g_cur);
    cudaGetSymbolAddress((void**)&permc, g_permc);
    cudaGetSymbolAddress((void**)&perml, g_perml);
    cudaGetSymbolAddress((void**)&l16,   g_l16);
    cudaGetSymbolAddress((void**)&c16,   g_c16);
    cudaGetSymbolAddress((void**)&mw,    g_mw16);
    cudaGetSymbolAddress((void**)&gw,    g_gw16);
    cudaGetSymbolAddress((void**)&bcc,   g_bcat_c);
    cudaGetSymbolAddress((void**)&bcl,   g_bcat_l);

    cudaFuncSetAttribute((const void*)fused_mlp<0>, cudaFuncAttributeMaxDynamicSharedMemorySize, SMEM_MLP);
    cudaFuncSetAttribute((const void*)fused_mlp<1>, cudaFuncAttributeMaxDynamicSharedMemorySize, SMEM_MLP);
    cudaFuncSetAttribute((const void*)gates_rz_in, cudaFuncAttributeMaxDynamicSharedMemorySize, SMEM_GATES);
    cudaFuncSetAttribute((const void*)gru_hn_pw, cudaFuncAttributeMaxDynamicSharedMemorySize, SMEM_GATES);

    // ---- prelude ----
    cudaMemsetAsync(cnt, 0, (size_t)T * sizeof(int), 0);
    convert_hist<<<(E + 255) / 256, 256>>>(l_ei_raw, c_ei_raw, lei, cei, cnt, C, L, E);
    scan_all<<<1, 1024>>>(cnt, off, cur, T);
    scatter_edges<<<(E + 255) / 256, 256>>>(lei, cei, cur, off, permc, perml, C, L, E);

    PrepArgs pa;
    pa.mlp[0] = (const float4*)l2c_W1; pa.mlp[1] = (const float4*)l2c_W2;
    pa.mlp[2] = (const float4*)c2l_W1; pa.mlp[3] = (const float4*)c2l_W2;
    pa.mlp[4] = (const float4*)l2l_W1; pa.mlp[5] = (const float4*)l2l_W2;
    pa.cWih = cgru_Wih; pa.cWhh = cgru_Whh;
    pa.lWih = lgru_Wih; pa.lWhh = lgru_Whh;
    pa.cbih = cgru_bih; pa.cbhh = cgru_bhh;
    pa.lbih = lgru_bih; pa.lbhh = lgru_bhh;
    pa.lemb = (const float4*)l_emb0; pa.cemb = (const float4*)c_emb0;
    pa.lout0 = l_out; pa.cout0 = c_out;
    pa.L32 = L * 32; pa.C32 = C * 32;
    const int prepN = PREP_TOT + pa.L32 + pa.C32;
    prep_all<<<(prepN + 255) / 256, 256>>>(pa, mw, gw, bcc, bcl, l16, c16);

    __half *W_[6];
    for (int i = 0; i < 6; i++) W_[i] = mw + (size_t)i * 16384;

    for (int it = 0; it < NITER; it++) {
        const float* lcur = l_out + (size_t)it * L * DIM;
        const float* ccur = c_out + (size_t)it * C * DIM;
        float* lnext = l_out + (size_t)(it + 1) * L * DIM;
        float* cnext = c_out + (size_t)(it + 1) * C * DIM;

        dim3 gl((L + 127) / 128), gc((C + 127) / 128);
        dim3 gl3((L + 127) / 128, 3), gc3((C + 127) / 128, 3);

        // --- 3 fused MLPs ---
        fused_mlp<0><<<gl, 256, SMEM_MLP>>>(l16, W_[0], l2c_b1, W_[1], l2c_b2, lfeat, L);
        fused_mlp<0><<<gc, 256, SMEM_MLP>>>(c16, W_[2], c2l_b1, W_[3], c2l_b2, cfeat, C);
        fused_mlp<1><<<gl, 256, SMEM_MLP>>>(l16, W_[4], l2l_b1, W_[5], l2l_b2, l2lm, L);

        // --- merged CSR segment sums ---
        seg_sum2<<<(int)(((long long)T * 32 + 255) / 256), 256>>>(
            permc, perml, off, lfeat, cfeat, caggr, lx0, C, T);

        // --- clause GRU ---
        ASrc ac; ac.p[0] = caggr; ac.p[1] = c16; ac.p[2] = nullptr;
        gates_rz_in<<<gc3, 256, SMEM_GATES>>>(ac, gw + OFF_WRZC, gw + OFF_WINC, bcc,
                                              gates, C, 256, 128);
        gru_hn_pw<<<gc, 256, SMEM_GATES>>>(c16, gw + OFF_WHNC, bcc + 384,
                                           gates, ccur, cnext, c16, C);

        // --- literal GRU ---
        ASrc al; al.p[0] = lx0; al.p[1] = l2lm; al.p[2] = l16;
        gates_rz_in<<<gl3, 256, SMEM_GATES>>>(al, gw + OFF_WRZL, gw + OFF_WINL, bcl,
                                              gates, L, 384, 256);
        gru_hn_pw<<<gl, 256, SMEM_GATES>>>(l16, gw + OFF_WHNL, bcl + 384,
                                           gates, lcur, lnext, l16, L);
    }
}